// round 6
// baseline (speedup 1.0000x reference)
#include <cuda_runtime.h>
#include <cuda_bf16.h>
#include <math.h>

#define NROWS 32768          // B*L
#define HDIM  256
#define LSEQ  512
#define NBATCH 64
#define HEADD 64
#define ITEMPAD 49999

typedef unsigned long long u64;

// ---------------- scratch (device globals; no allocs allowed) ----------------
__device__ __align__(16) float g_seqs[NROWS * HDIM];
__device__ __align__(16) float g_time[NROWS * HDIM];
__device__ __align__(16) float g_Q   [NROWS * HDIM];
__device__ __align__(16) float g_ao  [NROWS * HDIM];
__device__ __align__(16) float g_x   [NROWS * HDIM];
__device__ float g_keep[NROWS];
__device__ float g_gates[NROWS * 2];

// bf16 hi/lo split buffers
__device__ __align__(16) __nv_bfloat16 g_t_hi[NROWS * HDIM];
__device__ __align__(16) __nv_bfloat16 g_t_lo[NROWS * HDIM];
__device__ __align__(16) __nv_bfloat16 g_a_hi[NROWS * HDIM];
__device__ __align__(16) __nv_bfloat16 g_a_lo[NROWS * HDIM];
__device__ __align__(16) __nv_bfloat16 g_b_hi[NROWS * HDIM];
__device__ __align__(16) __nv_bfloat16 g_b_lo[NROWS * HDIM];
__device__ __align__(16) __nv_bfloat16 g_qh[NROWS * HDIM];
__device__ __align__(16) __nv_bfloat16 g_ql[NROWS * HDIM];
__device__ __align__(16) __nv_bfloat16 g_kh[NROWS * HDIM];
__device__ __align__(16) __nv_bfloat16 g_kl[NROWS * HDIM];
__device__ __align__(16) __nv_bfloat16 g_vh[NROWS * HDIM];
__device__ __align__(16) __nv_bfloat16 g_vl[NROWS * HDIM];
// weights: [mat(q,k,v,c1,c2)][block][256][256]
__device__ __align__(16) __nv_bfloat16 g_w_hi[5 * 2 * HDIM * HDIM];
__device__ __align__(16) __nv_bfloat16 g_w_lo[5 * 2 * HDIM * HDIM];

// ---------------- small helpers ----------------------------------------------
__device__ __forceinline__ void split_bf(float x, __nv_bfloat16& h, __nv_bfloat16& l) {
    h = __float2bfloat16_rn(x);
    l = __float2bfloat16_rn(x - __bfloat162float(h));
}
__device__ __forceinline__ unsigned pack_bf2(__nv_bfloat16 a, __nv_bfloat16 b) {
    return (unsigned)__bfloat16_as_ushort(a) | ((unsigned)__bfloat16_as_ushort(b) << 16);
}
__device__ __forceinline__ unsigned smem_u32(const void* p) {
    unsigned a;
    asm("{ .reg .u64 t; cvta.to.shared.u64 t, %1; cvt.u32.u64 %0, t; }" : "=r"(a) : "l"(p));
    return a;
}

// ---------------- warp-MMA + cp.async helpers (portable: sm_80+) --------------
__device__ __forceinline__ void ldsm_x4(unsigned& r0, unsigned& r1, unsigned& r2,
                                        unsigned& r3, unsigned addr) {
    asm volatile("ldmatrix.sync.aligned.m8n8.x4.shared.b16 {%0,%1,%2,%3}, [%4];"
        : "=r"(r0), "=r"(r1), "=r"(r2), "=r"(r3) : "r"(addr));
}
__device__ __forceinline__ void ldsm_x4_t(unsigned& r0, unsigned& r1, unsigned& r2,
                                          unsigned& r3, unsigned addr) {
    asm volatile("ldmatrix.sync.aligned.m8n8.x4.trans.shared.b16 {%0,%1,%2,%3}, [%4];"
        : "=r"(r0), "=r"(r1), "=r"(r2), "=r"(r3) : "r"(addr));
}
__device__ __forceinline__ void mma16816(float* d, const unsigned* a, const unsigned* b) {
    asm volatile("mma.sync.aligned.m16n8k16.row.col.f32.bf16.bf16.f32 "
        "{%0,%1,%2,%3}, {%4,%5,%6,%7}, {%8,%9}, {%0,%1,%2,%3};"
        : "+f"(d[0]), "+f"(d[1]), "+f"(d[2]), "+f"(d[3])
        : "r"(a[0]), "r"(a[1]), "r"(a[2]), "r"(a[3]), "r"(b[0]), "r"(b[1]));
}
__device__ __forceinline__ void cp16(unsigned dst, const void* src) {
    asm volatile("cp.async.cg.shared.global [%0], [%1], 16;" :: "r"(dst), "l"(src));
}
#define CP_COMMIT() asm volatile("cp.async.commit_group;" ::: "memory")
#define CP_WAIT1()  asm volatile("cp.async.wait_group 1;" ::: "memory")
#define CP_WAIT0()  asm volatile("cp.async.wait_group 0;" ::: "memory")

// ---------------- prep: pe gather, seqs/time, keep, gates, time hi/lo --------
__global__ __launch_bounds__(256) void prep_kernel(
    const int* __restrict__ seqs_data, const float* __restrict__ seqs_in,
    const int* __restrict__ position, const float* __restrict__ time_in,
    const float* __restrict__ pos_table, const float* __restrict__ gate_W,
    const float* __restrict__ gate_b)
{
    const int n = blockIdx.x;
    const int h = threadIdx.x;
    const size_t idx = (size_t)n * HDIM + h;
    const int p = position[n];
    const float pe = pos_table[(size_t)p * HDIM + h];
    const float t = time_in[idx] + pe;
    const float keep = (seqs_data[n] != ITEMPAD) ? 1.f : 0.f;
    g_seqs[idx] = (seqs_in[idx] + pe) * keep;
    g_time[idx] = t;
    __nv_bfloat16 th, tl;
    split_bf(t, th, tl);
    g_t_hi[idx] = th; g_t_lo[idx] = tl;
    if (h == 0) g_keep[n] = keep;

    __shared__ float red[2][8];
    float p0 = t * gate_W[h];
    float p1 = t * gate_W[HDIM + h];
    #pragma unroll
    for (int o = 16; o; o >>= 1) {
        p0 += __shfl_xor_sync(0xffffffffu, p0, o);
        p1 += __shfl_xor_sync(0xffffffffu, p1, o);
    }
    if ((h & 31) == 0) { red[0][h >> 5] = p0; red[1][h >> 5] = p1; }
    __syncthreads();
    if (h < 2) {
        float s = 0.f;
        #pragma unroll
        for (int j = 0; j < 8; j++) s += red[h][j];
        g_gates[(size_t)n * 2 + h] = 1.f / (1.f + __expf(-(s + gate_b[h])));
    }
}

// ---------------- weight conversion ------------------------------------------
__global__ __launch_bounds__(256) void wconv_kernel(
    const float* __restrict__ q, const float* __restrict__ k,
    const float* __restrict__ v, const float* __restrict__ c1,
    const float* __restrict__ c2)
{
    const int i = blockIdx.x * blockDim.x + threadIdx.x;
    if (i >= 5 * 32768) return;
    const int mat = i >> 15, rem = i & 32767;
    const float* src = (mat == 0) ? q : (mat == 1) ? k : (mat == 2) ? v : (mat == 3) ? c1 : c2;
    float4 x = ((const float4*)src)[rem];
    __nv_bfloat16 h0,l0,h1,l1,h2,l2,h3,l3;
    split_bf(x.x,h0,l0); split_bf(x.y,h1,l1); split_bf(x.z,h2,l2); split_bf(x.w,h3,l3);
    const size_t o = ((size_t)mat << 17) + (size_t)rem * 4;
    *(uint2*)(g_w_hi + o) = make_uint2(pack_bf2(h0,h1), pack_bf2(h2,h3));
    *(uint2*)(g_w_lo + o) = make_uint2(pack_bf2(l0,l1), pack_bf2(l2,l3));
}

// ---------------- fused LN(seqs) + (seqs+time) split --------------------------
__global__ __launch_bounds__(256) void lnadd_kernel(
    const float* __restrict__ g, const float* __restrict__ beta,
    float* __restrict__ Q, __nv_bfloat16* __restrict__ Dh,
    __nv_bfloat16* __restrict__ Dl, __nv_bfloat16* __restrict__ Sh,
    __nv_bfloat16* __restrict__ Sl)
{
    const int n = blockIdx.x;
    const int h = threadIdx.x;
    const size_t idx = (size_t)n * HDIM + h;
    const float x = g_seqs[idx];
    float s = x, q = x * x;
    __shared__ float rs[8], rq[8];
    #pragma unroll
    for (int o = 16; o; o >>= 1) {
        s += __shfl_xor_sync(0xffffffffu, s, o);
        q += __shfl_xor_sync(0xffffffffu, q, o);
    }
    if ((h & 31) == 0) { rs[h >> 5] = s; rq[h >> 5] = q; }
    __syncthreads();
    float tot = 0.f, totq = 0.f;
    #pragma unroll
    for (int j = 0; j < 8; j++) { tot += rs[j]; totq += rq[j]; }
    const float mean = tot * (1.f / HDIM);
    const float var  = totq * (1.f / HDIM) - mean * mean;
    const float y = (x - mean) * rsqrtf(var + 1e-8f) * g[h] + beta[h];
    Q[idx] = y;
    __nv_bfloat16 hh, ll;
    split_bf(y, hh, ll);
    Dh[idx] = hh; Dl[idx] = ll;
    const float st = x + g_time[idx];
    split_bf(st, hh, ll);
    Sh[idx] = hh; Sl[idx] = ll;
}

// ---------------- layernorm (+residual, +bf16 split outputs) ------------------
template<bool ADD, bool BF>
__global__ __launch_bounds__(256) void ln_kernel(
    const float* __restrict__ A, const float* __restrict__ B2,
    const float* __restrict__ g, const float* __restrict__ beta,
    float* __restrict__ dst, __nv_bfloat16* __restrict__ Dh,
    __nv_bfloat16* __restrict__ Dl)
{
    const int n = blockIdx.x;
    const int h = threadIdx.x;
    const size_t idx = (size_t)n * HDIM + h;
    float x = A[idx];
    if (ADD) x += B2[idx];
    float s = x, q = x * x;
    __shared__ float rs[8], rq[8];
    #pragma unroll
    for (int o = 16; o; o >>= 1) {
        s += __shfl_xor_sync(0xffffffffu, s, o);
        q += __shfl_xor_sync(0xffffffffu, q, o);
    }
    if ((h & 31) == 0) { rs[h >> 5] = s; rq[h >> 5] = q; }
    __syncthreads();
    float tot = 0.f, totq = 0.f;
    #pragma unroll
    for (int j = 0; j < 8; j++) { tot += rs[j]; totq += rq[j]; }
    const float mean = tot * (1.f / HDIM);
    const float var  = totq * (1.f / HDIM) - mean * mean;
    const float y = (x - mean) * rsqrtf(var + 1e-8f) * g[h] + beta[h];
    dst[idx] = y;
    if (BF) {
        __nv_bfloat16 hh, ll;
        split_bf(y, hh, ll);
        Dh[idx] = hh; Dl[idx] = ll;
    }
}

// ---------------- GEMM v3: 128x128 tile, cp.async double-buffered -------------
// 512 threads = 16 warps (4m x 4n), warp tile 32x32.
// EPI: 0 = fp32 out, 1 = relu -> bf16 hi/lo, 2 = (+R)*keep -> fp32, 3 = bf16 hi/lo
#define ASTRIDE 72
#define TSZ (128 * ASTRIDE)             // bf16 elems per tile slot
#define BUFSZ (4 * TSZ)                 // AH, AL, BH, BL
#define GEMM_SMEM (2 * BUFSZ * 2)       // bytes (two buffers)

#define GEMM_ISSUE(c, bb)                                                        \
    {                                                                            \
        _Pragma("unroll")                                                        \
        for (int i_ = 0; i_ < 2; i_++) {                                         \
            const int v_ = tid + 512 * i_;                                       \
            const int r_ = v_ >> 3, cc_ = v_ & 7;                                \
            const size_t gA_ = (size_t)(bm + r_) * HDIM + (c) * 64 + cc_ * 8;    \
            const size_t gB_ = (size_t)(bn + r_) * HDIM + (c) * 64 + cc_ * 8;    \
            const unsigned so_ = sbase + ((bb) + r_ * ASTRIDE + cc_ * 8) * 2u;   \
            cp16(so_,               Ah + gA_);                                   \
            cp16(so_ + TSZ * 2,     Al + gA_);                                   \
            cp16(so_ + 2 * TSZ * 2, Wh + gB_);                                   \
            cp16(so_ + 3 * TSZ * 2, Wl + gB_);                                   \
        }                                                                        \
        CP_COMMIT();                                                             \
    }

template<int EPI>
__global__ __launch_bounds__(512, 1) void gemm_mma(
    const __nv_bfloat16* __restrict__ Ah, const __nv_bfloat16* __restrict__ Al,
    const __nv_bfloat16* __restrict__ Wh, const __nv_bfloat16* __restrict__ Wl,
    const float* __restrict__ bias, const float* __restrict__ R,
    float* __restrict__ Cf, __nv_bfloat16* __restrict__ Ch,
    __nv_bfloat16* __restrict__ Cl)
{
    extern __shared__ __align__(16) __nv_bfloat16 smb[];
    const int tid = threadIdx.x;
    const int lane = tid & 31, wid = tid >> 5;
    const int bm = blockIdx.x << 7;
    const int bn = blockIdx.y << 7;
    const int wm = (wid >> 2) << 5;     // 0,32,64,96
    const int wn = (wid & 3) << 5;      // 0,32,64,96

    float acc[2][4][4];
    #pragma unroll
    for (int mt = 0; mt < 2; mt++)
        #pragma unroll
        for (int nt = 0; nt < 4; nt++)
            #pragma unroll
            for (int j = 0; j < 4; j++) acc[mt][nt][j] = 0.f;

    const unsigned sbase = smem_u32(smb);
    const int a_r = ((lane >> 3) & 1) * 8 + (lane & 7);
    const int a_c = (lane >> 4) * 8;
    const int b_r = (lane >> 4) * 8 + (lane & 7);
    const int b_c = ((lane >> 3) & 1) * 8;

    GEMM_ISSUE(0, 0u);

    for (int c = 0; c < 4; c++) {
        if (c + 1 < 4) {
            GEMM_ISSUE(c + 1, (unsigned)(((c + 1) & 1) * BUFSZ));
            CP_WAIT1();
        } else {
            CP_WAIT0();
        }
        __syncthreads();
        const unsigned bb = (unsigned)((c & 1) * BUFSZ) * 2u;   // byte offset

        #pragma unroll
        for (int ks = 0; ks < 4; ks++) {
            const int k = ks * 16;
            unsigned ah[2][4], al[2][4], bh[4][2], bl[4][2];
            #pragma unroll
            for (int mt = 0; mt < 2; mt++) {
                const unsigned off =
                    ((unsigned)((wm + mt * 16 + a_r) * ASTRIDE + k + a_c)) * 2u;
                ldsm_x4(ah[mt][0], ah[mt][1], ah[mt][2], ah[mt][3],
                        sbase + bb + off);
                ldsm_x4(al[mt][0], al[mt][1], al[mt][2], al[mt][3],
                        sbase + bb + TSZ * 2 + off);
            }
            #pragma unroll
            for (int nt2 = 0; nt2 < 2; nt2++) {
                const unsigned off =
                    ((unsigned)((wn + nt2 * 16 + b_r) * ASTRIDE + k + b_c)) * 2u;
                unsigned r0, r1, r2, r3;
                ldsm_x4(r0, r1, r2, r3, sbase + bb + 2 * TSZ * 2 + off);
                bh[nt2 * 2][0] = r0; bh[nt2 * 2][1] = r1;
                bh[nt2 * 2 + 1][0] = r2; bh[nt2 * 2 + 1][1] = r3;
                ldsm_x4(r0, r1, r2, r3, sbase + bb + 3 * TSZ * 2 + off);
                bl[nt2 * 2][0] = r0; bl[nt2 * 2][1] = r1;
                bl[nt2 * 2 + 1][0] = r2; bl[nt2 * 2 + 1][1] = r3;
            }
            #pragma unroll
            for (int mt = 0; mt < 2; mt++)
                #pragma unroll
                for (int nt = 0; nt < 4; nt++) {
                    mma16816(acc[mt][nt], ah[mt], bh[nt]);
                    mma16816(acc[mt][nt], al[mt], bh[nt]);
                    mma16816(acc[mt][nt], ah[mt], bl[nt]);
                }
        }
        __syncthreads();
    }

    const int qrow = lane >> 2;
    const int qcol = (lane & 3) * 2;
    #pragma unroll
    for (int mt = 0; mt < 2; mt++) {
        #pragma unroll
        for (int half = 0; half < 2; half++) {
            const int row = bm + wm + mt * 16 + qrow + half * 8;
            float keep = 1.f;
            if (EPI == 2) keep = g_keep[row];
            #pragma unroll
            for (int nt = 0; nt < 4; nt++) {
                const int col = bn + wn + nt * 8 + qcol;
                float v0 = acc[mt][nt][half * 2]     + __ldg(bias + col);
                float v1 = acc[mt][nt][half * 2 + 1] + __ldg(bias + col + 1);
                const size_t o = (size_t)row * HDIM + col;
                if (EPI == 0) {
                    *(float2*)(Cf + o) = make_float2(v0, v1);
                } else if (EPI == 1 || EPI == 3) {
                    if (EPI == 1) { v0 = fmaxf(v0, 0.f); v1 = fmaxf(v1, 0.f); }
                    __nv_bfloat16 h0, l0, h1, l1;
                    split_bf(v0, h0, l0); split_bf(v1, h1, l1);
                    *(unsigned*)(Ch + o) = pack_bf2(h0, h1);
                    *(unsigned*)(Cl + o) = pack_bf2(l0, l1);
                } else {
                    const float2 rr = *(const float2*)(R + o);
                    *(float2*)(Cf + o) = make_float2((v0 + rr.x) * keep,
                                                     (v1 + rr.y) * keep);
                }
            }
        }
    }
}

// ---------------- flash attention (MMA, causal, gated) ------------------------
#define AT_AST 72
#define SQH_B 0
#define SQL_B (128 * AT_AST * 2)
#define SKH_B (2 * 128 * AT_AST * 2)
#define SKL_B (SKH_B + 64 * AT_AST * 2)
#define SVH_B (SKL_B + 64 * AT_AST * 2)
#define SVL_B (SVH_B + 64 * AT_AST * 2)
#define STG_B (SVL_B + 64 * AT_AST * 2)
#define ATTN_SMEM (STG_B + 64 * 4)

__global__ __launch_bounds__(256) void attn_kernel(int blk)
{
    extern __shared__ __align__(16) __nv_bfloat16 smb[];
    float* stgk = (float*)((char*)smb + STG_B);

    const int tid = threadIdx.x;
    const int lane = tid & 31, wid = tid >> 5;
    const int qt = blockIdx.x, hh = blockIdx.y, b = blockIdx.z;
    const int q0 = qt * 128;
    const size_t base = (size_t)b * LSEQ;
    const int wm = wid * 16;
    const unsigned sbase = smem_u32(smb);

    #pragma unroll
    for (int i = 0; i < 4; i++) {
        const int v = tid + 256 * i;
        const int r = v >> 3, cc = v & 7;
        const size_t go = (base + q0 + r) * HDIM + hh * HEADD + cc * 8;
        *(uint4*)((char*)smb + SQH_B + (r * AT_AST + cc * 8) * 2) = *(const uint4*)(g_qh + go);
        *(uint4*)((char*)smb + SQL_B + (r * AT_AST + cc * 8) * 2) = *(const uint4*)(g_ql + go);
    }
    __syncthreads();

    const int a_r = ((lane >> 3) & 1) * 8 + (lane & 7);
    const int a_c = (lane >> 4) * 8;
    const int b_r = (lane >> 4) * 8 + (lane & 7);
    const int b_c = ((lane >> 3) & 1) * 8;
    const int v_r = lane & 15;
    const int v_c = (lane >> 4) * 8;

    unsigned aqh[4][4], aql[4][4];
    #pragma unroll
    for (int ks = 0; ks < 4; ks++) {
        const unsigned off = ((unsigned)((wm + a_r) * AT_AST + ks * 16 + a_c)) * 2u;
        ldsm_x4(aqh[ks][0], aqh[ks][1], aqh[ks][2], aqh[ks][3], sbase + SQH_B + off);
        ldsm_x4(aql[ks][0], aql[ks][1], aql[ks][2], aql[ks][3], sbase + SQL_B + off);
    }

    const int r = lane >> 2;
    const int c2 = (lane & 3) * 2;
    const float cq0 = 0.125f * g_gates[(base + q0 + wm + r) * 2 + blk];
    const float cq1 = 0.125f * g_gates[(base + q0 + wm + r + 8) * 2 + blk];
    float mrow0 = -1e30f, mrow1 = -1e30f, lrow0 = 0.f, lrow1 = 0.f;
    float O[8][4];
    #pragma unroll
    for (int nt = 0; nt < 8; nt++)
        #pragma unroll
        for (int j = 0; j < 4; j++) O[nt][j] = 0.f;

    const int nkt = 2 * (qt + 1);
    for (int kt = 0; kt < nkt; kt++) {
        const int k0 = kt * 64;
        __syncthreads();
        #pragma unroll
        for (int i = 0; i < 2; i++) {
            const int v = tid + 256 * i;
            const int rr = v >> 3, cc = v & 7;
            const size_t go = (base + k0 + rr) * HDIM + hh * HEADD + cc * 8;
            const int so = (rr * AT_AST + cc * 8) * 2;
            *(uint4*)((char*)smb + SKH_B + so) = *(const uint4*)(g_kh + go);
            *(uint4*)((char*)smb + SKL_B + so) = *(const uint4*)(g_kl + go);
            *(uint4*)((char*)smb + SVH_B + so) = *(const uint4*)(g_vh + go);
            *(uint4*)((char*)smb + SVL_B + so) = *(const uint4*)(g_vl + go);
        }
        if (tid < 64) stgk[tid] = g_gates[(base + k0 + tid) * 2 + blk];
        __syncthreads();

        float S[8][4];
        #pragma unroll
        for (int nt = 0; nt < 8; nt++)
            #pragma unroll
            for (int j = 0; j < 4; j++) S[nt][j] = 0.f;
        #pragma unroll
        for (int ks = 0; ks < 4; ks++) {
            #pragma unroll
            for (int n16 = 0; n16 < 4; n16++) {
                const unsigned off =
                    ((unsigned)((n16 * 16 + b_r) * AT_AST + ks * 16 + b_c)) * 2u;
                unsigned h0, h1, h2, h3, l0, l1, l2, l3;
                ldsm_x4(h0, h1, h2, h3, sbase + SKH_B + off);
                ldsm_x4(l0, l1, l2, l3, sbase + SKL_B + off);
                unsigned bh0[2] = {h0, h1}, bh1[2] = {h2, h3};
                unsigned bl0[2] = {l0, l1}, bl1[2] = {l2, l3};
                mma16816(S[2 * n16], aqh[ks], bh0);
                mma16816(S[2 * n16], aql[ks], bh0);
                mma16816(S[2 * n16], aqh[ks], bl0);
                mma16816(S[2 * n16 + 1], aqh[ks], bh1);
                mma16816(S[2 * n16 + 1], aql[ks], bh1);
                mma16816(S[2 * n16 + 1], aqh[ks], bl1);
            }
        }

        const bool need_mask = (k0 + 63 > q0 + wm);
        float mt0 = -1e30f, mt1 = -1e30f;
        #pragma unroll
        for (int nt = 0; nt < 8; nt++) {
            const int col = nt * 8 + c2;
            const float tga = stgk[col], tgb = stgk[col + 1];
            float v0 = S[nt][0] * cq0 * tga;
            float v1 = S[nt][1] * cq0 * tgb;
            float v2 = S[nt][2] * cq1 * tga;
            float v3 = S[nt][3] * cq1 * tgb;
            if (need_mask) {
                const int kg = k0 + col;
                const int qa = q0 + wm + r, qb2 = qa + 8;
                if (kg     > qa)  v0 = -1e30f;
                if (kg + 1 > qa)  v1 = -1e30f;
                if (kg     > qb2) v2 = -1e30f;
                if (kg + 1 > qb2) v3 = -1e30f;
            }
            S[nt][0] = v0; S[nt][1] = v1; S[nt][2] = v2; S[nt][3] = v3;
            mt0 = fmaxf(mt0, fmaxf(v0, v1));
            mt1 = fmaxf(mt1, fmaxf(v2, v3));
        }
        mt0 = fmaxf(mt0, __shfl_xor_sync(0xffffffffu, mt0, 1));
        mt0 = fmaxf(mt0, __shfl_xor_sync(0xffffffffu, mt0, 2));
        mt1 = fmaxf(mt1, __shfl_xor_sync(0xffffffffu, mt1, 1));
        mt1 = fmaxf(mt1, __shfl_xor_sync(0xffffffffu, mt1, 2));
        const float mn0 = fmaxf(mrow0, mt0), mn1 = fmaxf(mrow1, mt1);
        const float al0 = __expf(mrow0 - mn0), al1 = __expf(mrow1 - mn1);
        mrow0 = mn0; mrow1 = mn1;

        float rs0 = 0.f, rs1 = 0.f;
        unsigned pah[4][4], pal[4][4];
        #pragma unroll
        for (int j2 = 0; j2 < 4; j2++) {
            float p0 = __expf(S[2 * j2][0] - mn0);
            float p1 = __expf(S[2 * j2][1] - mn0);
            float p2 = __expf(S[2 * j2][2] - mn1);
            float p3 = __expf(S[2 * j2][3] - mn1);
            float p4 = __expf(S[2 * j2 + 1][0] - mn0);
            float p5 = __expf(S[2 * j2 + 1][1] - mn0);
            float p6 = __expf(S[2 * j2 + 1][2] - mn1);
            float p7 = __expf(S[2 * j2 + 1][3] - mn1);
            rs0 += (p0 + p1) + (p4 + p5);
            rs1 += (p2 + p3) + (p6 + p7);
            __nv_bfloat16 h0,l0,h1,l1,h2,l2,h3,l3,h4,l4,h5,l5,h6,l6,h7,l7;
            split_bf(p0,h0,l0); split_bf(p1,h1,l1); split_bf(p2,h2,l2); split_bf(p3,h3,l3);
            split_bf(p4,h4,l4); split_bf(p5,h5,l5); split_bf(p6,h6,l6); split_bf(p7,h7,l7);
            pah[j2][0] = pack_bf2(h0, h1); pal[j2][0] = pack_bf2(l0, l1);
            pah[j2][1] = pack_bf2(h2, h3); pal[j2][1] = pack_bf2(l2, l3);
            pah[j2][2] = pack_bf2(h4, h5); pal[j2][2] = pack_bf2(l4, l5);
            pah[j2][3] = pack_bf2(h6, h7); pal[j2][3] = pack_bf2(l6, l7);
        }
        rs0 += __shfl_xor_sync(0xffffffffu, rs0, 1);
        rs0 += __shfl_xor_sync(0xffffffffu, rs0, 2);
        rs1 += __shfl_xor_sync(0xffffffffu, rs1, 1);
        rs1 += __shfl_xor_sync(0xffffffffu, rs1, 2);
        lrow0 = lrow0 * al0 + rs0;
        lrow1 = lrow1 * al1 + rs1;

        #pragma unroll
        for (int nt = 0; nt < 8; nt++) {
            O[nt][0] *= al0; O[nt][1] *= al0;
            O[nt][2] *= al1; O[nt][3] *= al1;
        }

        #pragma unroll
        for (int ks = 0; ks < 4; ks++) {
            #pragma unroll
            for (int n16 = 0; n16 < 4; n16++) {
                const unsigned off =
                    ((unsigned)((ks * 16 + v_r) * AT_AST + n16 * 16 + v_c)) * 2u;
                unsigned h0, h1, h2, h3, l0, l1, l2, l3;
                ldsm_x4_t(h0, h1, h2, h3, sbase + SVH_B + off);
                ldsm_x4_t(l0, l1, l2, l3, sbase + SVL_B + off);
                unsigned bh0[2] = {h0, h1}, bh1[2] = {h2, h3};
                unsigned bl0[2] = {l0, l1}, bl1[2] = {l2, l3};
                mma16816(O[2 * n16], pah[ks], bh0);
                mma16816(O[2 * n16], pal[ks], bh0);
                mma16816(O[2 * n16], pah[ks], bl0);
                mma16816(O[2 * n16 + 1], pah[ks], bh1);
                mma16816(O[2 * n16 + 1], pal[ks], bh1);
                mma16816(O[2 * n16 + 1], pah[ks], bl1);
            }
        }
    }

    const float inv0 = 1.f / lrow0, inv1 = 1.f / lrow1;
    const size_t row0 = (base + q0 + wm + r) * HDIM + hh * HEADD;
    const size_t row1 = (base + q0 + wm + r + 8) * HDIM + hh * HEADD;
    #pragma unroll
    for (int nt = 0; nt < 8; nt++) {
        const int col = nt * 8 + c2;
        *(float2*)(g_ao + row0 + col) = make_float2(O[nt][0] * inv0, O[nt][1] * inv0);
        *(float2*)(g_ao + row1 + col) = make_float2(O[nt][2] * inv1, O[nt][3] * inv1);
    }
}

// ---------------- launcher ---------------------------------------------------
extern "C" void kernel_launch(void* const* d_in, const int* in_sizes, int n_in,
                              void* d_out, int out_size)
{
    const int*   seqs_data = (const int*)  d_in[0];
    const float* seqs_in   = (const float*)d_in[1];
    const int*   position  = (const int*)  d_in[2];
    const float* time_in   = (const float*)d_in[3];
    const float* pos_table = (const float*)d_in[4];
    const float* gate_W    = (const float*)d_in[5];
    const float* gate_b    = (const float*)d_in[6];
    const float* ln_attn_g = (const float*)d_in[7];
    const float* ln_attn_b = (const float*)d_in[8];
    const float* qW        = (const float*)d_in[9];
    const float* qb        = (const float*)d_in[10];
    const float* kW        = (const float*)d_in[11];
    const float* kb        = (const float*)d_in[12];
    const float* vW        = (const float*)d_in[13];
    const float* vb        = (const float*)d_in[14];
    const float* ln_ffn_g  = (const float*)d_in[15];
    const float* ln_ffn_b  = (const float*)d_in[16];
    const float* c1W       = (const float*)d_in[17];
    const float* c1b       = (const float*)d_in[18];
    const float* c2W       = (const float*)d_in[19];
    const float* c2b       = (const float*)d_in[20];
    const float* last_g    = (const float*)d_in[21];
    const float* last_b    = (const float*)d_in[22];

    float *p_seqs, *p_time, *p_Q, *p_ao, *p_x;
    __nv_bfloat16 *p_th, *p_tl, *p_ah, *p_al, *p_bh, *p_bl, *p_wh, *p_wl;
    __nv_bfloat16 *p_qh, *p_ql, *p_kh, *p_kl, *p_vh, *p_vl;
    cudaGetSymbolAddress((void**)&p_seqs, g_seqs);
    cudaGetSymbolAddress((void**)&p_time, g_time);
    cudaGetSymbolAddress((void**)&p_Q,    g_Q);
    cudaGetSymbolAddress((void**)&p_ao,   g_ao);
    cudaGetSymbolAddress((void**)&p_x,    g_x);
    cudaGetSymbolAddress((void**)&p_th,   g_t_hi);
    cudaGetSymbolAddress((void**)&p_tl,   g_t_lo);
    cudaGetSymbolAddress((void**)&p_ah,   g_a_hi);
    cudaGetSymbolAddress((void**)&p_al,   g_a_lo);
    cudaGetSymbolAddress((void**)&p_bh,   g_b_hi);
    cudaGetSymbolAddress((void**)&p_bl,   g_b_lo);
    cudaGetSymbolAddress((void**)&p_wh,   g_w_hi);
    cudaGetSymbolAddress((void**)&p_wl,   g_w_lo);
    cudaGetSymbolAddress((void**)&p_qh,   g_qh);
    cudaGetSymbolAddress((void**)&p_ql,   g_ql);
    cudaGetSymbolAddress((void**)&p_kh,   g_kh);
    cudaGetSymbolAddress((void**)&p_kl,   g_kl);
    cudaGetSymbolAddress((void**)&p_vh,   g_vh);
    cudaGetSymbolAddress((void**)&p_vl,   g_vl);

    cudaFuncSetAttribute(attn_kernel, cudaFuncAttributeMaxDynamicSharedMemorySize, ATTN_SMEM);
    cudaFuncSetAttribute(gemm_mma<0>, cudaFuncAttributeMaxDynamicSharedMemorySize, GEMM_SMEM);
    cudaFuncSetAttribute(gemm_mma<1>, cudaFuncAttributeMaxDynamicSharedMemorySize, GEMM_SMEM);
    cudaFuncSetAttribute(gemm_mma<2>, cudaFuncAttributeMaxDynamicSharedMemorySize, GEMM_SMEM);
    cudaFuncSetAttribute(gemm_mma<3>, cudaFuncAttributeMaxDynamicSharedMemorySize, GEMM_SMEM);

    prep_kernel<<<NROWS, 256>>>(seqs_data, seqs_in, position, time_in,
                                pos_table, gate_W, gate_b);
    wconv_kernel<<<640, 256>>>(qW, kW, vW, c1W, c2W);

    const size_t WSZ = (size_t)HDIM * HDIM;
    const dim3 ggrid(NROWS / 128, HDIM / 128);
    for (int i = 0; i < 2; i++) {
        lnadd_kernel<<<NROWS, 256>>>(ln_attn_g + i * HDIM, ln_attn_b + i * HDIM,
                                     p_Q, p_ah, p_al, p_bh, p_bl);
        gemm_mma<3><<<ggrid, 512, GEMM_SMEM>>>(p_ah, p_al,
            p_wh + (0 * 2 + i) * WSZ, p_wl + (0 * 2 + i) * WSZ,
            qb + i * HDIM, nullptr, nullptr, p_qh, p_ql);
        gemm_mma<3><<<ggrid, 512, GEMM_SMEM>>>(p_th, p_tl,
            p_wh + (1 * 2 + i) * WSZ, p_wl + (1 * 2 + i) * WSZ,
            kb + i * HDIM, nullptr, nullptr, p_kh, p_kl);
        gemm_mma<3><<<ggrid, 512, GEMM_SMEM>>>(p_bh, p_bl,
            p_wh + (2 * 2 + i) * WSZ, p_wl + (2 * 2 + i) * WSZ,
            vb + i * HDIM, nullptr, nullptr, p_vh, p_vl);
        attn_kernel<<<dim3(4, 4, NBATCH), 256, ATTN_SMEM>>>(i);
        ln_kernel<true, true><<<NROWS, 256>>>(p_Q, p_ao,
            ln_ffn_g + i * HDIM, ln_ffn_b + i * HDIM, p_x, p_ah, p_al);
        gemm_mma<1><<<ggrid, 512, GEMM_SMEM>>>(p_ah, p_al,
            p_wh + (3 * 2 + i) * WSZ, p_wl + (3 * 2 + i) * WSZ,
            c1b + i * HDIM, nullptr, nullptr, p_bh, p_bl);
        gemm_mma<2><<<ggrid, 512, GEMM_SMEM>>>(p_bh, p_bl,
            p_wh + (4 * 2 + i) * WSZ, p_wl + (4 * 2 + i) * WSZ,
            c2b + i * HDIM, p_x, p_seqs, nullptr, nullptr);
    }
    ln_kernel<false, false><<<NROWS, 256>>>(p_seqs, nullptr, last_g, last_b,
                                            (float*)d_out, nullptr, nullptr);
}

// round 8
// speedup vs baseline: 1.1491x; 1.1491x over previous
#include <cuda_runtime.h>
#include <cuda_bf16.h>
#include <math.h>

#define NROWS 32768          // B*L
#define HDIM  256
#define LSEQ  512
#define NBATCH 64
#define HEADD 64
#define ITEMPAD 49999

typedef unsigned long long u64;

// ---------------- scratch (device globals; no allocs allowed) ----------------
__device__ __align__(16) float g_seqs[NROWS * HDIM];
__device__ __align__(16) float g_time[NROWS * HDIM];
__device__ __align__(16) float g_Q   [NROWS * HDIM];
__device__ __align__(16) float g_ao  [NROWS * HDIM];
__device__ __align__(16) float g_x   [NROWS * HDIM];
__device__ float g_keep[NROWS];
__device__ float g_gates[NROWS * 2];

__device__ __align__(16) __nv_bfloat16 g_t_hi[NROWS * HDIM];
__device__ __align__(16) __nv_bfloat16 g_t_lo[NROWS * HDIM];
__device__ __align__(16) __nv_bfloat16 g_a_hi[NROWS * HDIM];
__device__ __align__(16) __nv_bfloat16 g_a_lo[NROWS * HDIM];
__device__ __align__(16) __nv_bfloat16 g_b_hi[NROWS * HDIM];
__device__ __align__(16) __nv_bfloat16 g_b_lo[NROWS * HDIM];
__device__ __align__(16) __nv_bfloat16 g_qh[NROWS * HDIM];
__device__ __align__(16) __nv_bfloat16 g_ql[NROWS * HDIM];
__device__ __align__(16) __nv_bfloat16 g_kh[NROWS * HDIM];
__device__ __align__(16) __nv_bfloat16 g_kl[NROWS * HDIM];
__device__ __align__(16) __nv_bfloat16 g_vh[NROWS * HDIM];
__device__ __align__(16) __nv_bfloat16 g_vl[NROWS * HDIM];
__device__ __align__(16) __nv_bfloat16 g_w_hi[5 * 2 * HDIM * HDIM];
__device__ __align__(16) __nv_bfloat16 g_w_lo[5 * 2 * HDIM * HDIM];

// ---------------- small helpers ----------------------------------------------
__device__ __forceinline__ void split_bf(float x, __nv_bfloat16& h, __nv_bfloat16& l) {
    h = __float2bfloat16_rn(x);
    l = __float2bfloat16_rn(x - __bfloat162float(h));
}
__device__ __forceinline__ unsigned pack_bf2(__nv_bfloat16 a, __nv_bfloat16 b) {
    return (unsigned)__bfloat16_as_ushort(a) | ((unsigned)__bfloat16_as_ushort(b) << 16);
}
__device__ __forceinline__ unsigned smem_u32(const void* p) {
    unsigned a;
    asm("{ .reg .u64 t; cvta.to.shared.u64 t, %1; cvt.u32.u64 %0, t; }" : "=r"(a) : "l"(p));
    return a;
}

// ---------------- warp-MMA + cp.async helpers (portable: sm_80+) --------------
__device__ __forceinline__ void ldsm_x4(unsigned& r0, unsigned& r1, unsigned& r2,
                                        unsigned& r3, unsigned addr) {
    asm volatile("ldmatrix.sync.aligned.m8n8.x4.shared.b16 {%0,%1,%2,%3}, [%4];"
        : "=r"(r0), "=r"(r1), "=r"(r2), "=r"(r3) : "r"(addr));
}
__device__ __forceinline__ void ldsm_x4_t(unsigned& r0, unsigned& r1, unsigned& r2,
                                          unsigned& r3, unsigned addr) {
    asm volatile("ldmatrix.sync.aligned.m8n8.x4.trans.shared.b16 {%0,%1,%2,%3}, [%4];"
        : "=r"(r0), "=r"(r1), "=r"(r2), "=r"(r3) : "r"(addr));
}
__device__ __forceinline__ void mma16816(float* d, const unsigned* a, const unsigned* b) {
    asm volatile("mma.sync.aligned.m16n8k16.row.col.f32.bf16.bf16.f32 "
        "{%0,%1,%2,%3}, {%4,%5,%6,%7}, {%8,%9}, {%0,%1,%2,%3};"
        : "+f"(d[0]), "+f"(d[1]), "+f"(d[2]), "+f"(d[3])
        : "r"(a[0]), "r"(a[1]), "r"(a[2]), "r"(a[3]), "r"(b[0]), "r"(b[1]));
}
__device__ __forceinline__ void cp16(unsigned dst, const void* src) {
    asm volatile("cp.async.cg.shared.global [%0], [%1], 16;" :: "r"(dst), "l"(src));
}
__device__ __forceinline__ void cp4(unsigned dst, const void* src) {
    asm volatile("cp.async.ca.shared.global [%0], [%1], 4;" :: "r"(dst), "l"(src));
}
#define CP_COMMIT() asm volatile("cp.async.commit_group;" ::: "memory")
#define CP_WAIT1()  asm volatile("cp.async.wait_group 1;" ::: "memory")
#define CP_WAIT0()  asm volatile("cp.async.wait_group 0;" ::: "memory")

// ---------------- prep -------------------------------------------------------
__global__ __launch_bounds__(256) void prep_kernel(
    const int* __restrict__ seqs_data, const float* __restrict__ seqs_in,
    const int* __restrict__ position, const float* __restrict__ time_in,
    const float* __restrict__ pos_table, const float* __restrict__ gate_W,
    const float* __restrict__ gate_b)
{
    const int n = blockIdx.x;
    const int h = threadIdx.x;
    const size_t idx = (size_t)n * HDIM + h;
    const int p = position[n];
    const float pe = pos_table[(size_t)p * HDIM + h];
    const float t = time_in[idx] + pe;
    const float keep = (seqs_data[n] != ITEMPAD) ? 1.f : 0.f;
    g_seqs[idx] = (seqs_in[idx] + pe) * keep;
    g_time[idx] = t;
    __nv_bfloat16 th, tl;
    split_bf(t, th, tl);
    g_t_hi[idx] = th; g_t_lo[idx] = tl;
    if (h == 0) g_keep[n] = keep;

    __shared__ float red[2][8];
    float p0 = t * gate_W[h];
    float p1 = t * gate_W[HDIM + h];
    #pragma unroll
    for (int o = 16; o; o >>= 1) {
        p0 += __shfl_xor_sync(0xffffffffu, p0, o);
        p1 += __shfl_xor_sync(0xffffffffu, p1, o);
    }
    if ((h & 31) == 0) { red[0][h >> 5] = p0; red[1][h >> 5] = p1; }
    __syncthreads();
    if (h < 2) {
        float s = 0.f;
        #pragma unroll
        for (int j = 0; j < 8; j++) s += red[h][j];
        g_gates[(size_t)n * 2 + h] = 1.f / (1.f + __expf(-(s + gate_b[h])));
    }
}

// ---------------- weight conversion ------------------------------------------
__global__ __launch_bounds__(256) void wconv_kernel(
    const float* __restrict__ q, const float* __restrict__ k,
    const float* __restrict__ v, const float* __restrict__ c1,
    const float* __restrict__ c2)
{
    const int i = blockIdx.x * blockDim.x + threadIdx.x;
    if (i >= 5 * 32768) return;
    const int mat = i >> 15, rem = i & 32767;
    const float* src = (mat == 0) ? q : (mat == 1) ? k : (mat == 2) ? v : (mat == 3) ? c1 : c2;
    float4 x = ((const float4*)src)[rem];
    __nv_bfloat16 h0,l0,h1,l1,h2,l2,h3,l3;
    split_bf(x.x,h0,l0); split_bf(x.y,h1,l1); split_bf(x.z,h2,l2); split_bf(x.w,h3,l3);
    const size_t o = ((size_t)mat << 17) + (size_t)rem * 4;
    *(uint2*)(g_w_hi + o) = make_uint2(pack_bf2(h0,h1), pack_bf2(h2,h3));
    *(uint2*)(g_w_lo + o) = make_uint2(pack_bf2(l0,l1), pack_bf2(l2,l3));
}

// ---------------- fused LN(seqs) + (seqs+time) split --------------------------
__global__ __launch_bounds__(256) void lnadd_kernel(
    const float* __restrict__ g, const float* __restrict__ beta,
    float* __restrict__ Q, __nv_bfloat16* __restrict__ Dh,
    __nv_bfloat16* __restrict__ Dl, __nv_bfloat16* __restrict__ Sh,
    __nv_bfloat16* __restrict__ Sl)
{
    const int n = blockIdx.x;
    const int h = threadIdx.x;
    const size_t idx = (size_t)n * HDIM + h;
    const float x = g_seqs[idx];
    float s = x, q = x * x;
    __shared__ float rs[8], rq[8];
    #pragma unroll
    for (int o = 16; o; o >>= 1) {
        s += __shfl_xor_sync(0xffffffffu, s, o);
        q += __shfl_xor_sync(0xffffffffu, q, o);
    }
    if ((h & 31) == 0) { rs[h >> 5] = s; rq[h >> 5] = q; }
    __syncthreads();
    float tot = 0.f, totq = 0.f;
    #pragma unroll
    for (int j = 0; j < 8; j++) { tot += rs[j]; totq += rq[j]; }
    const float mean = tot * (1.f / HDIM);
    const float var  = totq * (1.f / HDIM) - mean * mean;
    const float y = (x - mean) * rsqrtf(var + 1e-8f) * g[h] + beta[h];
    Q[idx] = y;
    __nv_bfloat16 hh, ll;
    split_bf(y, hh, ll);
    Dh[idx] = hh; Dl[idx] = ll;
    const float st = x + g_time[idx];
    split_bf(st, hh, ll);
    Sh[idx] = hh; Sl[idx] = ll;
}

// ---------------- layernorm (+residual, +bf16 split outputs) ------------------
template<bool ADD, bool BF>
__global__ __launch_bounds__(256) void ln_kernel(
    const float* __restrict__ A, const float* __restrict__ B2,
    const float* __restrict__ g, const float* __restrict__ beta,
    float* __restrict__ dst, __nv_bfloat16* __restrict__ Dh,
    __nv_bfloat16* __restrict__ Dl)
{
    const int n = blockIdx.x;
    const int h = threadIdx.x;
    const size_t idx = (size_t)n * HDIM + h;
    float x = A[idx];
    if (ADD) x += B2[idx];
    float s = x, q = x * x;
    __shared__ float rs[8], rq[8];
    #pragma unroll
    for (int o = 16; o; o >>= 1) {
        s += __shfl_xor_sync(0xffffffffu, s, o);
        q += __shfl_xor_sync(0xffffffffu, q, o);
    }
    if ((h & 31) == 0) { rs[h >> 5] = s; rq[h >> 5] = q; }
    __syncthreads();
    float tot = 0.f, totq = 0.f;
    #pragma unroll
    for (int j = 0; j < 8; j++) { tot += rs[j]; totq += rq[j]; }
    const float mean = tot * (1.f / HDIM);
    const float var  = totq * (1.f / HDIM) - mean * mean;
    const float y = (x - mean) * rsqrtf(var + 1e-8f) * g[h] + beta[h];
    dst[idx] = y;
    if (BF) {
        __nv_bfloat16 hh, ll;
        split_bf(y, hh, ll);
        Dh[idx] = hh; Dl[idx] = ll;
    }
}

// ---------------- GEMM v4: 128x64 tile, 2 CTA/SM, cp.async double-buffer ------
// 256 threads = 8 warps (4m x 2n), warp tile 32x32.
#define ASTRIDE 72
#define A_TSZ (128 * ASTRIDE)        // 9216 elems
#define B_TSZ (64 * ASTRIDE)         // 4608 elems
#define BUF_ELE (2 * A_TSZ + 2 * B_TSZ)   // 27648 elems = 55296 bytes
#define GEMM_SMEM (2 * BUF_ELE * 2)       // 110592 bytes

#define GEMM_ISSUE(c, bufe)                                                      \
    {                                                                            \
        _Pragma("unroll")                                                        \
        for (int i_ = 0; i_ < 4; i_++) {                                         \
            const int v_ = tid + 256 * i_;                                       \
            const int r_ = v_ >> 3, cc_ = v_ & 7;                                \
            const size_t gA_ = (size_t)(bm + r_) * HDIM + (c) * 64 + cc_ * 8;    \
            const unsigned so_ = sbase + ((bufe) + r_ * ASTRIDE + cc_ * 8) * 2u; \
            cp16(so_,             Ah + gA_);                                     \
            cp16(so_ + A_TSZ * 2, Al + gA_);                                     \
        }                                                                        \
        _Pragma("unroll")                                                        \
        for (int i_ = 0; i_ < 2; i_++) {                                         \
            const int v_ = tid + 256 * i_;                                       \
            const int r_ = v_ >> 3, cc_ = v_ & 7;                                \
            const size_t gB_ = (size_t)(bn + r_) * HDIM + (c) * 64 + cc_ * 8;    \
            const unsigned so_ = sbase +                                         \
                ((bufe) + 2 * A_TSZ + r_ * ASTRIDE + cc_ * 8) * 2u;              \
            cp16(so_,             Wh + gB_);                                     \
            cp16(so_ + B_TSZ * 2, Wl + gB_);                                     \
        }                                                                        \
        CP_COMMIT();                                                             \
    }

template<int EPI>
__global__ __launch_bounds__(256, 2) void gemm_mma(
    const __nv_bfloat16* __restrict__ Ah, const __nv_bfloat16* __restrict__ Al,
    const __nv_bfloat16* __restrict__ Wh, const __nv_bfloat16* __restrict__ Wl,
    const float* __restrict__ bias, const float* __restrict__ R,
    float* __restrict__ Cf, __nv_bfloat16* __restrict__ Ch,
    __nv_bfloat16* __restrict__ Cl)
{
    extern __shared__ __align__(16) __nv_bfloat16 smb[];
    const int tid = threadIdx.x;
    const int lane = tid & 31, wid = tid >> 5;
    const int bm = blockIdx.x << 7;
    const int bn = blockIdx.y << 6;
    const int wm = (wid >> 1) << 5;
    const int wn = (wid & 1) << 5;

    float acc[2][4][4];
    #pragma unroll
    for (int mt = 0; mt < 2; mt++)
        #pragma unroll
        for (int nt = 0; nt < 4; nt++)
            #pragma unroll
            for (int j = 0; j < 4; j++) acc[mt][nt][j] = 0.f;

    const unsigned sbase = smem_u32(smb);
    const int a_r = ((lane >> 3) & 1) * 8 + (lane & 7);
    const int a_c = (lane >> 4) * 8;
    const int b_r = (lane >> 4) * 8 + (lane & 7);
    const int b_c = ((lane >> 3) & 1) * 8;

    GEMM_ISSUE(0, 0u);

    for (int c = 0; c < 4; c++) {
        if (c + 1 < 4) {
            GEMM_ISSUE(c + 1, (unsigned)(((c + 1) & 1) * BUF_ELE));
            CP_WAIT1();
        } else {
            CP_WAIT0();
        }
        __syncthreads();
        const unsigned bb = (unsigned)((c & 1) * BUF_ELE) * 2u;   // bytes

        #pragma unroll
        for (int ks = 0; ks < 4; ks++) {
            const int k = ks * 16;
            unsigned ah[2][4], al[2][4], bh[4][2], bl[4][2];
            #pragma unroll
            for (int mt = 0; mt < 2; mt++) {
                const unsigned off =
                    ((unsigned)((wm + mt * 16 + a_r) * ASTRIDE + k + a_c)) * 2u;
                ldsm_x4(ah[mt][0], ah[mt][1], ah[mt][2], ah[mt][3],
                        sbase + bb + off);
                ldsm_x4(al[mt][0], al[mt][1], al[mt][2], al[mt][3],
                        sbase + bb + A_TSZ * 2 + off);
            }
            #pragma unroll
            for (int nt2 = 0; nt2 < 2; nt2++) {
                const unsigned off = ((unsigned)(2 * A_TSZ +
                    (wn + nt2 * 16 + b_r) * ASTRIDE + k + b_c)) * 2u;
                unsigned r0, r1, r2, r3;
                ldsm_x4(r0, r1, r2, r3, sbase + bb + off);
                bh[nt2 * 2][0] = r0; bh[nt2 * 2][1] = r1;
                bh[nt2 * 2 + 1][0] = r2; bh[nt2 * 2 + 1][1] = r3;
                ldsm_x4(r0, r1, r2, r3, sbase + bb + B_TSZ * 2 + off);
                bl[nt2 * 2][0] = r0; bl[nt2 * 2][1] = r1;
                bl[nt2 * 2 + 1][0] = r2; bl[nt2 * 2 + 1][1] = r3;
            }
            #pragma unroll
            for (int mt = 0; mt < 2; mt++)
                #pragma unroll
                for (int nt = 0; nt < 4; nt++) {
                    mma16816(acc[mt][nt], ah[mt], bh[nt]);
                    mma16816(acc[mt][nt], al[mt], bh[nt]);
                    mma16816(acc[mt][nt], ah[mt], bl[nt]);
                }
        }
        __syncthreads();
    }

    const int qrow = lane >> 2;
    const int qcol = (lane & 3) * 2;
    #pragma unroll
    for (int mt = 0; mt < 2; mt++) {
        #pragma unroll
        for (int half = 0; half < 2; half++) {
            const int row = bm + wm + mt * 16 + qrow + half * 8;
            float keep = 1.f;
            if (EPI == 2) keep = g_keep[row];
            #pragma unroll
            for (int nt = 0; nt < 4; nt++) {
                const int col = bn + wn + nt * 8 + qcol;
                float v0 = acc[mt][nt][half * 2]     + __ldg(bias + col);
                float v1 = acc[mt][nt][half * 2 + 1] + __ldg(bias + col + 1);
                const size_t o = (size_t)row * HDIM + col;
                if (EPI == 0) {
                    *(float2*)(Cf + o) = make_float2(v0, v1);
                } else if (EPI == 1 || EPI == 3) {
                    if (EPI == 1) { v0 = fmaxf(v0, 0.f); v1 = fmaxf(v1, 0.f); }
                    __nv_bfloat16 h0, l0, h1, l1;
                    split_bf(v0, h0, l0); split_bf(v1, h1, l1);
                    *(unsigned*)(Ch + o) = pack_bf2(h0, h1);
                    *(unsigned*)(Cl + o) = pack_bf2(l0, l1);
                } else {
                    const float2 rr = *(const float2*)(R + o);
                    *(float2*)(Cf + o) = make_float2((v0 + rr.x) * keep,
                                                     (v1 + rr.y) * keep);
                }
            }
        }
    }
}

// ---------------- flash attention (MMA, causal, gated, cp.async 2-buf) --------
#define AT_AST 72
#define SQH_B 0
#define SQL_B (128 * AT_AST * 2)                 // 18432
#define SKV0_B (2 * 128 * AT_AST * 2)            // 36864 (buffer 0)
#define KV_BUF_B (4 * 64 * AT_AST * 2)           // 36864 bytes per buffer
#define K_TB (64 * AT_AST * 2)                   // 9216 bytes per sub-tile
#define STG_B (SKV0_B + 2 * KV_BUF_B)            // 110592
#define ATTN_SMEM (STG_B + 2 * 64 * 4)           // +512

#define KV_ISSUE(kt, bufb)                                                       \
    {                                                                            \
        const int k0_ = (kt) * 64;                                               \
        _Pragma("unroll")                                                        \
        for (int i_ = 0; i_ < 2; i_++) {                                         \
            const int v_ = tid + 256 * i_;                                       \
            const int rr_ = v_ >> 3, cc_ = v_ & 7;                               \
            const size_t go_ = (base + k0_ + rr_) * HDIM + hh * HEADD + cc_ * 8; \
            const unsigned so_ = sbase + (bufb) + (rr_ * AT_AST + cc_ * 8) * 2u; \
            cp16(so_,            g_kh + go_);                                    \
            cp16(so_ + K_TB,     g_kl + go_);                                    \
            cp16(so_ + 2 * K_TB, g_vh + go_);                                    \
            cp16(so_ + 3 * K_TB, g_vl + go_);                                    \
        }                                                                        \
        if (tid < 64)                                                            \
            cp4(sbase + STG_B + (((kt) & 1) * 64 + tid) * 4u,                    \
                g_gates + (base + k0_ + tid) * 2 + blk);                         \
        CP_COMMIT();                                                             \
    }

__global__ __launch_bounds__(256) void attn_kernel(int blk)
{
    extern __shared__ __align__(16) __nv_bfloat16 smb[];
    float* stgk = (float*)((char*)smb + STG_B);

    const int tid = threadIdx.x;
    const int lane = tid & 31, wid = tid >> 5;
    const int qt = blockIdx.x, hh = blockIdx.y, b = blockIdx.z;
    const int q0 = qt * 128;
    const size_t base = (size_t)b * LSEQ;
    const int wm = wid * 16;
    const unsigned sbase = smem_u32(smb);
    const int nkt = 2 * (qt + 1);

    KV_ISSUE(0, (unsigned)SKV0_B);

    #pragma unroll
    for (int i = 0; i < 4; i++) {
        const int v = tid + 256 * i;
        const int r = v >> 3, cc = v & 7;
        const size_t go = (base + q0 + r) * HDIM + hh * HEADD + cc * 8;
        *(uint4*)((char*)smb + SQH_B + (r * AT_AST + cc * 8) * 2) = *(const uint4*)(g_qh + go);
        *(uint4*)((char*)smb + SQL_B + (r * AT_AST + cc * 8) * 2) = *(const uint4*)(g_ql + go);
    }
    __syncthreads();

    const int a_r = ((lane >> 3) & 1) * 8 + (lane & 7);
    const int a_c = (lane >> 4) * 8;
    const int b_r = (lane >> 4) * 8 + (lane & 7);
    const int b_c = ((lane >> 3) & 1) * 8;
    const int v_r = lane & 15;
    const int v_c = (lane >> 4) * 8;

    unsigned aqh[4][4], aql[4][4];
    #pragma unroll
    for (int ks = 0; ks < 4; ks++) {
        const unsigned off = ((unsigned)((wm + a_r) * AT_AST + ks * 16 + a_c)) * 2u;
        ldsm_x4(aqh[ks][0], aqh[ks][1], aqh[ks][2], aqh[ks][3], sbase + SQH_B + off);
        ldsm_x4(aql[ks][0], aql[ks][1], aql[ks][2], aql[ks][3], sbase + SQL_B + off);
    }

    const int r = lane >> 2;
    const int c2 = (lane & 3) * 2;
    const float cq0 = 0.125f * g_gates[(base + q0 + wm + r) * 2 + blk];
    const float cq1 = 0.125f * g_gates[(base + q0 + wm + r + 8) * 2 + blk];
    float mrow0 = -1e30f, mrow1 = -1e30f, lrow0 = 0.f, lrow1 = 0.f;
    float O[8][4];
    #pragma unroll
    for (int nt = 0; nt < 8; nt++)
        #pragma unroll
        for (int j = 0; j < 4; j++) O[nt][j] = 0.f;

    for (int kt = 0; kt < nkt; kt++) {
        const int k0 = kt * 64;
        if (kt + 1 < nkt) {
            KV_ISSUE(kt + 1, (unsigned)(SKV0_B + ((kt + 1) & 1) * KV_BUF_B));
            CP_WAIT1();
        } else {
            CP_WAIT0();
        }
        __syncthreads();
        const unsigned kvb = (unsigned)(SKV0_B + (kt & 1) * KV_BUF_B);
        const float* stg = stgk + (kt & 1) * 64;

        float S[8][4];
        #pragma unroll
        for (int nt = 0; nt < 8; nt++)
            #pragma unroll
            for (int j = 0; j < 4; j++) S[nt][j] = 0.f;
        #pragma unroll
        for (int ks = 0; ks < 4; ks++) {
            #pragma unroll
            for (int n16 = 0; n16 < 4; n16++) {
                const unsigned off =
                    ((unsigned)((n16 * 16 + b_r) * AT_AST + ks * 16 + b_c)) * 2u;
                unsigned h0, h1, h2, h3, l0, l1, l2, l3;
                ldsm_x4(h0, h1, h2, h3, sbase + kvb + off);
                ldsm_x4(l0, l1, l2, l3, sbase + kvb + K_TB + off);
                unsigned bh0[2] = {h0, h1}, bh1[2] = {h2, h3};
                unsigned bl0[2] = {l0, l1}, bl1[2] = {l2, l3};
                mma16816(S[2 * n16], aqh[ks], bh0);
                mma16816(S[2 * n16], aql[ks], bh0);
                mma16816(S[2 * n16], aqh[ks], bl0);
                mma16816(S[2 * n16 + 1], aqh[ks], bh1);
                mma16816(S[2 * n16 + 1], aql[ks], bh1);
                mma16816(S[2 * n16 + 1], aqh[ks], bl1);
            }
        }

        const bool need_mask = (k0 + 63 > q0 + wm);
        float mt0 = -1e30f, mt1 = -1e30f;
        #pragma unroll
        for (int nt = 0; nt < 8; nt++) {
            const int col = nt * 8 + c2;
            const float tga = stg[col], tgb = stg[col + 1];
            float v0 = S[nt][0] * cq0 * tga;
            float v1 = S[nt][1] * cq0 * tgb;
            float v2 = S[nt][2] * cq1 * tga;
            float v3 = S[nt][3] * cq1 * tgb;
            if (need_mask) {
                const int kg = k0 + col;
                const int qa = q0 + wm + r, qb2 = qa + 8;
                if (kg     > qa)  v0 = -1e30f;
                if (kg + 1 > qa)  v1 = -1e30f;
                if (kg     > qb2) v2 = -1e30f;
                if (kg + 1 > qb2) v3 = -1e30f;
            }
            S[nt][0] = v0; S[nt][1] = v1; S[nt][2] = v2; S[nt][3] = v3;
            mt0 = fmaxf(mt0, fmaxf(v0, v1));
            mt1 = fmaxf(mt1, fmaxf(v2, v3));
        }
        mt0 = fmaxf(mt0, __shfl_xor_sync(0xffffffffu, mt0, 1));
        mt0 = fmaxf(mt0, __shfl_xor_sync(0xffffffffu, mt0, 2));
        mt1 = fmaxf(mt1, __shfl_xor_sync(0xffffffffu, mt1, 1));
        mt1 = fmaxf(mt1, __shfl_xor_sync(0xffffffffu, mt1, 2));
        const float mn0 = fmaxf(mrow0, mt0), mn1 = fmaxf(mrow1, mt1);
        const float al0 = __expf(mrow0 - mn0), al1 = __expf(mrow1 - mn1);
        mrow0 = mn0; mrow1 = mn1;

        float rs0 = 0.f, rs1 = 0.f;
        unsigned pah[4][4], pal[4][4];
        #pragma unroll
        for (int j2 = 0; j2 < 4; j2++) {
            float p0 = __expf(S[2 * j2][0] - mn0);
            float p1 = __expf(S[2 * j2][1] - mn0);
            float p2 = __expf(S[2 * j2][2] - mn1);
            float p3 = __expf(S[2 * j2][3] - mn1);
            float p4 = __expf(S[2 * j2 + 1][0] - mn0);
            float p5 = __expf(S[2 * j2 + 1][1] - mn0);
            float p6 = __expf(S[2 * j2 + 1][2] - mn1);
            float p7 = __expf(S[2 * j2 + 1][3] - mn1);
            rs0 += (p0 + p1) + (p4 + p5);
            rs1 += (p2 + p3) + (p6 + p7);
            __nv_bfloat16 h0,l0,h1,l1,h2,l2,h3,l3,h4,l4,h5,l5,h6,l6,h7,l7;
            split_bf(p0,h0,l0); split_bf(p1,h1,l1); split_bf(p2,h2,l2); split_bf(p3,h3,l3);
            split_bf(p4,h4,l4); split_bf(p5,h5,l5); split_bf(p6,h6,l6); split_bf(p7,h7,l7);
            pah[j2][0] = pack_bf2(h0, h1); pal[j2][0] = pack_bf2(l0, l1);
            pah[j2][1] = pack_bf2(h2, h3); pal[j2][1] = pack_bf2(l2, l3);
            pah[j2][2] = pack_bf2(h4, h5); pal[j2][2] = pack_bf2(l4, l5);
            pah[j2][3] = pack_bf2(h6, h7); pal[j2][3] = pack_bf2(l6, l7);
        }
        rs0 += __shfl_xor_sync(0xffffffffu, rs0, 1);
        rs0 += __shfl_xor_sync(0xffffffffu, rs0, 2);
        rs1 += __shfl_xor_sync(0xffffffffu, rs1, 1);
        rs1 += __shfl_xor_sync(0xffffffffu, rs1, 2);
        lrow0 = lrow0 * al0 + rs0;
        lrow1 = lrow1 * al1 + rs1;

        #pragma unroll
        for (int nt = 0; nt < 8; nt++) {
            O[nt][0] *= al0; O[nt][1] *= al0;
            O[nt][2] *= al1; O[nt][3] *= al1;
        }

        #pragma unroll
        for (int ks = 0; ks < 4; ks++) {
            #pragma unroll
            for (int n16 = 0; n16 < 4; n16++) {
                const unsigned off =
                    ((unsigned)((ks * 16 + v_r) * AT_AST + n16 * 16 + v_c)) * 2u;
                unsigned h0, h1, h2, h3, l0, l1, l2, l3;
                ldsm_x4_t(h0, h1, h2, h3, sbase + kvb + 2 * K_TB + off);
                ldsm_x4_t(l0, l1, l2, l3, sbase + kvb + 3 * K_TB + off);
                unsigned bh0[2] = {h0, h1}, bh1[2] = {h2, h3};
                unsigned bl0[2] = {l0, l1}, bl1[2] = {l2, l3};
                mma16816(O[2 * n16], pah[ks], bh0);
                mma16816(O[2 * n16], pal[ks], bh0);
                mma16816(O[2 * n16], pah[ks], bl0);
                mma16816(O[2 * n16 + 1], pah[ks], bh1);
                mma16816(O[2 * n16 + 1], pal[ks], bh1);
                mma16816(O[2 * n16 + 1], pah[ks], bl1);
            }
        }
        __syncthreads();
    }

    const float inv0 = 1.f / lrow0, inv1 = 1.f / lrow1;
    const size_t row0 = (base + q0 + wm + r) * HDIM + hh * HEADD;
    const size_t row1 = (base + q0 + wm + r + 8) * HDIM + hh * HEADD;
    #pragma unroll
    for (int nt = 0; nt < 8; nt++) {
        const int col = nt * 8 + c2;
        *(float2*)(g_ao + row0 + col) = make_float2(O[nt][0] * inv0, O[nt][1] * inv0);
        *(float2*)(g_ao + row1 + col) = make_float2(O[nt][2] * inv1, O[nt][3] * inv1);
    }
}

// ---------------- launcher ---------------------------------------------------
extern "C" void kernel_launch(void* const* d_in, const int* in_sizes, int n_in,
                              void* d_out, int out_size)
{
    const int*   seqs_data = (const int*)  d_in[0];
    const float* seqs_in   = (const float*)d_in[1];
    const int*   position  = (const int*)  d_in[2];
    const float* time_in   = (const float*)d_in[3];
    const float* pos_table = (const float*)d_in[4];
    const float* gate_W    = (const float*)d_in[5];
    const float* gate_b    = (const float*)d_in[6];
    const float* ln_attn_g = (const float*)d_in[7];
    const float* ln_attn_b = (const float*)d_in[8];
    const float* qW        = (const float*)d_in[9];
    const float* qb        = (const float*)d_in[10];
    const float* kW        = (const float*)d_in[11];
    const float* kb        = (const float*)d_in[12];
    const float* vW        = (const float*)d_in[13];
    const float* vb        = (const float*)d_in[14];
    const float* ln_ffn_g  = (const float*)d_in[15];
    const float* ln_ffn_b  = (const float*)d_in[16];
    const float* c1W       = (const float*)d_in[17];
    const float* c1b       = (const float*)d_in[18];
    const float* c2W       = (const float*)d_in[19];
    const float* c2b       = (const float*)d_in[20];
    const float* last_g    = (const float*)d_in[21];
    const float* last_b    = (const float*)d_in[22];

    float *p_seqs, *p_time, *p_Q, *p_ao, *p_x;
    __nv_bfloat16 *p_th, *p_tl, *p_ah, *p_al, *p_bh, *p_bl, *p_wh, *p_wl;
    __nv_bfloat16 *p_qh, *p_ql, *p_kh, *p_kl, *p_vh, *p_vl;
    cudaGetSymbolAddress((void**)&p_seqs, g_seqs);
    cudaGetSymbolAddress((void**)&p_time, g_time);
    cudaGetSymbolAddress((void**)&p_Q,    g_Q);
    cudaGetSymbolAddress((void**)&p_ao,   g_ao);
    cudaGetSymbolAddress((void**)&p_x,    g_x);
    cudaGetSymbolAddress((void**)&p_th,   g_t_hi);
    cudaGetSymbolAddress((void**)&p_tl,   g_t_lo);
    cudaGetSymbolAddress((void**)&p_ah,   g_a_hi);
    cudaGetSymbolAddress((void**)&p_al,   g_a_lo);
    cudaGetSymbolAddress((void**)&p_bh,   g_b_hi);
    cudaGetSymbolAddress((void**)&p_bl,   g_b_lo);
    cudaGetSymbolAddress((void**)&p_wh,   g_w_hi);
    cudaGetSymbolAddress((void**)&p_wl,   g_w_lo);
    cudaGetSymbolAddress((void**)&p_qh,   g_qh);
    cudaGetSymbolAddress((void**)&p_ql,   g_ql);
    cudaGetSymbolAddress((void**)&p_kh,   g_kh);
    cudaGetSymbolAddress((void**)&p_kl,   g_kl);
    cudaGetSymbolAddress((void**)&p_vh,   g_vh);
    cudaGetSymbolAddress((void**)&p_vl,   g_vl);

    cudaFuncSetAttribute(attn_kernel, cudaFuncAttributeMaxDynamicSharedMemorySize, ATTN_SMEM);
    cudaFuncSetAttribute(gemm_mma<0>, cudaFuncAttributeMaxDynamicSharedMemorySize, GEMM_SMEM);
    cudaFuncSetAttribute(gemm_mma<1>, cudaFuncAttributeMaxDynamicSharedMemorySize, GEMM_SMEM);
    cudaFuncSetAttribute(gemm_mma<2>, cudaFuncAttributeMaxDynamicSharedMemorySize, GEMM_SMEM);
    cudaFuncSetAttribute(gemm_mma<3>, cudaFuncAttributeMaxDynamicSharedMemorySize, GEMM_SMEM);

    prep_kernel<<<NROWS, 256>>>(seqs_data, seqs_in, position, time_in,
                                pos_table, gate_W, gate_b);
    wconv_kernel<<<640, 256>>>(qW, kW, vW, c1W, c2W);

    const size_t WSZ = (size_t)HDIM * HDIM;
    const dim3 ggrid(NROWS / 128, HDIM / 64);
    for (int i = 0; i < 2; i++) {
        lnadd_kernel<<<NROWS, 256>>>(ln_attn_g + i * HDIM, ln_attn_b + i * HDIM,
                                     p_Q, p_ah, p_al, p_bh, p_bl);
        gemm_mma<3><<<ggrid, 256, GEMM_SMEM>>>(p_ah, p_al,
            p_wh + (0 * 2 + i) * WSZ, p_wl + (0 * 2 + i) * WSZ,
            qb + i * HDIM, nullptr, nullptr, p_qh, p_ql);
        gemm_mma<3><<<ggrid, 256, GEMM_SMEM>>>(p_th, p_tl,
            p_wh + (1 * 2 + i) * WSZ, p_wl + (1 * 2 + i) * WSZ,
            kb + i * HDIM, nullptr, nullptr, p_kh, p_kl);
        gemm_mma<3><<<ggrid, 256, GEMM_SMEM>>>(p_bh, p_bl,
            p_wh + (2 * 2 + i) * WSZ, p_wl + (2 * 2 + i) * WSZ,
            vb + i * HDIM, nullptr, nullptr, p_vh, p_vl);
        attn_kernel<<<dim3(4, 4, NBATCH), 256, ATTN_SMEM>>>(i);
        ln_kernel<true, true><<<NROWS, 256>>>(p_Q, p_ao,
            ln_ffn_g + i * HDIM, ln_ffn_b + i * HDIM, p_x, p_ah, p_al);
        gemm_mma<1><<<ggrid, 256, GEMM_SMEM>>>(p_ah, p_al,
            p_wh + (3 * 2 + i) * WSZ, p_wl + (3 * 2 + i) * WSZ,
            c1b + i * HDIM, nullptr, nullptr, p_bh, p_bl);
        gemm_mma<2><<<ggrid, 256, GEMM_SMEM>>>(p_bh, p_bl,
            p_wh + (4 * 2 + i) * WSZ, p_wl + (4 * 2 + i) * WSZ,
            c2b + i * HDIM, p_x, p_seqs, nullptr, nullptr);
    }
    ln_kernel<false, false><<<NROWS, 256>>>(p_seqs, nullptr, last_g, last_b,
                                            (float*)d_out, nullptr, nullptr);
}

// round 9
// speedup vs baseline: 1.2022x; 1.0463x over previous
#include <cuda_runtime.h>
#include <cuda_bf16.h>
#include <math.h>

#define NROWS 32768          // B*L
#define HDIM  256
#define LSEQ  512
#define NBATCH 64
#define HEADD 64
#define ITEMPAD 49999

typedef unsigned long long u64;

// ---------------- scratch (device globals; no allocs allowed) ----------------
__device__ __align__(16) float g_seqs[NROWS * HDIM];
__device__ __align__(16) float g_time[NROWS * HDIM];
__device__ __align__(16) float g_Q   [NROWS * HDIM];
__device__ __align__(16) float g_ao  [NROWS * HDIM];
__device__ __align__(16) float g_x   [NROWS * HDIM];
__device__ float g_keep[NROWS];
__device__ float g_gates[NROWS * 2];

__device__ __align__(16) __nv_bfloat16 g_t_hi[NROWS * HDIM];
__device__ __align__(16) __nv_bfloat16 g_t_lo[NROWS * HDIM];
__device__ __align__(16) __nv_bfloat16 g_a_hi[NROWS * HDIM];
__device__ __align__(16) __nv_bfloat16 g_a_lo[NROWS * HDIM];
__device__ __align__(16) __nv_bfloat16 g_b_hi[NROWS * HDIM];
__device__ __align__(16) __nv_bfloat16 g_b_lo[NROWS * HDIM];
__device__ __align__(16) __nv_bfloat16 g_qh[NROWS * HDIM];
__device__ __align__(16) __nv_bfloat16 g_ql[NROWS * HDIM];
__device__ __align__(16) __nv_bfloat16 g_kh[NROWS * HDIM];
__device__ __align__(16) __nv_bfloat16 g_kl[NROWS * HDIM];
__device__ __align__(16) __nv_bfloat16 g_vh[NROWS * HDIM];
__device__ __align__(16) __nv_bfloat16 g_vl[NROWS * HDIM];
__device__ __align__(16) __nv_bfloat16 g_w_hi[5 * 2 * HDIM * HDIM];
__device__ __align__(16) __nv_bfloat16 g_w_lo[5 * 2 * HDIM * HDIM];

// ---------------- small helpers ----------------------------------------------
__device__ __forceinline__ void split_bf(float x, __nv_bfloat16& h, __nv_bfloat16& l) {
    h = __float2bfloat16_rn(x);
    l = __float2bfloat16_rn(x - __bfloat162float(h));
}
__device__ __forceinline__ unsigned pack_bf2(__nv_bfloat16 a, __nv_bfloat16 b) {
    return (unsigned)__bfloat16_as_ushort(a) | ((unsigned)__bfloat16_as_ushort(b) << 16);
}
__device__ __forceinline__ unsigned smem_u32(const void* p) {
    unsigned a;
    asm("{ .reg .u64 t; cvta.to.shared.u64 t, %1; cvt.u32.u64 %0, t; }" : "=r"(a) : "l"(p));
    return a;
}

// ---------------- warp-MMA + cp.async helpers (portable: sm_80+) --------------
__device__ __forceinline__ void ldsm_x4(unsigned& r0, unsigned& r1, unsigned& r2,
                                        unsigned& r3, unsigned addr) {
    asm volatile("ldmatrix.sync.aligned.m8n8.x4.shared.b16 {%0,%1,%2,%3}, [%4];"
        : "=r"(r0), "=r"(r1), "=r"(r2), "=r"(r3) : "r"(addr));
}
__device__ __forceinline__ void ldsm_x4_t(unsigned& r0, unsigned& r1, unsigned& r2,
                                          unsigned& r3, unsigned addr) {
    asm volatile("ldmatrix.sync.aligned.m8n8.x4.trans.shared.b16 {%0,%1,%2,%3}, [%4];"
        : "=r"(r0), "=r"(r1), "=r"(r2), "=r"(r3) : "r"(addr));
}
__device__ __forceinline__ void mma16816(float* d, const unsigned* a, const unsigned* b) {
    asm volatile("mma.sync.aligned.m16n8k16.row.col.f32.bf16.bf16.f32 "
        "{%0,%1,%2,%3}, {%4,%5,%6,%7}, {%8,%9}, {%0,%1,%2,%3};"
        : "+f"(d[0]), "+f"(d[1]), "+f"(d[2]), "+f"(d[3])
        : "r"(a[0]), "r"(a[1]), "r"(a[2]), "r"(a[3]), "r"(b[0]), "r"(b[1]));
}
__device__ __forceinline__ void cp16(unsigned dst, const void* src) {
    asm volatile("cp.async.cg.shared.global [%0], [%1], 16;" :: "r"(dst), "l"(src));
}
__device__ __forceinline__ void cp4(unsigned dst, const void* src) {
    asm volatile("cp.async.ca.shared.global [%0], [%1], 4;" :: "r"(dst), "l"(src));
}
#define CP_COMMIT() asm volatile("cp.async.commit_group;" ::: "memory")
#define CP_WAIT1()  asm volatile("cp.async.wait_group 1;" ::: "memory")
#define CP_WAIT0()  asm volatile("cp.async.wait_group 0;" ::: "memory")

// ---------------- prep -------------------------------------------------------
__global__ __launch_bounds__(256) void prep_kernel(
    const int* __restrict__ seqs_data, const float* __restrict__ seqs_in,
    const int* __restrict__ position, const float* __restrict__ time_in,
    const float* __restrict__ pos_table, const float* __restrict__ gate_W,
    const float* __restrict__ gate_b)
{
    const int n = blockIdx.x;
    const int h = threadIdx.x;
    const size_t idx = (size_t)n * HDIM + h;
    const int p = position[n];
    const float pe = pos_table[(size_t)p * HDIM + h];
    const float t = time_in[idx] + pe;
    const float keep = (seqs_data[n] != ITEMPAD) ? 1.f : 0.f;
    g_seqs[idx] = (seqs_in[idx] + pe) * keep;
    g_time[idx] = t;
    __nv_bfloat16 th, tl;
    split_bf(t, th, tl);
    g_t_hi[idx] = th; g_t_lo[idx] = tl;
    if (h == 0) g_keep[n] = keep;

    __shared__ float red[2][8];
    float p0 = t * gate_W[h];
    float p1 = t * gate_W[HDIM + h];
    #pragma unroll
    for (int o = 16; o; o >>= 1) {
        p0 += __shfl_xor_sync(0xffffffffu, p0, o);
        p1 += __shfl_xor_sync(0xffffffffu, p1, o);
    }
    if ((h & 31) == 0) { red[0][h >> 5] = p0; red[1][h >> 5] = p1; }
    __syncthreads();
    if (h < 2) {
        float s = 0.f;
        #pragma unroll
        for (int j = 0; j < 8; j++) s += red[h][j];
        g_gates[(size_t)n * 2 + h] = 1.f / (1.f + __expf(-(s + gate_b[h])));
    }
}

// ---------------- weight conversion ------------------------------------------
__global__ __launch_bounds__(256) void wconv_kernel(
    const float* __restrict__ q, const float* __restrict__ k,
    const float* __restrict__ v, const float* __restrict__ c1,
    const float* __restrict__ c2)
{
    const int i = blockIdx.x * blockDim.x + threadIdx.x;
    if (i >= 5 * 32768) return;
    const int mat = i >> 15, rem = i & 32767;
    const float* src = (mat == 0) ? q : (mat == 1) ? k : (mat == 2) ? v : (mat == 3) ? c1 : c2;
    float4 x = ((const float4*)src)[rem];
    __nv_bfloat16 h0,l0,h1,l1,h2,l2,h3,l3;
    split_bf(x.x,h0,l0); split_bf(x.y,h1,l1); split_bf(x.z,h2,l2); split_bf(x.w,h3,l3);
    const size_t o = ((size_t)mat << 17) + (size_t)rem * 4;
    *(uint2*)(g_w_hi + o) = make_uint2(pack_bf2(h0,h1), pack_bf2(h2,h3));
    *(uint2*)(g_w_lo + o) = make_uint2(pack_bf2(l0,l1), pack_bf2(l2,l3));
}

// ---------------- fused LN(seqs) + (seqs+time) split --------------------------
__global__ __launch_bounds__(256) void lnadd_kernel(
    const float* __restrict__ g, const float* __restrict__ beta,
    float* __restrict__ Q, __nv_bfloat16* __restrict__ Dh,
    __nv_bfloat16* __restrict__ Dl, __nv_bfloat16* __restrict__ Sh,
    __nv_bfloat16* __restrict__ Sl)
{
    const int n = blockIdx.x;
    const int h = threadIdx.x;
    const size_t idx = (size_t)n * HDIM + h;
    const float x = g_seqs[idx];
    float s = x, q = x * x;
    __shared__ float rs[8], rq[8];
    #pragma unroll
    for (int o = 16; o; o >>= 1) {
        s += __shfl_xor_sync(0xffffffffu, s, o);
        q += __shfl_xor_sync(0xffffffffu, q, o);
    }
    if ((h & 31) == 0) { rs[h >> 5] = s; rq[h >> 5] = q; }
    __syncthreads();
    float tot = 0.f, totq = 0.f;
    #pragma unroll
    for (int j = 0; j < 8; j++) { tot += rs[j]; totq += rq[j]; }
    const float mean = tot * (1.f / HDIM);
    const float var  = totq * (1.f / HDIM) - mean * mean;
    const float y = (x - mean) * rsqrtf(var + 1e-8f) * g[h] + beta[h];
    Q[idx] = y;
    __nv_bfloat16 hh, ll;
    split_bf(y, hh, ll);
    Dh[idx] = hh; Dl[idx] = ll;
    const float st = x + g_time[idx];
    split_bf(st, hh, ll);
    Sh[idx] = hh; Sl[idx] = ll;
}

// ---------------- layernorm (+residual, +bf16 split outputs) ------------------
template<bool ADD, bool BF>
__global__ __launch_bounds__(256) void ln_kernel(
    const float* __restrict__ A, const float* __restrict__ B2,
    const float* __restrict__ g, const float* __restrict__ beta,
    float* __restrict__ dst, __nv_bfloat16* __restrict__ Dh,
    __nv_bfloat16* __restrict__ Dl)
{
    const int n = blockIdx.x;
    const int h = threadIdx.x;
    const size_t idx = (size_t)n * HDIM + h;
    float x = A[idx];
    if (ADD) x += B2[idx];
    float s = x, q = x * x;
    __shared__ float rs[8], rq[8];
    #pragma unroll
    for (int o = 16; o; o >>= 1) {
        s += __shfl_xor_sync(0xffffffffu, s, o);
        q += __shfl_xor_sync(0xffffffffu, q, o);
    }
    if ((h & 31) == 0) { rs[h >> 5] = s; rq[h >> 5] = q; }
    __syncthreads();
    float tot = 0.f, totq = 0.f;
    #pragma unroll
    for (int j = 0; j < 8; j++) { tot += rs[j]; totq += rq[j]; }
    const float mean = tot * (1.f / HDIM);
    const float var  = totq * (1.f / HDIM) - mean * mean;
    const float y = (x - mean) * rsqrtf(var + 1e-8f) * g[h] + beta[h];
    dst[idx] = y;
    if (BF) {
        __nv_bfloat16 hh, ll;
        split_bf(y, hh, ll);
        Dh[idx] = hh; Dl[idx] = ll;
    }
}

// ---------------- GEMM v5: 128x64 tile, 2 CTA/SM, cp.async + frag pipeline ----
#define ASTRIDE 72
#define A_TSZ (128 * ASTRIDE)
#define B_TSZ (64 * ASTRIDE)
#define BUF_ELE (2 * A_TSZ + 2 * B_TSZ)   // 55296 bytes
#define GEMM_SMEM (2 * BUF_ELE * 2)       // 110592 bytes

#define GEMM_ISSUE(c, bufe)                                                      \
    {                                                                            \
        _Pragma("unroll")                                                        \
        for (int i_ = 0; i_ < 4; i_++) {                                         \
            const int v_ = tid + 256 * i_;                                       \
            const int r_ = v_ >> 3, cc_ = v_ & 7;                                \
            const size_t gA_ = (size_t)(bm + r_) * HDIM + (c) * 64 + cc_ * 8;    \
            const unsigned so_ = sbase + ((bufe) + r_ * ASTRIDE + cc_ * 8) * 2u; \
            cp16(so_,             Ah + gA_);                                     \
            cp16(so_ + A_TSZ * 2, Al + gA_);                                     \
        }                                                                        \
        _Pragma("unroll")                                                        \
        for (int i_ = 0; i_ < 2; i_++) {                                         \
            const int v_ = tid + 256 * i_;                                       \
            const int r_ = v_ >> 3, cc_ = v_ & 7;                                \
            const size_t gB_ = (size_t)(bn + r_) * HDIM + (c) * 64 + cc_ * 8;    \
            const unsigned so_ = sbase +                                         \
                ((bufe) + 2 * A_TSZ + r_ * ASTRIDE + cc_ * 8) * 2u;              \
            cp16(so_,             Wh + gB_);                                     \
            cp16(so_ + B_TSZ * 2, Wl + gB_);                                     \
        }                                                                        \
        CP_COMMIT();                                                             \
    }

// Load all fragments for K-step ks into fragment-buffer parity p.
#define LOADF(p, ks)                                                             \
    {                                                                            \
        const int k_ = (ks) * 16;                                                \
        _Pragma("unroll")                                                        \
        for (int mt_ = 0; mt_ < 2; mt_++) {                                      \
            const unsigned off_ =                                                \
                ((unsigned)((wm + mt_ * 16 + a_r) * ASTRIDE + k_ + a_c)) * 2u;   \
            ldsm_x4(ah[p][mt_][0], ah[p][mt_][1], ah[p][mt_][2], ah[p][mt_][3],  \
                    sbase + bb + off_);                                          \
            ldsm_x4(al[p][mt_][0], al[p][mt_][1], al[p][mt_][2], al[p][mt_][3],  \
                    sbase + bb + A_TSZ * 2 + off_);                              \
        }                                                                        \
        _Pragma("unroll")                                                        \
        for (int nt2_ = 0; nt2_ < 2; nt2_++) {                                   \
            const unsigned off_ = ((unsigned)(2 * A_TSZ +                        \
                (wn + nt2_ * 16 + b_r) * ASTRIDE + k_ + b_c)) * 2u;              \
            unsigned r0_, r1_, r2_, r3_;                                         \
            ldsm_x4(r0_, r1_, r2_, r3_, sbase + bb + off_);                      \
            bh[p][nt2_ * 2][0] = r0_; bh[p][nt2_ * 2][1] = r1_;                  \
            bh[p][nt2_ * 2 + 1][0] = r2_; bh[p][nt2_ * 2 + 1][1] = r3_;          \
            ldsm_x4(r0_, r1_, r2_, r3_, sbase + bb + B_TSZ * 2 + off_);          \
            bl[p][nt2_ * 2][0] = r0_; bl[p][nt2_ * 2][1] = r1_;                  \
            bl[p][nt2_ * 2 + 1][0] = r2_; bl[p][nt2_ * 2 + 1][1] = r3_;          \
        }                                                                        \
    }

template<int EPI>
__global__ __launch_bounds__(256, 2) void gemm_mma(
    const __nv_bfloat16* __restrict__ Ah, const __nv_bfloat16* __restrict__ Al,
    const __nv_bfloat16* __restrict__ Wh, const __nv_bfloat16* __restrict__ Wl,
    const float* __restrict__ bias, const float* __restrict__ R,
    float* __restrict__ Cf, __nv_bfloat16* __restrict__ Ch,
    __nv_bfloat16* __restrict__ Cl)
{
    extern __shared__ __align__(16) __nv_bfloat16 smb[];
    const int tid = threadIdx.x;
    const int lane = tid & 31, wid = tid >> 5;
    const int bm = blockIdx.x << 7;
    const int bn = blockIdx.y << 6;
    const int wm = (wid >> 1) << 5;
    const int wn = (wid & 1) << 5;

    float acc[2][4][4];
    #pragma unroll
    for (int mt = 0; mt < 2; mt++)
        #pragma unroll
        for (int nt = 0; nt < 4; nt++)
            #pragma unroll
            for (int j = 0; j < 4; j++) acc[mt][nt][j] = 0.f;

    const unsigned sbase = smem_u32(smb);
    const int a_r = ((lane >> 3) & 1) * 8 + (lane & 7);
    const int a_c = (lane >> 4) * 8;
    const int b_r = (lane >> 4) * 8 + (lane & 7);
    const int b_c = ((lane >> 3) & 1) * 8;

    unsigned ah[2][2][4], al[2][2][4], bh[2][4][2], bl[2][4][2];

    GEMM_ISSUE(0, 0u);

    for (int c = 0; c < 4; c++) {
        if (c + 1 < 4) {
            GEMM_ISSUE(c + 1, (unsigned)(((c + 1) & 1) * BUF_ELE));
            CP_WAIT1();
        } else {
            CP_WAIT0();
        }
        __syncthreads();
        const unsigned bb = (unsigned)((c & 1) * BUF_ELE) * 2u;

        LOADF(0, 0);
        #pragma unroll
        for (int ks = 0; ks < 4; ks++) {
            if (ks < 3) LOADF((ks + 1) & 1, ks + 1);
            const int p = ks & 1;
            #pragma unroll
            for (int mt = 0; mt < 2; mt++)
                #pragma unroll
                for (int nt = 0; nt < 4; nt++) {
                    mma16816(acc[mt][nt], ah[p][mt], bh[p][nt]);
                    mma16816(acc[mt][nt], al[p][mt], bh[p][nt]);
                    mma16816(acc[mt][nt], ah[p][mt], bl[p][nt]);
                }
        }
        __syncthreads();
    }

    const int qrow = lane >> 2;
    const int qcol = (lane & 3) * 2;
    #pragma unroll
    for (int mt = 0; mt < 2; mt++) {
        #pragma unroll
        for (int half = 0; half < 2; half++) {
            const int row = bm + wm + mt * 16 + qrow + half * 8;
            float keep = 1.f;
            if (EPI == 2) keep = g_keep[row];
            #pragma unroll
            for (int nt = 0; nt < 4; nt++) {
                const int col = bn + wn + nt * 8 + qcol;
                float v0 = acc[mt][nt][half * 2]     + __ldg(bias + col);
                float v1 = acc[mt][nt][half * 2 + 1] + __ldg(bias + col + 1);
                const size_t o = (size_t)row * HDIM + col;
                if (EPI == 0) {
                    *(float2*)(Cf + o) = make_float2(v0, v1);
                } else if (EPI == 1 || EPI == 3) {
                    if (EPI == 1) { v0 = fmaxf(v0, 0.f); v1 = fmaxf(v1, 0.f); }
                    __nv_bfloat16 h0, l0, h1, l1;
                    split_bf(v0, h0, l0); split_bf(v1, h1, l1);
                    *(unsigned*)(Ch + o) = pack_bf2(h0, h1);
                    *(unsigned*)(Cl + o) = pack_bf2(l0, l1);
                } else {
                    const float2 rr = *(const float2*)(R + o);
                    *(float2*)(Cf + o) = make_float2((v0 + rr.x) * keep,
                                                     (v1 + rr.y) * keep);
                }
            }
        }
    }
}

// ---------------- merged q/k/v GEMM (EPI=3), z selects the job ----------------
__global__ __launch_bounds__(256, 2) void gemm_qkv(
    const __nv_bfloat16* __restrict__ Ah0, const __nv_bfloat16* __restrict__ Al0,
    const __nv_bfloat16* __restrict__ Ah1, const __nv_bfloat16* __restrict__ Al1,
    const __nv_bfloat16* __restrict__ Ah2, const __nv_bfloat16* __restrict__ Al2,
    const __nv_bfloat16* __restrict__ Whb, const __nv_bfloat16* __restrict__ Wlb,
    const float* __restrict__ b0, const float* __restrict__ b1,
    const float* __restrict__ b2,
    __nv_bfloat16* __restrict__ C0h, __nv_bfloat16* __restrict__ C0l,
    __nv_bfloat16* __restrict__ C1h, __nv_bfloat16* __restrict__ C1l,
    __nv_bfloat16* __restrict__ C2h, __nv_bfloat16* __restrict__ C2l)
{
    extern __shared__ __align__(16) __nv_bfloat16 smb[];
    const int z = blockIdx.z;
    const __nv_bfloat16* Ah = (z == 0) ? Ah0 : (z == 1) ? Ah1 : Ah2;
    const __nv_bfloat16* Al = (z == 0) ? Al0 : (z == 1) ? Al1 : Al2;
    const __nv_bfloat16* Wh = Whb + (size_t)z * 2 * HDIM * HDIM;
    const __nv_bfloat16* Wl = Wlb + (size_t)z * 2 * HDIM * HDIM;
    const float* bias = (z == 0) ? b0 : (z == 1) ? b1 : b2;
    __nv_bfloat16* Ch = (z == 0) ? C0h : (z == 1) ? C1h : C2h;
    __nv_bfloat16* Cl = (z == 0) ? C0l : (z == 1) ? C1l : C2l;

    const int tid = threadIdx.x;
    const int lane = tid & 31, wid = tid >> 5;
    const int bm = blockIdx.x << 7;
    const int bn = blockIdx.y << 6;
    const int wm = (wid >> 1) << 5;
    const int wn = (wid & 1) << 5;

    float acc[2][4][4];
    #pragma unroll
    for (int mt = 0; mt < 2; mt++)
        #pragma unroll
        for (int nt = 0; nt < 4; nt++)
            #pragma unroll
            for (int j = 0; j < 4; j++) acc[mt][nt][j] = 0.f;

    const unsigned sbase = smem_u32(smb);
    const int a_r = ((lane >> 3) & 1) * 8 + (lane & 7);
    const int a_c = (lane >> 4) * 8;
    const int b_r = (lane >> 4) * 8 + (lane & 7);
    const int b_c = ((lane >> 3) & 1) * 8;

    unsigned ah[2][2][4], al[2][2][4], bh[2][4][2], bl[2][4][2];

    GEMM_ISSUE(0, 0u);

    for (int c = 0; c < 4; c++) {
        if (c + 1 < 4) {
            GEMM_ISSUE(c + 1, (unsigned)(((c + 1) & 1) * BUF_ELE));
            CP_WAIT1();
        } else {
            CP_WAIT0();
        }
        __syncthreads();
        const unsigned bb = (unsigned)((c & 1) * BUF_ELE) * 2u;

        LOADF(0, 0);
        #pragma unroll
        for (int ks = 0; ks < 4; ks++) {
            if (ks < 3) LOADF((ks + 1) & 1, ks + 1);
            const int p = ks & 1;
            #pragma unroll
            for (int mt = 0; mt < 2; mt++)
                #pragma unroll
                for (int nt = 0; nt < 4; nt++) {
                    mma16816(acc[mt][nt], ah[p][mt], bh[p][nt]);
                    mma16816(acc[mt][nt], al[p][mt], bh[p][nt]);
                    mma16816(acc[mt][nt], ah[p][mt], bl[p][nt]);
                }
        }
        __syncthreads();
    }

    const int qrow = lane >> 2;
    const int qcol = (lane & 3) * 2;
    #pragma unroll
    for (int mt = 0; mt < 2; mt++) {
        #pragma unroll
        for (int half = 0; half < 2; half++) {
            const int row = bm + wm + mt * 16 + qrow + half * 8;
            #pragma unroll
            for (int nt = 0; nt < 4; nt++) {
                const int col = bn + wn + nt * 8 + qcol;
                float v0 = acc[mt][nt][half * 2]     + __ldg(bias + col);
                float v1 = acc[mt][nt][half * 2 + 1] + __ldg(bias + col + 1);
                const size_t o = (size_t)row * HDIM + col;
                __nv_bfloat16 h0, l0, h1, l1;
                split_bf(v0, h0, l0); split_bf(v1, h1, l1);
                *(unsigned*)(Ch + o) = pack_bf2(h0, h1);
                *(unsigned*)(Cl + o) = pack_bf2(l0, l1);
            }
        }
    }
}

// ---------------- flash attention (MMA, causal, gated, cp.async 2-buf) --------
#define AT_AST 72
#define SQH_B 0
#define SQL_B (128 * AT_AST * 2)
#define SKV0_B (2 * 128 * AT_AST * 2)
#define KV_BUF_B (4 * 64 * AT_AST * 2)
#define K_TB (64 * AT_AST * 2)
#define STG_B (SKV0_B + 2 * KV_BUF_B)
#define ATTN_SMEM (STG_B + 2 * 64 * 4)

#define KV_ISSUE(kt, bufb)                                                       \
    {                                                                            \
        const int k0_ = (kt) * 64;                                               \
        _Pragma("unroll")                                                        \
        for (int i_ = 0; i_ < 2; i_++) {                                         \
            const int v_ = tid + 256 * i_;                                       \
            const int rr_ = v_ >> 3, cc_ = v_ & 7;                               \
            const size_t go_ = (base + k0_ + rr_) * HDIM + hh * HEADD + cc_ * 8; \
            const unsigned so_ = sbase + (bufb) + (rr_ * AT_AST + cc_ * 8) * 2u; \
            cp16(so_,            g_kh + go_);                                    \
            cp16(so_ + K_TB,     g_kl + go_);                                    \
            cp16(so_ + 2 * K_TB, g_vh + go_);                                    \
            cp16(so_ + 3 * K_TB, g_vl + go_);                                    \
        }                                                                        \
        if (tid < 64)                                                            \
            cp4(sbase + STG_B + (((kt) & 1) * 64 + tid) * 4u,                    \
                g_gates + (base + k0_ + tid) * 2 + blk);                         \
        CP_COMMIT();                                                             \
    }

__global__ __launch_bounds__(256) void attn_kernel(int blk)
{
    extern __shared__ __align__(16) __nv_bfloat16 smb[];
    float* stgk = (float*)((char*)smb + STG_B);

    const int tid = threadIdx.x;
    const int lane = tid & 31, wid = tid >> 5;
    const int qt = blockIdx.x, hh = blockIdx.y, b = blockIdx.z;
    const int q0 = qt * 128;
    const size_t base = (size_t)b * LSEQ;
    const int wm = wid * 16;
    const unsigned sbase = smem_u32(smb);
    const int nkt = 2 * (qt + 1);

    KV_ISSUE(0, (unsigned)SKV0_B);

    #pragma unroll
    for (int i = 0; i < 4; i++) {
        const int v = tid + 256 * i;
        const int r = v >> 3, cc = v & 7;
        const size_t go = (base + q0 + r) * HDIM + hh * HEADD + cc * 8;
        *(uint4*)((char*)smb + SQH_B + (r * AT_AST + cc * 8) * 2) = *(const uint4*)(g_qh + go);
        *(uint4*)((char*)smb + SQL_B + (r * AT_AST + cc * 8) * 2) = *(const uint4*)(g_ql + go);
    }
    __syncthreads();

    const int a_r = ((lane >> 3) & 1) * 8 + (lane & 7);
    const int a_c = (lane >> 4) * 8;
    const int b_r = (lane >> 4) * 8 + (lane & 7);
    const int b_c = ((lane >> 3) & 1) * 8;
    const int v_r = lane & 15;
    const int v_c = (lane >> 4) * 8;

    unsigned aqh[4][4], aql[4][4];
    #pragma unroll
    for (int ks = 0; ks < 4; ks++) {
        const unsigned off = ((unsigned)((wm + a_r) * AT_AST + ks * 16 + a_c)) * 2u;
        ldsm_x4(aqh[ks][0], aqh[ks][1], aqh[ks][2], aqh[ks][3], sbase + SQH_B + off);
        ldsm_x4(aql[ks][0], aql[ks][1], aql[ks][2], aql[ks][3], sbase + SQL_B + off);
    }

    const int r = lane >> 2;
    const int c2 = (lane & 3) * 2;
    const int qmax = q0 + wm + 15;           // max q row this warp owns
    const float cq0 = 0.125f * g_gates[(base + q0 + wm + r) * 2 + blk];
    const float cq1 = 0.125f * g_gates[(base + q0 + wm + r + 8) * 2 + blk];
    float mrow0 = -1e30f, mrow1 = -1e30f, lrow0 = 0.f, lrow1 = 0.f;
    float O[8][4];
    #pragma unroll
    for (int nt = 0; nt < 8; nt++)
        #pragma unroll
        for (int j = 0; j < 4; j++) O[nt][j] = 0.f;

    for (int kt = 0; kt < nkt; kt++) {
        const int k0 = kt * 64;
        if (kt + 1 < nkt) {
            KV_ISSUE(kt + 1, (unsigned)(SKV0_B + ((kt + 1) & 1) * KV_BUF_B));
            CP_WAIT1();
        } else {
            CP_WAIT0();
        }
        __syncthreads();
        const unsigned kvb = (unsigned)(SKV0_B + (kt & 1) * KV_BUF_B);
        const float* stg = stgk + (kt & 1) * 64;

        float S[8][4];
        #pragma unroll
        for (int nt = 0; nt < 8; nt++)
            #pragma unroll
            for (int j = 0; j < 4; j++) S[nt][j] = 0.f;
        #pragma unroll
        for (int n16 = 0; n16 < 4; n16++) {
            if (k0 + n16 * 16 <= qmax) {        // skip fully-masked 16-col blocks
                #pragma unroll
                for (int ks = 0; ks < 4; ks++) {
                    const unsigned off =
                        ((unsigned)((n16 * 16 + b_r) * AT_AST + ks * 16 + b_c)) * 2u;
                    unsigned h0, h1, h2, h3, l0, l1, l2, l3;
                    ldsm_x4(h0, h1, h2, h3, sbase + kvb + off);
                    ldsm_x4(l0, l1, l2, l3, sbase + kvb + K_TB + off);
                    unsigned bh0[2] = {h0, h1}, bh1[2] = {h2, h3};
                    unsigned bl0[2] = {l0, l1}, bl1[2] = {l2, l3};
                    mma16816(S[2 * n16], aqh[ks], bh0);
                    mma16816(S[2 * n16], aql[ks], bh0);
                    mma16816(S[2 * n16], aqh[ks], bl0);
                    mma16816(S[2 * n16 + 1], aqh[ks], bh1);
                    mma16816(S[2 * n16 + 1], aql[ks], bh1);
                    mma16816(S[2 * n16 + 1], aqh[ks], bl1);
                }
            }
        }

        const bool need_mask = (k0 + 63 > q0 + wm);
        float mt0 = -1e30f, mt1 = -1e30f;
        #pragma unroll
        for (int nt = 0; nt < 8; nt++) {
            const int col = nt * 8 + c2;
            const float tga = stg[col], tgb = stg[col + 1];
            float v0 = S[nt][0] * cq0 * tga;
            float v1 = S[nt][1] * cq0 * tgb;
            float v2 = S[nt][2] * cq1 * tga;
            float v3 = S[nt][3] * cq1 * tgb;
            if (need_mask) {
                const int kg = k0 + col;
                const int qa = q0 + wm + r, qb2 = qa + 8;
                if (kg     > qa)  v0 = -1e30f;
                if (kg + 1 > qa)  v1 = -1e30f;
                if (kg     > qb2) v2 = -1e30f;
                if (kg + 1 > qb2) v3 = -1e30f;
            }
            S[nt][0] = v0; S[nt][1] = v1; S[nt][2] = v2; S[nt][3] = v3;
            mt0 = fmaxf(mt0, fmaxf(v0, v1));
            mt1 = fmaxf(mt1, fmaxf(v2, v3));
        }
        mt0 = fmaxf(mt0, __shfl_xor_sync(0xffffffffu, mt0, 1));
        mt0 = fmaxf(mt0, __shfl_xor_sync(0xffffffffu, mt0, 2));
        mt1 = fmaxf(mt1, __shfl_xor_sync(0xffffffffu, mt1, 1));
        mt1 = fmaxf(mt1, __shfl_xor_sync(0xffffffffu, mt1, 2));
        const float mn0 = fmaxf(mrow0, mt0), mn1 = fmaxf(mrow1, mt1);
        const float al0 = __expf(mrow0 - mn0), al1 = __expf(mrow1 - mn1);
        mrow0 = mn0; mrow1 = mn1;

        // P rounded to bf16 once; l accumulated from ROUNDED values (consistent)
        float rs0 = 0.f, rs1 = 0.f;
        unsigned pah[4][4];
        #pragma unroll
        for (int j2 = 0; j2 < 4; j2++) {
            __nv_bfloat16 h0 = __float2bfloat16_rn(__expf(S[2 * j2][0] - mn0));
            __nv_bfloat16 h1 = __float2bfloat16_rn(__expf(S[2 * j2][1] - mn0));
            __nv_bfloat16 h2 = __float2bfloat16_rn(__expf(S[2 * j2][2] - mn1));
            __nv_bfloat16 h3 = __float2bfloat16_rn(__expf(S[2 * j2][3] - mn1));
            __nv_bfloat16 h4 = __float2bfloat16_rn(__expf(S[2 * j2 + 1][0] - mn0));
            __nv_bfloat16 h5 = __float2bfloat16_rn(__expf(S[2 * j2 + 1][1] - mn0));
            __nv_bfloat16 h6 = __float2bfloat16_rn(__expf(S[2 * j2 + 1][2] - mn1));
            __nv_bfloat16 h7 = __float2bfloat16_rn(__expf(S[2 * j2 + 1][3] - mn1));
            rs0 += (__bfloat162float(h0) + __bfloat162float(h1))
                 + (__bfloat162float(h4) + __bfloat162float(h5));
            rs1 += (__bfloat162float(h2) + __bfloat162float(h3))
                 + (__bfloat162float(h6) + __bfloat162float(h7));
            pah[j2][0] = pack_bf2(h0, h1);
            pah[j2][1] = pack_bf2(h2, h3);
            pah[j2][2] = pack_bf2(h4, h5);
            pah[j2][3] = pack_bf2(h6, h7);
        }
        rs0 += __shfl_xor_sync(0xffffffffu, rs0, 1);
        rs0 += __shfl_xor_sync(0xffffffffu, rs0, 2);
        rs1 += __shfl_xor_sync(0xffffffffu, rs1, 1);
        rs1 += __shfl_xor_sync(0xffffffffu, rs1, 2);
        lrow0 = lrow0 * al0 + rs0;
        lrow1 = lrow1 * al1 + rs1;

        #pragma unroll
        for (int nt = 0; nt < 8; nt++) {
            O[nt][0] *= al0; O[nt][1] *= al0;
            O[nt][2] *= al1; O[nt][3] *= al1;
        }

        // O += P (Vh + Vl); skip k-blocks that are entirely masked (p == 0)
        #pragma unroll
        for (int ks = 0; ks < 4; ks++) {
            if (k0 + ks * 16 <= qmax) {
                #pragma unroll
                for (int n16 = 0; n16 < 4; n16++) {
                    const unsigned off =
                        ((unsigned)((ks * 16 + v_r) * AT_AST + n16 * 16 + v_c)) * 2u;
                    unsigned h0, h1, h2, h3, l0, l1, l2, l3;
                    ldsm_x4_t(h0, h1, h2, h3, sbase + kvb + 2 * K_TB + off);
                    ldsm_x4_t(l0, l1, l2, l3, sbase + kvb + 3 * K_TB + off);
                    unsigned bh0[2] = {h0, h1}, bh1[2] = {h2, h3};
                    unsigned bl0[2] = {l0, l1}, bl1[2] = {l2, l3};
                    mma16816(O[2 * n16], pah[ks], bh0);
                    mma16816(O[2 * n16], pah[ks], bl0);
                    mma16816(O[2 * n16 + 1], pah[ks], bh1);
                    mma16816(O[2 * n16 + 1], pah[ks], bl1);
                }
            }
        }
        __syncthreads();
    }

    const float inv0 = 1.f / lrow0, inv1 = 1.f / lrow1;
    const size_t row0 = (base + q0 + wm + r) * HDIM + hh * HEADD;
    const size_t row1 = (base + q0 + wm + r + 8) * HDIM + hh * HEADD;
    #pragma unroll
    for (int nt = 0; nt < 8; nt++) {
        const int col = nt * 8 + c2;
        *(float2*)(g_ao + row0 + col) = make_float2(O[nt][0] * inv0, O[nt][1] * inv0);
        *(float2*)(g_ao + row1 + col) = make_float2(O[nt][2] * inv1, O[nt][3] * inv1);
    }
}

// ---------------- launcher ---------------------------------------------------
extern "C" void kernel_launch(void* const* d_in, const int* in_sizes, int n_in,
                              void* d_out, int out_size)
{
    const int*   seqs_data = (const int*)  d_in[0];
    const float* seqs_in   = (const float*)d_in[1];
    const int*   position  = (const int*)  d_in[2];
    const float* time_in   = (const float*)d_in[3];
    const float* pos_table = (const float*)d_in[4];
    const float* gate_W    = (const float*)d_in[5];
    const float* gate_b    = (const float*)d_in[6];
    const float* ln_attn_g = (const float*)d_in[7];
    const float* ln_attn_b = (const float*)d_in[8];
    const float* qW        = (const float*)d_in[9];
    const float* qb        = (const float*)d_in[10];
    const float* kW        = (const float*)d_in[11];
    const float* kb        = (const float*)d_in[12];
    const float* vW        = (const float*)d_in[13];
    const float* vb        = (const float*)d_in[14];
    const float* ln_ffn_g  = (const float*)d_in[15];
    const float* ln_ffn_b  = (const float*)d_in[16];
    const float* c1W       = (const float*)d_in[17];
    const float* c1b       = (const float*)d_in[18];
    const float* c2W       = (const float*)d_in[19];
    const float* c2b       = (const float*)d_in[20];
    const float* last_g    = (const float*)d_in[21];
    const float* last_b    = (const float*)d_in[22];

    float *p_seqs, *p_time, *p_Q, *p_ao, *p_x;
    __nv_bfloat16 *p_th, *p_tl, *p_ah, *p_al, *p_bh, *p_bl, *p_wh, *p_wl;
    __nv_bfloat16 *p_qh, *p_ql, *p_kh, *p_kl, *p_vh, *p_vl;
    cudaGetSymbolAddress((void**)&p_seqs, g_seqs);
    cudaGetSymbolAddress((void**)&p_time, g_time);
    cudaGetSymbolAddress((void**)&p_Q,    g_Q);
    cudaGetSymbolAddress((void**)&p_ao,   g_ao);
    cudaGetSymbolAddress((void**)&p_x,    g_x);
    cudaGetSymbolAddress((void**)&p_th,   g_t_hi);
    cudaGetSymbolAddress((void**)&p_tl,   g_t_lo);
    cudaGetSymbolAddress((void**)&p_ah,   g_a_hi);
    cudaGetSymbolAddress((void**)&p_al,   g_a_lo);
    cudaGetSymbolAddress((void**)&p_bh,   g_b_hi);
    cudaGetSymbolAddress((void**)&p_bl,   g_b_lo);
    cudaGetSymbolAddress((void**)&p_wh,   g_w_hi);
    cudaGetSymbolAddress((void**)&p_wl,   g_w_lo);
    cudaGetSymbolAddress((void**)&p_qh,   g_qh);
    cudaGetSymbolAddress((void**)&p_ql,   g_ql);
    cudaGetSymbolAddress((void**)&p_kh,   g_kh);
    cudaGetSymbolAddress((void**)&p_kl,   g_kl);
    cudaGetSymbolAddress((void**)&p_vh,   g_vh);
    cudaGetSymbolAddress((void**)&p_vl,   g_vl);

    cudaFuncSetAttribute(attn_kernel, cudaFuncAttributeMaxDynamicSharedMemorySize, ATTN_SMEM);
    cudaFuncSetAttribute(gemm_qkv,    cudaFuncAttributeMaxDynamicSharedMemorySize, GEMM_SMEM);
    cudaFuncSetAttribute(gemm_mma<1>, cudaFuncAttributeMaxDynamicSharedMemorySize, GEMM_SMEM);
    cudaFuncSetAttribute(gemm_mma<2>, cudaFuncAttributeMaxDynamicSharedMemorySize, GEMM_SMEM);

    prep_kernel<<<NROWS, 256>>>(seqs_data, seqs_in, position, time_in,
                                pos_table, gate_W, gate_b);
    wconv_kernel<<<640, 256>>>(qW, kW, vW, c1W, c2W);

    const size_t WSZ = (size_t)HDIM * HDIM;
    const dim3 ggrid(NROWS / 128, HDIM / 64);
    const dim3 qkvgrid(NROWS / 128, HDIM / 64, 3);
    for (int i = 0; i < 2; i++) {
        lnadd_kernel<<<NROWS, 256>>>(ln_attn_g + i * HDIM, ln_attn_b + i * HDIM,
                                     p_Q, p_ah, p_al, p_bh, p_bl);
        gemm_qkv<<<qkvgrid, 256, GEMM_SMEM>>>(
            p_ah, p_al, p_th, p_tl, p_bh, p_bl,
            p_wh + (size_t)i * WSZ, p_wl + (size_t)i * WSZ,
            qb + i * HDIM, kb + i * HDIM, vb + i * HDIM,
            p_qh, p_ql, p_kh, p_kl, p_vh, p_vl);
        attn_kernel<<<dim3(4, 4, NBATCH), 256, ATTN_SMEM>>>(i);
        ln_kernel<true, true><<<NROWS, 256>>>(p_Q, p_ao,
            ln_ffn_g + i * HDIM, ln_ffn_b + i * HDIM, p_x, p_ah, p_al);
        gemm_mma<1><<<ggrid, 256, GEMM_SMEM>>>(p_ah, p_al,
            p_wh + (3 * 2 + i) * WSZ, p_wl + (3 * 2 + i) * WSZ,
            c1b + i * HDIM, nullptr, nullptr, p_bh, p_bl);
        gemm_mma<2><<<ggrid, 256, GEMM_SMEM>>>(p_bh, p_bl,
            p_wh + (4 * 2 + i) * WSZ, p_wl + (4 * 2 + i) * WSZ,
            c2b + i * HDIM, p_x, p_seqs, nullptr, nullptr);
    }
    ln_kernel<false, false><<<NROWS, 256>>>(p_seqs, nullptr, last_g, last_b,
                                            (float*)d_out, nullptr, nullptr);
}

// round 12
// speedup vs baseline: 1.2460x; 1.0364x over previous
#include <cuda_runtime.h>
#include <cuda_bf16.h>
#include <math.h>

#define NROWS 32768          // B*L
#define HDIM  256
#define LSEQ  512
#define NBATCH 64
#define HEADD 64
#define ITEMPAD 49999

typedef unsigned long long u64;

// ---------------- scratch (device globals; no allocs allowed) ----------------
__device__ __align__(16) float g_seqs[NROWS * HDIM];
__device__ __align__(16) float g_time[NROWS * HDIM];
__device__ __align__(16) float g_Q   [NROWS * HDIM];
__device__ __align__(16) float g_ao  [NROWS * HDIM];
__device__ __align__(16) float g_x   [NROWS * HDIM];
__device__ float g_keep[NROWS];
__device__ float g_gates[NROWS * 2];

__device__ __align__(16) __nv_bfloat16 g_t_hi[NROWS * HDIM];
__device__ __align__(16) __nv_bfloat16 g_t_lo[NROWS * HDIM];
__device__ __align__(16) __nv_bfloat16 g_a_hi[NROWS * HDIM];
__device__ __align__(16) __nv_bfloat16 g_a_lo[NROWS * HDIM];
__device__ __align__(16) __nv_bfloat16 g_b_hi[NROWS * HDIM];
__device__ __align__(16) __nv_bfloat16 g_b_lo[NROWS * HDIM];
__device__ __align__(16) __nv_bfloat16 g_qh[NROWS * HDIM];
__device__ __align__(16) __nv_bfloat16 g_ql[NROWS * HDIM];
__device__ __align__(16) __nv_bfloat16 g_kh[NROWS * HDIM];
__device__ __align__(16) __nv_bfloat16 g_kl[NROWS * HDIM];
__device__ __align__(16) __nv_bfloat16 g_vh[NROWS * HDIM];
__device__ __align__(16) __nv_bfloat16 g_vl[NROWS * HDIM];
__device__ __align__(16) __nv_bfloat16 g_w_hi[5 * 2 * HDIM * HDIM];
__device__ __align__(16) __nv_bfloat16 g_w_lo[5 * 2 * HDIM * HDIM];

// ---------------- small helpers ----------------------------------------------
__device__ __forceinline__ void split_bf(float x, __nv_bfloat16& h, __nv_bfloat16& l) {
    h = __float2bfloat16_rn(x);
    l = __float2bfloat16_rn(x - __bfloat162float(h));
}
__device__ __forceinline__ unsigned pack_bf2(__nv_bfloat16 a, __nv_bfloat16 b) {
    return (unsigned)__bfloat16_as_ushort(a) | ((unsigned)__bfloat16_as_ushort(b) << 16);
}
__device__ __forceinline__ unsigned smem_u32(const void* p) {
    unsigned a;
    asm("{ .reg .u64 t; cvta.to.shared.u64 t, %1; cvt.u32.u64 %0, t; }" : "=r"(a) : "l"(p));
    return a;
}

// ---------------- warp-MMA + cp.async helpers (portable: sm_80+) --------------
__device__ __forceinline__ void ldsm_x4(unsigned& r0, unsigned& r1, unsigned& r2,
                                        unsigned& r3, unsigned addr) {
    asm volatile("ldmatrix.sync.aligned.m8n8.x4.shared.b16 {%0,%1,%2,%3}, [%4];"
        : "=r"(r0), "=r"(r1), "=r"(r2), "=r"(r3) : "r"(addr));
}
__device__ __forceinline__ void ldsm_x4_t(unsigned& r0, unsigned& r1, unsigned& r2,
                                          unsigned& r3, unsigned addr) {
    asm volatile("ldmatrix.sync.aligned.m8n8.x4.trans.shared.b16 {%0,%1,%2,%3}, [%4];"
        : "=r"(r0), "=r"(r1), "=r"(r2), "=r"(r3) : "r"(addr));
}
__device__ __forceinline__ void mma16816(float* d, const unsigned* a, const unsigned* b) {
    asm volatile("mma.sync.aligned.m16n8k16.row.col.f32.bf16.bf16.f32 "
        "{%0,%1,%2,%3}, {%4,%5,%6,%7}, {%8,%9}, {%0,%1,%2,%3};"
        : "+f"(d[0]), "+f"(d[1]), "+f"(d[2]), "+f"(d[3])
        : "r"(a[0]), "r"(a[1]), "r"(a[2]), "r"(a[3]), "r"(b[0]), "r"(b[1]));
}
__device__ __forceinline__ void cp16(unsigned dst, const void* src) {
    asm volatile("cp.async.cg.shared.global [%0], [%1], 16;" :: "r"(dst), "l"(src));
}
__device__ __forceinline__ void cp4(unsigned dst, const void* src) {
    asm volatile("cp.async.ca.shared.global [%0], [%1], 4;" :: "r"(dst), "l"(src));
}
#define CP_COMMIT() asm volatile("cp.async.commit_group;" ::: "memory")
#define CP_WAIT1()  asm volatile("cp.async.wait_group 1;" ::: "memory")
#define CP_WAIT0()  asm volatile("cp.async.wait_group 0;" ::: "memory")

// ---------------- prep -------------------------------------------------------
__global__ __launch_bounds__(256) void prep_kernel(
    const int* __restrict__ seqs_data, const float* __restrict__ seqs_in,
    const int* __restrict__ position, const float* __restrict__ time_in,
    const float* __restrict__ pos_table, const float* __restrict__ gate_W,
    const float* __restrict__ gate_b)
{
    const int n = blockIdx.x;
    const int h = threadIdx.x;
    const size_t idx = (size_t)n * HDIM + h;
    const int p = position[n];
    const float pe = pos_table[(size_t)p * HDIM + h];
    const float t = time_in[idx] + pe;
    const float keep = (seqs_data[n] != ITEMPAD) ? 1.f : 0.f;
    g_seqs[idx] = (seqs_in[idx] + pe) * keep;
    g_time[idx] = t;
    __nv_bfloat16 th, tl;
    split_bf(t, th, tl);
    g_t_hi[idx] = th; g_t_lo[idx] = tl;
    if (h == 0) g_keep[n] = keep;

    __shared__ float red[2][8];
    float p0 = t * gate_W[h];
    float p1 = t * gate_W[HDIM + h];
    #pragma unroll
    for (int o = 16; o; o >>= 1) {
        p0 += __shfl_xor_sync(0xffffffffu, p0, o);
        p1 += __shfl_xor_sync(0xffffffffu, p1, o);
    }
    if ((h & 31) == 0) { red[0][h >> 5] = p0; red[1][h >> 5] = p1; }
    __syncthreads();
    if (h < 2) {
        float s = 0.f;
        #pragma unroll
        for (int j = 0; j < 8; j++) s += red[h][j];
        g_gates[(size_t)n * 2 + h] = 1.f / (1.f + __expf(-(s + gate_b[h])));
    }
}

// ---------------- weight conversion ------------------------------------------
__global__ __launch_bounds__(256) void wconv_kernel(
    const float* __restrict__ q, const float* __restrict__ k,
    const float* __restrict__ v, const float* __restrict__ c1,
    const float* __restrict__ c2)
{
    const int i = blockIdx.x * blockDim.x + threadIdx.x;
    if (i >= 5 * 32768) return;
    const int mat = i >> 15, rem = i & 32767;
    const float* src = (mat == 0) ? q : (mat == 1) ? k : (mat == 2) ? v : (mat == 3) ? c1 : c2;
    float4 x = ((const float4*)src)[rem];
    __nv_bfloat16 h0,l0,h1,l1,h2,l2,h3,l3;
    split_bf(x.x,h0,l0); split_bf(x.y,h1,l1); split_bf(x.z,h2,l2); split_bf(x.w,h3,l3);
    const size_t o = ((size_t)mat << 17) + (size_t)rem * 4;
    *(uint2*)(g_w_hi + o) = make_uint2(pack_bf2(h0,h1), pack_bf2(h2,h3));
    *(uint2*)(g_w_lo + o) = make_uint2(pack_bf2(l0,l1), pack_bf2(l2,l3));
}

// ---------------- fused LN(seqs) + (seqs+time) split --------------------------
__global__ __launch_bounds__(256) void lnadd_kernel(
    const float* __restrict__ g, const float* __restrict__ beta,
    float* __restrict__ Q, __nv_bfloat16* __restrict__ Dh,
    __nv_bfloat16* __restrict__ Dl, __nv_bfloat16* __restrict__ Sh,
    __nv_bfloat16* __restrict__ Sl)
{
    const int n = blockIdx.x;
    const int h = threadIdx.x;
    const size_t idx = (size_t)n * HDIM + h;
    const float x = g_seqs[idx];
    float s = x, q = x * x;
    __shared__ float rs[8], rq[8];
    #pragma unroll
    for (int o = 16; o; o >>= 1) {
        s += __shfl_xor_sync(0xffffffffu, s, o);
        q += __shfl_xor_sync(0xffffffffu, q, o);
    }
    if ((h & 31) == 0) { rs[h >> 5] = s; rq[h >> 5] = q; }
    __syncthreads();
    float tot = 0.f, totq = 0.f;
    #pragma unroll
    for (int j = 0; j < 8; j++) { tot += rs[j]; totq += rq[j]; }
    const float mean = tot * (1.f / HDIM);
    const float var  = totq * (1.f / HDIM) - mean * mean;
    const float y = (x - mean) * rsqrtf(var + 1e-8f) * g[h] + beta[h];
    Q[idx] = y;
    __nv_bfloat16 hh, ll;
    split_bf(y, hh, ll);
    Dh[idx] = hh; Dl[idx] = ll;
    const float st = x + g_time[idx];
    split_bf(st, hh, ll);
    Sh[idx] = hh; Sl[idx] = ll;
}

// ---------------- layernorm (+residual, +bf16 split outputs) ------------------
template<bool ADD, bool BF>
__global__ __launch_bounds__(256) void ln_kernel(
    const float* __restrict__ A, const float* __restrict__ B2,
    const float* __restrict__ g, const float* __restrict__ beta,
    float* __restrict__ dst, __nv_bfloat16* __restrict__ Dh,
    __nv_bfloat16* __restrict__ Dl)
{
    const int n = blockIdx.x;
    const int h = threadIdx.x;
    const size_t idx = (size_t)n * HDIM + h;
    float x = A[idx];
    if (ADD) x += B2[idx];
    float s = x, q = x * x;
    __shared__ float rs[8], rq[8];
    #pragma unroll
    for (int o = 16; o; o >>= 1) {
        s += __shfl_xor_sync(0xffffffffu, s, o);
        q += __shfl_xor_sync(0xffffffffu, q, o);
    }
    if ((h & 31) == 0) { rs[h >> 5] = s; rq[h >> 5] = q; }
    __syncthreads();
    float tot = 0.f, totq = 0.f;
    #pragma unroll
    for (int j = 0; j < 8; j++) { tot += rs[j]; totq += rq[j]; }
    const float mean = tot * (1.f / HDIM);
    const float var  = totq * (1.f / HDIM) - mean * mean;
    const float y = (x - mean) * rsqrtf(var + 1e-8f) * g[h] + beta[h];
    dst[idx] = y;
    if (BF) {
        __nv_bfloat16 hh, ll;
        split_bf(y, hh, ll);
        Dh[idx] = hh; Dl[idx] = ll;
    }
}

// ---------------- GEMM v5: 128x64 tile, 2 CTA/SM, cp.async + frag pipeline ----
#define ASTRIDE 72
#define A_TSZ (128 * ASTRIDE)
#define B_TSZ (64 * ASTRIDE)
#define BUF_ELE (2 * A_TSZ + 2 * B_TSZ)   // 55296 bytes
#define GEMM_SMEM (2 * BUF_ELE * 2)       // 110592 bytes

#define GEMM_ISSUE(c, bufe)                                                      \
    {                                                                            \
        _Pragma("unroll")                                                        \
        for (int i_ = 0; i_ < 4; i_++) {                                         \
            const int v_ = tid + 256 * i_;                                       \
            const int r_ = v_ >> 3, cc_ = v_ & 7;                                \
            const size_t gA_ = (size_t)(bm + r_) * HDIM + (c) * 64 + cc_ * 8;    \
            const unsigned so_ = sbase + ((bufe) + r_ * ASTRIDE + cc_ * 8) * 2u; \
            cp16(so_,             Ah + gA_);                                     \
            cp16(so_ + A_TSZ * 2, Al + gA_);                                     \
        }                                                                        \
        _Pragma("unroll")                                                        \
        for (int i_ = 0; i_ < 2; i_++) {                                         \
            const int v_ = tid + 256 * i_;                                       \
            const int r_ = v_ >> 3, cc_ = v_ & 7;                                \
            const size_t gB_ = (size_t)(bn + r_) * HDIM + (c) * 64 + cc_ * 8;    \
            const unsigned so_ = sbase +                                         \
                ((bufe) + 2 * A_TSZ + r_ * ASTRIDE + cc_ * 8) * 2u;              \
            cp16(so_,             Wh + gB_);                                     \
            cp16(so_ + B_TSZ * 2, Wl + gB_);                                     \
        }                                                                        \
        CP_COMMIT();                                                             \
    }

#define LOADF(p, ks)                                                             \
    {                                                                            \
        const int k_ = (ks) * 16;                                                \
        _Pragma("unroll")                                                        \
        for (int mt_ = 0; mt_ < 2; mt_++) {                                      \
            const unsigned off_ =                                                \
                ((unsigned)((wm + mt_ * 16 + a_r) * ASTRIDE + k_ + a_c)) * 2u;   \
            ldsm_x4(ah[p][mt_][0], ah[p][mt_][1], ah[p][mt_][2], ah[p][mt_][3],  \
                    sbase + bb + off_);                                          \
            ldsm_x4(al[p][mt_][0], al[p][mt_][1], al[p][mt_][2], al[p][mt_][3],  \
                    sbase + bb + A_TSZ * 2 + off_);                              \
        }                                                                        \
        _Pragma("unroll")                                                        \
        for (int nt2_ = 0; nt2_ < 2; nt2_++) {                                   \
            const unsigned off_ = ((unsigned)(2 * A_TSZ +                        \
                (wn + nt2_ * 16 + b_r) * ASTRIDE + k_ + b_c)) * 2u;              \
            unsigned r0_, r1_, r2_, r3_;                                         \
            ldsm_x4(r0_, r1_, r2_, r3_, sbase + bb + off_);                      \
            bh[p][nt2_ * 2][0] = r0_; bh[p][nt2_ * 2][1] = r1_;                  \
            bh[p][nt2_ * 2 + 1][0] = r2_; bh[p][nt2_ * 2 + 1][1] = r3_;          \
            ldsm_x4(r0_, r1_, r2_, r3_, sbase + bb + B_TSZ * 2 + off_);          \
            bl[p][nt2_ * 2][0] = r0_; bl[p][nt2_ * 2][1] = r1_;                  \
            bl[p][nt2_ * 2 + 1][0] = r2_; bl[p][nt2_ * 2 + 1][1] = r3_;          \
        }                                                                        \
    }

template<int EPI>
__global__ __launch_bounds__(256, 2) void gemm_mma(
    const __nv_bfloat16* __restrict__ Ah, const __nv_bfloat16* __restrict__ Al,
    const __nv_bfloat16* __restrict__ Wh, const __nv_bfloat16* __restrict__ Wl,
    const float* __restrict__ bias, const float* __restrict__ R,
    float* __restrict__ Cf, __nv_bfloat16* __restrict__ Ch,
    __nv_bfloat16* __restrict__ Cl)
{
    extern __shared__ __align__(16) __nv_bfloat16 smb[];
    const int tid = threadIdx.x;
    const int lane = tid & 31, wid = tid >> 5;
    const int bm = blockIdx.x << 7;
    const int bn = blockIdx.y << 6;
    const int wm = (wid >> 1) << 5;
    const int wn = (wid & 1) << 5;

    float acc[2][4][4];
    #pragma unroll
    for (int mt = 0; mt < 2; mt++)
        #pragma unroll
        for (int nt = 0; nt < 4; nt++)
            #pragma unroll
            for (int j = 0; j < 4; j++) acc[mt][nt][j] = 0.f;

    const unsigned sbase = smem_u32(smb);
    const int a_r = ((lane >> 3) & 1) * 8 + (lane & 7);
    const int a_c = (lane >> 4) * 8;
    const int b_r = (lane >> 4) * 8 + (lane & 7);
    const int b_c = ((lane >> 3) & 1) * 8;

    unsigned ah[2][2][4], al[2][2][4], bh[2][4][2], bl[2][4][2];

    GEMM_ISSUE(0, 0u);

    for (int c = 0; c < 4; c++) {
        if (c + 1 < 4) {
            GEMM_ISSUE(c + 1, (unsigned)(((c + 1) & 1) * BUF_ELE));
            CP_WAIT1();
        } else {
            CP_WAIT0();
        }
        __syncthreads();
        const unsigned bb = (unsigned)((c & 1) * BUF_ELE) * 2u;

        LOADF(0, 0);
        #pragma unroll
        for (int ks = 0; ks < 4; ks++) {
            if (ks < 3) LOADF((ks + 1) & 1, ks + 1);
            const int p = ks & 1;
            #pragma unroll
            for (int mt = 0; mt < 2; mt++)
                #pragma unroll
                for (int nt = 0; nt < 4; nt++) {
                    mma16816(acc[mt][nt], ah[p][mt], bh[p][nt]);
                    mma16816(acc[mt][nt], al[p][mt], bh[p][nt]);
                    mma16816(acc[mt][nt], ah[p][mt], bl[p][nt]);
                }
        }
        __syncthreads();
    }

    const int qrow = lane >> 2;
    const int qcol = (lane & 3) * 2;
    #pragma unroll
    for (int mt = 0; mt < 2; mt++) {
        #pragma unroll
        for (int half = 0; half < 2; half++) {
            const int row = bm + wm + mt * 16 + qrow + half * 8;
            float keep = 1.f;
            if (EPI == 2) keep = g_keep[row];
            #pragma unroll
            for (int nt = 0; nt < 4; nt++) {
                const int col = bn + wn + nt * 8 + qcol;
                float v0 = acc[mt][nt][half * 2]     + __ldg(bias + col);
                float v1 = acc[mt][nt][half * 2 + 1] + __ldg(bias + col + 1);
                const size_t o = (size_t)row * HDIM + col;
                if (EPI == 0) {
                    *(float2*)(Cf + o) = make_float2(v0, v1);
                } else if (EPI == 1 || EPI == 3) {
                    if (EPI == 1) { v0 = fmaxf(v0, 0.f); v1 = fmaxf(v1, 0.f); }
                    __nv_bfloat16 h0, l0, h1, l1;
                    split_bf(v0, h0, l0); split_bf(v1, h1, l1);
                    *(unsigned*)(Ch + o) = pack_bf2(h0, h1);
                    *(unsigned*)(Cl + o) = pack_bf2(l0, l1);
                } else {
                    const float2 rr = *(const float2*)(R + o);
                    *(float2*)(Cf + o) = make_float2((v0 + rr.x) * keep,
                                                     (v1 + rr.y) * keep);
                }
            }
        }
    }
}

// ---------------- merged q/k/v GEMM (EPI=3), z selects the job ----------------
__global__ __launch_bounds__(256, 2) void gemm_qkv(
    const __nv_bfloat16* __restrict__ Ah0, const __nv_bfloat16* __restrict__ Al0,
    const __nv_bfloat16* __restrict__ Ah1, const __nv_bfloat16* __restrict__ Al1,
    const __nv_bfloat16* __restrict__ Ah2, const __nv_bfloat16* __restrict__ Al2,
    const __nv_bfloat16* __restrict__ Whb, const __nv_bfloat16* __restrict__ Wlb,
    const float* __restrict__ b0, const float* __restrict__ b1,
    const float* __restrict__ b2,
    __nv_bfloat16* __restrict__ C0h, __nv_bfloat16* __restrict__ C0l,
    __nv_bfloat16* __restrict__ C1h, __nv_bfloat16* __restrict__ C1l,
    __nv_bfloat16* __restrict__ C2h, __nv_bfloat16* __restrict__ C2l)
{
    extern __shared__ __align__(16) __nv_bfloat16 smb[];
    const int z = blockIdx.z;
    const __nv_bfloat16* Ah = (z == 0) ? Ah0 : (z == 1) ? Ah1 : Ah2;
    const __nv_bfloat16* Al = (z == 0) ? Al0 : (z == 1) ? Al1 : Al2;
    const __nv_bfloat16* Wh = Whb + (size_t)z * 2 * HDIM * HDIM;
    const __nv_bfloat16* Wl = Wlb + (size_t)z * 2 * HDIM * HDIM;
    const float* bias = (z == 0) ? b0 : (z == 1) ? b1 : b2;
    __nv_bfloat16* Ch = (z == 0) ? C0h : (z == 1) ? C1h : C2h;
    __nv_bfloat16* Cl = (z == 0) ? C0l : (z == 1) ? C1l : C2l;

    const int tid = threadIdx.x;
    const int lane = tid & 31, wid = tid >> 5;
    const int bm = blockIdx.x << 7;
    const int bn = blockIdx.y << 6;
    const int wm = (wid >> 1) << 5;
    const int wn = (wid & 1) << 5;

    float acc[2][4][4];
    #pragma unroll
    for (int mt = 0; mt < 2; mt++)
        #pragma unroll
        for (int nt = 0; nt < 4; nt++)
            #pragma unroll
            for (int j = 0; j < 4; j++) acc[mt][nt][j] = 0.f;

    const unsigned sbase = smem_u32(smb);
    const int a_r = ((lane >> 3) & 1) * 8 + (lane & 7);
    const int a_c = (lane >> 4) * 8;
    const int b_r = (lane >> 4) * 8 + (lane & 7);
    const int b_c = ((lane >> 3) & 1) * 8;

    unsigned ah[2][2][4], al[2][2][4], bh[2][4][2], bl[2][4][2];

    GEMM_ISSUE(0, 0u);

    for (int c = 0; c < 4; c++) {
        if (c + 1 < 4) {
            GEMM_ISSUE(c + 1, (unsigned)(((c + 1) & 1) * BUF_ELE));
            CP_WAIT1();
        } else {
            CP_WAIT0();
        }
        __syncthreads();
        const unsigned bb = (unsigned)((c & 1) * BUF_ELE) * 2u;

        LOADF(0, 0);
        #pragma unroll
        for (int ks = 0; ks < 4; ks++) {
            if (ks < 3) LOADF((ks + 1) & 1, ks + 1);
            const int p = ks & 1;
            #pragma unroll
            for (int mt = 0; mt < 2; mt++)
                #pragma unroll
                for (int nt = 0; nt < 4; nt++) {
                    mma16816(acc[mt][nt], ah[p][mt], bh[p][nt]);
                    mma16816(acc[mt][nt], al[p][mt], bh[p][nt]);
                    mma16816(acc[mt][nt], ah[p][mt], bl[p][nt]);
                }
        }
        __syncthreads();
    }

    const int qrow = lane >> 2;
    const int qcol = (lane & 3) * 2;
    #pragma unroll
    for (int mt = 0; mt < 2; mt++) {
        #pragma unroll
        for (int half = 0; half < 2; half++) {
            const int row = bm + wm + mt * 16 + qrow + half * 8;
            #pragma unroll
            for (int nt = 0; nt < 4; nt++) {
                const int col = bn + wn + nt * 8 + qcol;
                float v0 = acc[mt][nt][half * 2]     + __ldg(bias + col);
                float v1 = acc[mt][nt][half * 2 + 1] + __ldg(bias + col + 1);
                const size_t o = (size_t)row * HDIM + col;
                __nv_bfloat16 h0, l0, h1, l1;
                split_bf(v0, h0, l0); split_bf(v1, h1, l1);
                *(unsigned*)(Ch + o) = pack_bf2(h0, h1);
                *(unsigned*)(Cl + o) = pack_bf2(l0, l1);
            }
        }
    }
}

// ---------------- flash attention (MMA, causal, gated, cp.async 2-buf) --------
#define AT_AST 72
#define SQH_B 0
#define SQL_B (128 * AT_AST * 2)
#define SKV0_B (2 * 128 * AT_AST * 2)
#define KV_BUF_B (4 * 64 * AT_AST * 2)
#define K_TB (64 * AT_AST * 2)
#define STG_B (SKV0_B + 2 * KV_BUF_B)
#define ATTN_SMEM (STG_B + 2 * 64 * 4)

#define KV_ISSUE(kt, bufb)                                                       \
    {                                                                            \
        const int k0_ = (kt) * 64;                                               \
        _Pragma("unroll")                                                        \
        for (int i_ = 0; i_ < 2; i_++) {                                         \
            const int v_ = tid + 256 * i_;                                       \
            const int rr_ = v_ >> 3, cc_ = v_ & 7;                               \
            const size_t go_ = (base + k0_ + rr_) * HDIM + hh * HEADD + cc_ * 8; \
            const unsigned so_ = sbase + (bufb) + (rr_ * AT_AST + cc_ * 8) * 2u; \
            cp16(so_,            g_kh + go_);                                    \
            cp16(so_ + K_TB,     g_kl + go_);                                    \
            cp16(so_ + 2 * K_TB, g_vh + go_);                                    \
            cp16(so_ + 3 * K_TB, g_vl + go_);                                    \
        }                                                                        \
        if (tid < 64)                                                            \
            cp4(sbase + STG_B + (((kt) & 1) * 64 + tid) * 4u,                    \
                g_gates + (base + k0_ + tid) * 2 + blk);                         \
        CP_COMMIT();                                                             \
    }

__global__ __launch_bounds__(256, 2) void attn_kernel(int blk)
{
    extern __shared__ __align__(16) __nv_bfloat16 smb[];
    float* stgk = (float*)((char*)smb + STG_B);

    const int tid = threadIdx.x;
    const int lane = tid & 31, wid = tid >> 5;
    const int qt = blockIdx.x, hh = blockIdx.y, b = blockIdx.z;
    const int q0 = qt * 128;
    const size_t base = (size_t)b * LSEQ;
    const int wm = wid * 16;
    const unsigned sbase = smem_u32(smb);
    const int nkt = 2 * (qt + 1);

    KV_ISSUE(0, (unsigned)SKV0_B);

    #pragma unroll
    for (int i = 0; i < 4; i++) {
        const int v = tid + 256 * i;
        const int r = v >> 3, cc = v & 7;
        const size_t go = (base + q0 + r) * HDIM + hh * HEADD + cc * 8;
        *(uint4*)((char*)smb + SQH_B + (r * AT_AST + cc * 8) * 2) = *(const uint4*)(g_qh + go);
        *(uint4*)((char*)smb + SQL_B + (r * AT_AST + cc * 8) * 2) = *(const uint4*)(g_ql + go);
    }
    __syncthreads();

    const int a_r = ((lane >> 3) & 1) * 8 + (lane & 7);
    const int a_c = (lane >> 4) * 8;
    const int b_r = (lane >> 4) * 8 + (lane & 7);
    const int b_c = ((lane >> 3) & 1) * 8;
    const int v_r = lane & 15;
    const int v_c = (lane >> 4) * 8;

    const int r = lane >> 2;
    const int c2 = (lane & 3) * 2;
    const int qmax = q0 + wm + 15;
    const float cq0 = 0.125f * g_gates[(base + q0 + wm + r) * 2 + blk];
    const float cq1 = 0.125f * g_gates[(base + q0 + wm + r + 8) * 2 + blk];
    float mrow0 = -1e30f, mrow1 = -1e30f, lrow0 = 0.f, lrow1 = 0.f;
    float O[8][4];
    #pragma unroll
    for (int nt = 0; nt < 8; nt++)
        #pragma unroll
        for (int j = 0; j < 4; j++) O[nt][j] = 0.f;

    for (int kt = 0; kt < nkt; kt++) {
        const int k0 = kt * 64;
        if (kt + 1 < nkt) {
            KV_ISSUE(kt + 1, (unsigned)(SKV0_B + ((kt + 1) & 1) * KV_BUF_B));
            CP_WAIT1();
        } else {
            CP_WAIT0();
        }
        __syncthreads();
        const unsigned kvb = (unsigned)(SKV0_B + (kt & 1) * KV_BUF_B);
        const float* stg = stgk + (kt & 1) * 64;

        float S[8][4];
        #pragma unroll
        for (int nt = 0; nt < 8; nt++)
            #pragma unroll
            for (int j = 0; j < 4; j++) S[nt][j] = 0.f;
        // Q fragments reloaded per tile (frees 32 persistent regs for 2 CTA/SM)
        #pragma unroll
        for (int ks = 0; ks < 4; ks++) {
            unsigned aqh[4], aql[4];
            const unsigned qoff =
                ((unsigned)((wm + a_r) * AT_AST + ks * 16 + a_c)) * 2u;
            ldsm_x4(aqh[0], aqh[1], aqh[2], aqh[3], sbase + SQH_B + qoff);
            ldsm_x4(aql[0], aql[1], aql[2], aql[3], sbase + SQL_B + qoff);
            #pragma unroll
            for (int n16 = 0; n16 < 4; n16++) {
                if (k0 + n16 * 16 <= qmax) {
                    const unsigned off =
                        ((unsigned)((n16 * 16 + b_r) * AT_AST + ks * 16 + b_c)) * 2u;
                    unsigned h0, h1, h2, h3, l0, l1, l2, l3;
                    ldsm_x4(h0, h1, h2, h3, sbase + kvb + off);
                    ldsm_x4(l0, l1, l2, l3, sbase + kvb + K_TB + off);
                    unsigned bh0[2] = {h0, h1}, bh1[2] = {h2, h3};
                    unsigned bl0[2] = {l0, l1}, bl1[2] = {l2, l3};
                    mma16816(S[2 * n16], aqh, bh0);
                    mma16816(S[2 * n16], aql, bh0);
                    mma16816(S[2 * n16], aqh, bl0);
                    mma16816(S[2 * n16 + 1], aqh, bh1);
                    mma16816(S[2 * n16 + 1], aql, bh1);
                    mma16816(S[2 * n16 + 1], aqh, bl1);
                }
            }
        }

        const bool need_mask = (k0 + 63 > q0 + wm);
        float mt0 = -1e30f, mt1 = -1e30f;
        #pragma unroll
        for (int nt = 0; nt < 8; nt++) {
            const int col = nt * 8 + c2;
            const float tga = stg[col], tgb = stg[col + 1];
            float v0 = S[nt][0] * cq0 * tga;
            float v1 = S[nt][1] * cq0 * tgb;
            float v2 = S[nt][2] * cq1 * tga;
            float v3 = S[nt][3] * cq1 * tgb;
            if (need_mask) {
                const int kg = k0 + col;
                const int qa = q0 + wm + r, qb2 = qa + 8;
                if (kg     > qa)  v0 = -1e30f;
                if (kg + 1 > qa)  v1 = -1e30f;
                if (kg     > qb2) v2 = -1e30f;
                if (kg + 1 > qb2) v3 = -1e30f;
            }
            S[nt][0] = v0; S[nt][1] = v1; S[nt][2] = v2; S[nt][3] = v3;
            mt0 = fmaxf(mt0, fmaxf(v0, v1));
            mt1 = fmaxf(mt1, fmaxf(v2, v3));
        }
        mt0 = fmaxf(mt0, __shfl_xor_sync(0xffffffffu, mt0, 1));
        mt0 = fmaxf(mt0, __shfl_xor_sync(0xffffffffu, mt0, 2));
        mt1 = fmaxf(mt1, __shfl_xor_sync(0xffffffffu, mt1, 1));
        mt1 = fmaxf(mt1, __shfl_xor_sync(0xffffffffu, mt1, 2));
        const float mn0 = fmaxf(mrow0, mt0), mn1 = fmaxf(mrow1, mt1);
        const float al0 = __expf(mrow0 - mn0), al1 = __expf(mrow1 - mn1);
        mrow0 = mn0; mrow1 = mn1;

        float rs0 = 0.f, rs1 = 0.f;
        unsigned pah[4][4];
        #pragma unroll
        for (int j2 = 0; j2 < 4; j2++) {
            __nv_bfloat16 h0 = __float2bfloat16_rn(__expf(S[2 * j2][0] - mn0));
            __nv_bfloat16 h1 = __float2bfloat16_rn(__expf(S[2 * j2][1] - mn0));
            __nv_bfloat16 h2 = __float2bfloat16_rn(__expf(S[2 * j2][2] - mn1));
            __nv_bfloat16 h3 = __float2bfloat16_rn(__expf(S[2 * j2][3] - mn1));
            __nv_bfloat16 h4 = __float2bfloat16_rn(__expf(S[2 * j2 + 1][0] - mn0));
            __nv_bfloat16 h5 = __float2bfloat16_rn(__expf(S[2 * j2 + 1][1] - mn0));
            __nv_bfloat16 h6 = __float2bfloat16_rn(__expf(S[2 * j2 + 1][2] - mn1));
            __nv_bfloat16 h7 = __float2bfloat16_rn(__expf(S[2 * j2 + 1][3] - mn1));
            rs0 += (__bfloat162float(h0) + __bfloat162float(h1))
                 + (__bfloat162float(h4) + __bfloat162float(h5));
            rs1 += (__bfloat162float(h2) + __bfloat162float(h3))
                 + (__bfloat162float(h6) + __bfloat162float(h7));
            pah[j2][0] = pack_bf2(h0, h1);
            pah[j2][1] = pack_bf2(h2, h3);
            pah[j2][2] = pack_bf2(h4, h5);
            pah[j2][3] = pack_bf2(h6, h7);
        }
        rs0 += __shfl_xor_sync(0xffffffffu, rs0, 1);
        rs0 += __shfl_xor_sync(0xffffffffu, rs0, 2);
        rs1 += __shfl_xor_sync(0xffffffffu, rs1, 1);
        rs1 += __shfl_xor_sync(0xffffffffu, rs1, 2);
        lrow0 = lrow0 * al0 + rs0;
        lrow1 = lrow1 * al1 + rs1;

        #pragma unroll
        for (int nt = 0; nt < 8; nt++) {
            O[nt][0] *= al0; O[nt][1] *= al0;
            O[nt][2] *= al1; O[nt][3] *= al1;
        }

        #pragma unroll
        for (int ks = 0; ks < 4; ks++) {
            if (k0 + ks * 16 <= qmax) {
                #pragma unroll
                for (int n16 = 0; n16 < 4; n16++) {
                    const unsigned off =
                        ((unsigned)((ks * 16 + v_r) * AT_AST + n16 * 16 + v_c)) * 2u;
                    unsigned h0, h1, h2, h3, l0, l1, l2, l3;
                    ldsm_x4_t(h0, h1, h2, h3, sbase + kvb + 2 * K_TB + off);
                    ldsm_x4_t(l0, l1, l2, l3, sbase + kvb + 3 * K_TB + off);
                    unsigned bh0[2] = {h0, h1}, bh1[2] = {h2, h3};
                    unsigned bl0[2] = {l0, l1}, bl1[2] = {l2, l3};
                    mma16816(O[2 * n16], pah[ks], bh0);
                    mma16816(O[2 * n16], pah[ks], bl0);
                    mma16816(O[2 * n16 + 1], pah[ks], bh1);
                    mma16816(O[2 * n16 + 1], pah[ks], bl1);
                }
            }
        }
        __syncthreads();
    }

    const float inv0 = 1.f / lrow0, inv1 = 1.f / lrow1;
    const size_t row0 = (base + q0 + wm + r) * HDIM + hh * HEADD;
    const size_t row1 = (base + q0 + wm + r + 8) * HDIM + hh * HEADD;
    #pragma unroll
    for (int nt = 0; nt < 8; nt++) {
        const int col = nt * 8 + c2;
        *(float2*)(g_ao + row0 + col) = make_float2(O[nt][0] * inv0, O[nt][1] * inv0);
        *(float2*)(g_ao + row1 + col) = make_float2(O[nt][2] * inv1, O[nt][3] * inv1);
    }
}

// ---------------- launcher ---------------------------------------------------
extern "C" void kernel_launch(void* const* d_in, const int* in_sizes, int n_in,
                              void* d_out, int out_size)
{
    const int*   seqs_data = (const int*)  d_in[0];
    const float* seqs_in   = (const float*)d_in[1];
    const int*   position  = (const int*)  d_in[2];
    const float* time_in   = (const float*)d_in[3];
    const float* pos_table = (const float*)d_in[4];
    const float* gate_W    = (const float*)d_in[5];
    const float* gate_b    = (const float*)d_in[6];
    const float* ln_attn_g = (const float*)d_in[7];
    const float* ln_attn_b = (const float*)d_in[8];
    const float* qW        = (const float*)d_in[9];
    const float* qb        = (const float*)d_in[10];
    const float* kW        = (const float*)d_in[11];
    const float* kb        = (const float*)d_in[12];
    const float* vW        = (const float*)d_in[13];
    const float* vb        = (const float*)d_in[14];
    const float* ln_ffn_g  = (const float*)d_in[15];
    const float* ln_ffn_b  = (const float*)d_in[16];
    const float* c1W       = (const float*)d_in[17];
    const float* c1b       = (const float*)d_in[18];
    const float* c2W       = (const float*)d_in[19];
    const float* c2b       = (const float*)d_in[20];
    const float* last_g    = (const float*)d_in[21];
    const float* last_b    = (const float*)d_in[22];

    float *p_seqs, *p_time, *p_Q, *p_ao, *p_x;
    __nv_bfloat16 *p_th, *p_tl, *p_ah, *p_al, *p_bh, *p_bl, *p_wh, *p_wl;
    __nv_bfloat16 *p_qh, *p_ql, *p_kh, *p_kl, *p_vh, *p_vl;
    cudaGetSymbolAddress((void**)&p_seqs, g_seqs);
    cudaGetSymbolAddress((void**)&p_time, g_time);
    cudaGetSymbolAddress((void**)&p_Q,    g_Q);
    cudaGetSymbolAddress((void**)&p_ao,   g_ao);
    cudaGetSymbolAddress((void**)&p_x,    g_x);
    cudaGetSymbolAddress((void**)&p_th,   g_t_hi);
    cudaGetSymbolAddress((void**)&p_tl,   g_t_lo);
    cudaGetSymbolAddress((void**)&p_ah,   g_a_hi);
    cudaGetSymbolAddress((void**)&p_al,   g_a_lo);
    cudaGetSymbolAddress((void**)&p_bh,   g_b_hi);
    cudaGetSymbolAddress((void**)&p_bl,   g_b_lo);
    cudaGetSymbolAddress((void**)&p_wh,   g_w_hi);
    cudaGetSymbolAddress((void**)&p_wl,   g_w_lo);
    cudaGetSymbolAddress((void**)&p_qh,   g_qh);
    cudaGetSymbolAddress((void**)&p_ql,   g_ql);
    cudaGetSymbolAddress((void**)&p_kh,   g_kh);
    cudaGetSymbolAddress((void**)&p_kl,   g_kl);
    cudaGetSymbolAddress((void**)&p_vh,   g_vh);
    cudaGetSymbolAddress((void**)&p_vl,   g_vl);

    cudaFuncSetAttribute(attn_kernel, cudaFuncAttributeMaxDynamicSharedMemorySize, ATTN_SMEM);
    cudaFuncSetAttribute(gemm_qkv,    cudaFuncAttributeMaxDynamicSharedMemorySize, GEMM_SMEM);
    cudaFuncSetAttribute(gemm_mma<1>, cudaFuncAttributeMaxDynamicSharedMemorySize, GEMM_SMEM);
    cudaFuncSetAttribute(gemm_mma<2>, cudaFuncAttributeMaxDynamicSharedMemorySize, GEMM_SMEM);

    prep_kernel<<<NROWS, 256>>>(seqs_data, seqs_in, position, time_in,
                                pos_table, gate_W, gate_b);
    wconv_kernel<<<640, 256>>>(qW, kW, vW, c1W, c2W);

    const size_t WSZ = (size_t)HDIM * HDIM;
    const dim3 ggrid(NROWS / 128, HDIM / 64);
    const dim3 qkvgrid(NROWS / 128, HDIM / 64, 3);
    for (int i = 0; i < 2; i++) {
        lnadd_kernel<<<NROWS, 256>>>(ln_attn_g + i * HDIM, ln_attn_b + i * HDIM,
                                     p_Q, p_ah, p_al, p_bh, p_bl);
        gemm_qkv<<<qkvgrid, 256, GEMM_SMEM>>>(
            p_ah, p_al, p_th, p_tl, p_bh, p_bl,
            p_wh + (size_t)i * WSZ, p_wl + (size_t)i * WSZ,
            qb + i * HDIM, kb + i * HDIM, vb + i * HDIM,
            p_qh, p_ql, p_kh, p_kl, p_vh, p_vl);
        attn_kernel<<<dim3(4, 4, NBATCH), 256, ATTN_SMEM>>>(i);
        ln_kernel<true, true><<<NROWS, 256>>>(p_Q, p_ao,
            ln_ffn_g + i * HDIM, ln_ffn_b + i * HDIM, p_x, p_ah, p_al);
        gemm_mma<1><<<ggrid, 256, GEMM_SMEM>>>(p_ah, p_al,
            p_wh + (3 * 2 + i) * WSZ, p_wl + (3 * 2 + i) * WSZ,
            c1b + i * HDIM, nullptr, nullptr, p_bh, p_bl);
        gemm_mma<2><<<ggrid, 256, GEMM_SMEM>>>(p_bh, p_bl,
            p_wh + (4 * 2 + i) * WSZ, p_wl + (4 * 2 + i) * WSZ,
            c2b + i * HDIM, p_x, p_seqs, nullptr, nullptr);
    }
    ln_kernel<false, false><<<NROWS, 256>>>(p_seqs, nullptr, last_g, last_b,
                                            (float*)d_out, nullptr, nullptr);
}

// round 13
// speedup vs baseline: 1.2521x; 1.0049x over previous
#include <cuda_runtime.h>
#include <cuda_bf16.h>
#include <math.h>

#define NROWS 32768          // B*L
#define HDIM  256
#define LSEQ  512
#define NBATCH 64
#define HEADD 64
#define ITEMPAD 49999

typedef unsigned long long u64;

// ---------------- scratch (device globals; no allocs allowed) ----------------
__device__ __align__(16) float g_seqs[NROWS * HDIM];
__device__ __align__(16) float g_time[NROWS * HDIM];
__device__ __align__(16) float g_Q   [NROWS * HDIM];
__device__ __align__(16) float g_ao  [NROWS * HDIM];
__device__ __align__(16) float g_x   [NROWS * HDIM];
__device__ float g_keep[NROWS];
__device__ float g_gates[NROWS * 2];

__device__ __align__(16) __nv_bfloat16 g_t_hi[NROWS * HDIM];
__device__ __align__(16) __nv_bfloat16 g_t_lo[NROWS * HDIM];
__device__ __align__(16) __nv_bfloat16 g_a_hi[NROWS * HDIM];
__device__ __align__(16) __nv_bfloat16 g_a_lo[NROWS * HDIM];
__device__ __align__(16) __nv_bfloat16 g_b_hi[NROWS * HDIM];
__device__ __align__(16) __nv_bfloat16 g_b_lo[NROWS * HDIM];
__device__ __align__(16) __nv_bfloat16 g_qh[NROWS * HDIM];
__device__ __align__(16) __nv_bfloat16 g_ql[NROWS * HDIM];
__device__ __align__(16) __nv_bfloat16 g_kh[NROWS * HDIM];
__device__ __align__(16) __nv_bfloat16 g_kl[NROWS * HDIM];
__device__ __align__(16) __nv_bfloat16 g_vh[NROWS * HDIM];
__device__ __align__(16) __nv_bfloat16 g_vl[NROWS * HDIM];
__device__ __align__(16) __nv_bfloat16 g_w_hi[5 * 2 * HDIM * HDIM];
__device__ __align__(16) __nv_bfloat16 g_w_lo[5 * 2 * HDIM * HDIM];

// ---------------- small helpers ----------------------------------------------
__device__ __forceinline__ void split_bf(float x, __nv_bfloat16& h, __nv_bfloat16& l) {
    h = __float2bfloat16_rn(x);
    l = __float2bfloat16_rn(x - __bfloat162float(h));
}
__device__ __forceinline__ unsigned pack_bf2(__nv_bfloat16 a, __nv_bfloat16 b) {
    return (unsigned)__bfloat16_as_ushort(a) | ((unsigned)__bfloat16_as_ushort(b) << 16);
}
__device__ __forceinline__ unsigned smem_u32(const void* p) {
    unsigned a;
    asm("{ .reg .u64 t; cvta.to.shared.u64 t, %1; cvt.u32.u64 %0, t; }" : "=r"(a) : "l"(p));
    return a;
}

// ---------------- warp-MMA + cp.async helpers (portable: sm_80+) --------------
__device__ __forceinline__ void ldsm_x4(unsigned& r0, unsigned& r1, unsigned& r2,
                                        unsigned& r3, unsigned addr) {
    asm volatile("ldmatrix.sync.aligned.m8n8.x4.shared.b16 {%0,%1,%2,%3}, [%4];"
        : "=r"(r0), "=r"(r1), "=r"(r2), "=r"(r3) : "r"(addr));
}
__device__ __forceinline__ void ldsm_x4_t(unsigned& r0, unsigned& r1, unsigned& r2,
                                          unsigned& r3, unsigned addr) {
    asm volatile("ldmatrix.sync.aligned.m8n8.x4.trans.shared.b16 {%0,%1,%2,%3}, [%4];"
        : "=r"(r0), "=r"(r1), "=r"(r2), "=r"(r3) : "r"(addr));
}
__device__ __forceinline__ void mma16816(float* d, const unsigned* a, const unsigned* b) {
    asm volatile("mma.sync.aligned.m16n8k16.row.col.f32.bf16.bf16.f32 "
        "{%0,%1,%2,%3}, {%4,%5,%6,%7}, {%8,%9}, {%0,%1,%2,%3};"
        : "+f"(d[0]), "+f"(d[1]), "+f"(d[2]), "+f"(d[3])
        : "r"(a[0]), "r"(a[1]), "r"(a[2]), "r"(a[3]), "r"(b[0]), "r"(b[1]));
}
__device__ __forceinline__ void cp16(unsigned dst, const void* src) {
    asm volatile("cp.async.cg.shared.global [%0], [%1], 16;" :: "r"(dst), "l"(src));
}
__device__ __forceinline__ void cp4(unsigned dst, const void* src) {
    asm volatile("cp.async.ca.shared.global [%0], [%1], 4;" :: "r"(dst), "l"(src));
}
#define CP_COMMIT() asm volatile("cp.async.commit_group;" ::: "memory")
#define CP_WAIT1()  asm volatile("cp.async.wait_group 1;" ::: "memory")
#define CP_WAIT0()  asm volatile("cp.async.wait_group 0;" ::: "memory")

// ---------------- prep -------------------------------------------------------
__global__ __launch_bounds__(256) void prep_kernel(
    const int* __restrict__ seqs_data, const float* __restrict__ seqs_in,
    const int* __restrict__ position, const float* __restrict__ time_in,
    const float* __restrict__ pos_table, const float* __restrict__ gate_W,
    const float* __restrict__ gate_b)
{
    const int n = blockIdx.x;
    const int h = threadIdx.x;
    const size_t idx = (size_t)n * HDIM + h;
    const int p = position[n];
    const float pe = pos_table[(size_t)p * HDIM + h];
    const float t = time_in[idx] + pe;
    const float keep = (seqs_data[n] != ITEMPAD) ? 1.f : 0.f;
    g_seqs[idx] = (seqs_in[idx] + pe) * keep;
    g_time[idx] = t;
    __nv_bfloat16 th, tl;
    split_bf(t, th, tl);
    g_t_hi[idx] = th; g_t_lo[idx] = tl;
    if (h == 0) g_keep[n] = keep;

    __shared__ float red[2][8];
    float p0 = t * gate_W[h];
    float p1 = t * gate_W[HDIM + h];
    #pragma unroll
    for (int o = 16; o; o >>= 1) {
        p0 += __shfl_xor_sync(0xffffffffu, p0, o);
        p1 += __shfl_xor_sync(0xffffffffu, p1, o);
    }
    if ((h & 31) == 0) { red[0][h >> 5] = p0; red[1][h >> 5] = p1; }
    __syncthreads();
    if (h < 2) {
        float s = 0.f;
        #pragma unroll
        for (int j = 0; j < 8; j++) s += red[h][j];
        g_gates[(size_t)n * 2 + h] = 1.f / (1.f + __expf(-(s + gate_b[h])));
    }
}

// ---------------- weight conversion ------------------------------------------
__global__ __launch_bounds__(256) void wconv_kernel(
    const float* __restrict__ q, const float* __restrict__ k,
    const float* __restrict__ v, const float* __restrict__ c1,
    const float* __restrict__ c2)
{
    const int i = blockIdx.x * blockDim.x + threadIdx.x;
    if (i >= 5 * 32768) return;
    const int mat = i >> 15, rem = i & 32767;
    const float* src = (mat == 0) ? q : (mat == 1) ? k : (mat == 2) ? v : (mat == 3) ? c1 : c2;
    float4 x = ((const float4*)src)[rem];
    __nv_bfloat16 h0,l0,h1,l1,h2,l2,h3,l3;
    split_bf(x.x,h0,l0); split_bf(x.y,h1,l1); split_bf(x.z,h2,l2); split_bf(x.w,h3,l3);
    const size_t o = ((size_t)mat << 17) + (size_t)rem * 4;
    *(uint2*)(g_w_hi + o) = make_uint2(pack_bf2(h0,h1), pack_bf2(h2,h3));
    *(uint2*)(g_w_lo + o) = make_uint2(pack_bf2(l0,l1), pack_bf2(l2,l3));
}

// ---------------- fused LN(seqs) + (seqs+time) split --------------------------
__global__ __launch_bounds__(256) void lnadd_kernel(
    const float* __restrict__ g, const float* __restrict__ beta,
    float* __restrict__ Q, __nv_bfloat16* __restrict__ Dh,
    __nv_bfloat16* __restrict__ Dl, __nv_bfloat16* __restrict__ Sh,
    __nv_bfloat16* __restrict__ Sl)
{
    const int n = blockIdx.x;
    const int h = threadIdx.x;
    const size_t idx = (size_t)n * HDIM + h;
    const float x = g_seqs[idx];
    float s = x, q = x * x;
    __shared__ float rs[8], rq[8];
    #pragma unroll
    for (int o = 16; o; o >>= 1) {
        s += __shfl_xor_sync(0xffffffffu, s, o);
        q += __shfl_xor_sync(0xffffffffu, q, o);
    }
    if ((h & 31) == 0) { rs[h >> 5] = s; rq[h >> 5] = q; }
    __syncthreads();
    float tot = 0.f, totq = 0.f;
    #pragma unroll
    for (int j = 0; j < 8; j++) { tot += rs[j]; totq += rq[j]; }
    const float mean = tot * (1.f / HDIM);
    const float var  = totq * (1.f / HDIM) - mean * mean;
    const float y = (x - mean) * rsqrtf(var + 1e-8f) * g[h] + beta[h];
    Q[idx] = y;
    __nv_bfloat16 hh, ll;
    split_bf(y, hh, ll);
    Dh[idx] = hh; Dl[idx] = ll;
    const float st = x + g_time[idx];
    split_bf(st, hh, ll);
    Sh[idx] = hh; Sl[idx] = ll;
}

// ---------------- layernorm (+residual, +bf16 split outputs) ------------------
template<bool ADD, bool BF>
__global__ __launch_bounds__(256) void ln_kernel(
    const float* __restrict__ A, const float* __restrict__ B2,
    const float* __restrict__ g, const float* __restrict__ beta,
    float* __restrict__ dst, __nv_bfloat16* __restrict__ Dh,
    __nv_bfloat16* __restrict__ Dl)
{
    const int n = blockIdx.x;
    const int h = threadIdx.x;
    const size_t idx = (size_t)n * HDIM + h;
    float x = A[idx];
    if (ADD) x += B2[idx];
    float s = x, q = x * x;
    __shared__ float rs[8], rq[8];
    #pragma unroll
    for (int o = 16; o; o >>= 1) {
        s += __shfl_xor_sync(0xffffffffu, s, o);
        q += __shfl_xor_sync(0xffffffffu, q, o);
    }
    if ((h & 31) == 0) { rs[h >> 5] = s; rq[h >> 5] = q; }
    __syncthreads();
    float tot = 0.f, totq = 0.f;
    #pragma unroll
    for (int j = 0; j < 8; j++) { tot += rs[j]; totq += rq[j]; }
    const float mean = tot * (1.f / HDIM);
    const float var  = totq * (1.f / HDIM) - mean * mean;
    const float y = (x - mean) * rsqrtf(var + 1e-8f) * g[h] + beta[h];
    dst[idx] = y;
    if (BF) {
        __nv_bfloat16 hh, ll;
        split_bf(y, hh, ll);
        Dh[idx] = hh; Dl[idx] = ll;
    }
}

// ---------------- GEMM v6: term-outer MMA order (breaks RAW chains) -----------
#define ASTRIDE 72
#define A_TSZ (128 * ASTRIDE)
#define B_TSZ (64 * ASTRIDE)
#define BUF_ELE (2 * A_TSZ + 2 * B_TSZ)   // 55296 bytes
#define GEMM_SMEM (2 * BUF_ELE * 2)       // 110592 bytes

#define GEMM_ISSUE(c, bufe)                                                      \
    {                                                                            \
        _Pragma("unroll")                                                        \
        for (int i_ = 0; i_ < 4; i_++) {                                         \
            const int v_ = tid + 256 * i_;                                       \
            const int r_ = v_ >> 3, cc_ = v_ & 7;                                \
            const size_t gA_ = (size_t)(bm + r_) * HDIM + (c) * 64 + cc_ * 8;    \
            const unsigned so_ = sbase + ((bufe) + r_ * ASTRIDE + cc_ * 8) * 2u; \
            cp16(so_,             Ah + gA_);                                     \
            cp16(so_ + A_TSZ * 2, Al + gA_);                                     \
        }                                                                        \
        _Pragma("unroll")                                                        \
        for (int i_ = 0; i_ < 2; i_++) {                                         \
            const int v_ = tid + 256 * i_;                                       \
            const int r_ = v_ >> 3, cc_ = v_ & 7;                                \
            const size_t gB_ = (size_t)(bn + r_) * HDIM + (c) * 64 + cc_ * 8;    \
            const unsigned so_ = sbase +                                         \
                ((bufe) + 2 * A_TSZ + r_ * ASTRIDE + cc_ * 8) * 2u;              \
            cp16(so_,             Wh + gB_);                                     \
            cp16(so_ + B_TSZ * 2, Wl + gB_);                                     \
        }                                                                        \
        CP_COMMIT();                                                             \
    }

#define LOADF(p, ks)                                                             \
    {                                                                            \
        const int k_ = (ks) * 16;                                                \
        _Pragma("unroll")                                                        \
        for (int mt_ = 0; mt_ < 2; mt_++) {                                      \
            const unsigned off_ =                                                \
                ((unsigned)((wm + mt_ * 16 + a_r) * ASTRIDE + k_ + a_c)) * 2u;   \
            ldsm_x4(ah[p][mt_][0], ah[p][mt_][1], ah[p][mt_][2], ah[p][mt_][3],  \
                    sbase + bb + off_);                                          \
            ldsm_x4(al[p][mt_][0], al[p][mt_][1], al[p][mt_][2], al[p][mt_][3],  \
                    sbase + bb + A_TSZ * 2 + off_);                              \
        }                                                                        \
        _Pragma("unroll")                                                        \
        for (int nt2_ = 0; nt2_ < 2; nt2_++) {                                   \
            const unsigned off_ = ((unsigned)(2 * A_TSZ +                        \
                (wn + nt2_ * 16 + b_r) * ASTRIDE + k_ + b_c)) * 2u;              \
            unsigned r0_, r1_, r2_, r3_;                                         \
            ldsm_x4(r0_, r1_, r2_, r3_, sbase + bb + off_);                      \
            bh[p][nt2_ * 2][0] = r0_; bh[p][nt2_ * 2][1] = r1_;                  \
            bh[p][nt2_ * 2 + 1][0] = r2_; bh[p][nt2_ * 2 + 1][1] = r3_;          \
            ldsm_x4(r0_, r1_, r2_, r3_, sbase + bb + B_TSZ * 2 + off_);          \
            bl[p][nt2_ * 2][0] = r0_; bl[p][nt2_ * 2][1] = r1_;                  \
            bl[p][nt2_ * 2 + 1][0] = r2_; bl[p][nt2_ * 2 + 1][1] = r3_;          \
        }                                                                        \
    }

// term-outer MMA body: same per-acc order (hh, lh, hl) => bit-identical
#define GEMM_MMAS(p)                                                             \
    {                                                                            \
        _Pragma("unroll")                                                        \
        for (int mt = 0; mt < 2; mt++)                                           \
            _Pragma("unroll")                                                    \
            for (int nt = 0; nt < 4; nt++)                                       \
                mma16816(acc[mt][nt], ah[p][mt], bh[p][nt]);                     \
        _Pragma("unroll")                                                        \
        for (int mt = 0; mt < 2; mt++)                                           \
            _Pragma("unroll")                                                    \
            for (int nt = 0; nt < 4; nt++)                                       \
                mma16816(acc[mt][nt], al[p][mt], bh[p][nt]);                     \
        _Pragma("unroll")                                                        \
        for (int mt = 0; mt < 2; mt++)                                           \
            _Pragma("unroll")                                                    \
            for (int nt = 0; nt < 4; nt++)                                       \
                mma16816(acc[mt][nt], ah[p][mt], bl[p][nt]);                     \
    }

template<int EPI>
__global__ __launch_bounds__(256, 2) void gemm_mma(
    const __nv_bfloat16* __restrict__ Ah, const __nv_bfloat16* __restrict__ Al,
    const __nv_bfloat16* __restrict__ Wh, const __nv_bfloat16* __restrict__ Wl,
    const float* __restrict__ bias, const float* __restrict__ R,
    float* __restrict__ Cf, __nv_bfloat16* __restrict__ Ch,
    __nv_bfloat16* __restrict__ Cl)
{
    extern __shared__ __align__(16) __nv_bfloat16 smb[];
    const int tid = threadIdx.x;
    const int lane = tid & 31, wid = tid >> 5;
    const int bm = blockIdx.x << 7;
    const int bn = blockIdx.y << 6;
    const int wm = (wid >> 1) << 5;
    const int wn = (wid & 1) << 5;

    float acc[2][4][4];
    #pragma unroll
    for (int mt = 0; mt < 2; mt++)
        #pragma unroll
        for (int nt = 0; nt < 4; nt++)
            #pragma unroll
            for (int j = 0; j < 4; j++) acc[mt][nt][j] = 0.f;

    const unsigned sbase = smem_u32(smb);
    const int a_r = ((lane >> 3) & 1) * 8 + (lane & 7);
    const int a_c = (lane >> 4) * 8;
    const int b_r = (lane >> 4) * 8 + (lane & 7);
    const int b_c = ((lane >> 3) & 1) * 8;

    unsigned ah[2][2][4], al[2][2][4], bh[2][4][2], bl[2][4][2];

    GEMM_ISSUE(0, 0u);

    for (int c = 0; c < 4; c++) {
        if (c + 1 < 4) {
            GEMM_ISSUE(c + 1, (unsigned)(((c + 1) & 1) * BUF_ELE));
            CP_WAIT1();
        } else {
            CP_WAIT0();
        }
        __syncthreads();
        const unsigned bb = (unsigned)((c & 1) * BUF_ELE) * 2u;

        LOADF(0, 0);
        #pragma unroll
        for (int ks = 0; ks < 4; ks++) {
            if (ks < 3) LOADF((ks + 1) & 1, ks + 1);
            const int p = ks & 1;
            GEMM_MMAS(p);
        }
        __syncthreads();
    }

    const int qrow = lane >> 2;
    const int qcol = (lane & 3) * 2;
    #pragma unroll
    for (int mt = 0; mt < 2; mt++) {
        #pragma unroll
        for (int half = 0; half < 2; half++) {
            const int row = bm + wm + mt * 16 + qrow + half * 8;
            float keep = 1.f;
            if (EPI == 2) keep = g_keep[row];
            #pragma unroll
            for (int nt = 0; nt < 4; nt++) {
                const int col = bn + wn + nt * 8 + qcol;
                float v0 = acc[mt][nt][half * 2]     + __ldg(bias + col);
                float v1 = acc[mt][nt][half * 2 + 1] + __ldg(bias + col + 1);
                const size_t o = (size_t)row * HDIM + col;
                if (EPI == 0) {
                    *(float2*)(Cf + o) = make_float2(v0, v1);
                } else if (EPI == 1 || EPI == 3) {
                    if (EPI == 1) { v0 = fmaxf(v0, 0.f); v1 = fmaxf(v1, 0.f); }
                    __nv_bfloat16 h0, l0, h1, l1;
                    split_bf(v0, h0, l0); split_bf(v1, h1, l1);
                    *(unsigned*)(Ch + o) = pack_bf2(h0, h1);
                    *(unsigned*)(Cl + o) = pack_bf2(l0, l1);
                } else {
                    const float2 rr = *(const float2*)(R + o);
                    *(float2*)(Cf + o) = make_float2((v0 + rr.x) * keep,
                                                     (v1 + rr.y) * keep);
                }
            }
        }
    }
}

// ---------------- merged q/k/v GEMM (EPI=3), z selects the job ----------------
__global__ __launch_bounds__(256, 2) void gemm_qkv(
    const __nv_bfloat16* __restrict__ Ah0, const __nv_bfloat16* __restrict__ Al0,
    const __nv_bfloat16* __restrict__ Ah1, const __nv_bfloat16* __restrict__ Al1,
    const __nv_bfloat16* __restrict__ Ah2, const __nv_bfloat16* __restrict__ Al2,
    const __nv_bfloat16* __restrict__ Whb, const __nv_bfloat16* __restrict__ Wlb,
    const float* __restrict__ b0, const float* __restrict__ b1,
    const float* __restrict__ b2,
    __nv_bfloat16* __restrict__ C0h, __nv_bfloat16* __restrict__ C0l,
    __nv_bfloat16* __restrict__ C1h, __nv_bfloat16* __restrict__ C1l,
    __nv_bfloat16* __restrict__ C2h, __nv_bfloat16* __restrict__ C2l)
{
    extern __shared__ __align__(16) __nv_bfloat16 smb[];
    const int z = blockIdx.z;
    const __nv_bfloat16* Ah = (z == 0) ? Ah0 : (z == 1) ? Ah1 : Ah2;
    const __nv_bfloat16* Al = (z == 0) ? Al0 : (z == 1) ? Al1 : Al2;
    const __nv_bfloat16* Wh = Whb + (size_t)z * 2 * HDIM * HDIM;
    const __nv_bfloat16* Wl = Wlb + (size_t)z * 2 * HDIM * HDIM;
    const float* bias = (z == 0) ? b0 : (z == 1) ? b1 : b2;
    __nv_bfloat16* Ch = (z == 0) ? C0h : (z == 1) ? C1h : C2h;
    __nv_bfloat16* Cl = (z == 0) ? C0l : (z == 1) ? C1l : C2l;

    const int tid = threadIdx.x;
    const int lane = tid & 31, wid = tid >> 5;
    const int bm = blockIdx.x << 7;
    const int bn = blockIdx.y << 6;
    const int wm = (wid >> 1) << 5;
    const int wn = (wid & 1) << 5;

    float acc[2][4][4];
    #pragma unroll
    for (int mt = 0; mt < 2; mt++)
        #pragma unroll
        for (int nt = 0; nt < 4; nt++)
            #pragma unroll
            for (int j = 0; j < 4; j++) acc[mt][nt][j] = 0.f;

    const unsigned sbase = smem_u32(smb);
    const int a_r = ((lane >> 3) & 1) * 8 + (lane & 7);
    const int a_c = (lane >> 4) * 8;
    const int b_r = (lane >> 4) * 8 + (lane & 7);
    const int b_c = ((lane >> 3) & 1) * 8;

    unsigned ah[2][2][4], al[2][2][4], bh[2][4][2], bl[2][4][2];

    GEMM_ISSUE(0, 0u);

    for (int c = 0; c < 4; c++) {
        if (c + 1 < 4) {
            GEMM_ISSUE(c + 1, (unsigned)(((c + 1) & 1) * BUF_ELE));
            CP_WAIT1();
        } else {
            CP_WAIT0();
        }
        __syncthreads();
        const unsigned bb = (unsigned)((c & 1) * BUF_ELE) * 2u;

        LOADF(0, 0);
        #pragma unroll
        for (int ks = 0; ks < 4; ks++) {
            if (ks < 3) LOADF((ks + 1) & 1, ks + 1);
            const int p = ks & 1;
            GEMM_MMAS(p);
        }
        __syncthreads();
    }

    const int qrow = lane >> 2;
    const int qcol = (lane & 3) * 2;
    #pragma unroll
    for (int mt = 0; mt < 2; mt++) {
        #pragma unroll
        for (int half = 0; half < 2; half++) {
            const int row = bm + wm + mt * 16 + qrow + half * 8;
            #pragma unroll
            for (int nt = 0; nt < 4; nt++) {
                const int col = bn + wn + nt * 8 + qcol;
                float v0 = acc[mt][nt][half * 2]     + __ldg(bias + col);
                float v1 = acc[mt][nt][half * 2 + 1] + __ldg(bias + col + 1);
                const size_t o = (size_t)row * HDIM + col;
                __nv_bfloat16 h0, l0, h1, l1;
                split_bf(v0, h0, l0); split_bf(v1, h1, l1);
                *(unsigned*)(Ch + o) = pack_bf2(h0, h1);
                *(unsigned*)(Cl + o) = pack_bf2(l0, l1);
            }
        }
    }
}

// ---------------- flash attention (MMA, causal, gated, cp.async 2-buf) --------
#define AT_AST 72
#define SQH_B 0
#define SQL_B (128 * AT_AST * 2)
#define SKV0_B (2 * 128 * AT_AST * 2)
#define KV_BUF_B (4 * 64 * AT_AST * 2)
#define K_TB (64 * AT_AST * 2)
#define STG_B (SKV0_B + 2 * KV_BUF_B)
#define ATTN_SMEM (STG_B + 2 * 64 * 4)

#define KV_ISSUE(kt, bufb)                                                       \
    {                                                                            \
        const int k0_ = (kt) * 64;                                               \
        _Pragma("unroll")                                                        \
        for (int i_ = 0; i_ < 2; i_++) {                                         \
            const int v_ = tid + 256 * i_;                                       \
            const int rr_ = v_ >> 3, cc_ = v_ & 7;                               \
            const size_t go_ = (base + k0_ + rr_) * HDIM + hh * HEADD + cc_ * 8; \
            const unsigned so_ = sbase + (bufb) + (rr_ * AT_AST + cc_ * 8) * 2u; \
            cp16(so_,            g_kh + go_);                                    \
            cp16(so_ + K_TB,     g_kl + go_);                                    \
            cp16(so_ + 2 * K_TB, g_vh + go_);                                    \
            cp16(so_ + 3 * K_TB, g_vl + go_);                                    \
        }                                                                        \
        if (tid < 64)                                                            \
            cp4(sbase + STG_B + (((kt) & 1) * 64 + tid) * 4u,                    \
                g_gates + (base + k0_ + tid) * 2 + blk);                         \
        CP_COMMIT();                                                             \
    }

__global__ __launch_bounds__(256, 2) void attn_kernel(int blk)
{
    extern __shared__ __align__(16) __nv_bfloat16 smb[];
    float* stgk = (float*)((char*)smb + STG_B);

    const int tid = threadIdx.x;
    const int lane = tid & 31, wid = tid >> 5;
    const int qt = blockIdx.x, hh = blockIdx.y, b = blockIdx.z;
    const int q0 = qt * 128;
    const size_t base = (size_t)b * LSEQ;
    const int wm = wid * 16;
    const unsigned sbase = smem_u32(smb);
    const int nkt = 2 * (qt + 1);

    KV_ISSUE(0, (unsigned)SKV0_B);

    #pragma unroll
    for (int i = 0; i < 4; i++) {
        const int v = tid + 256 * i;
        const int r = v >> 3, cc = v & 7;
        const size_t go = (base + q0 + r) * HDIM + hh * HEADD + cc * 8;
        *(uint4*)((char*)smb + SQH_B + (r * AT_AST + cc * 8) * 2) = *(const uint4*)(g_qh + go);
        *(uint4*)((char*)smb + SQL_B + (r * AT_AST + cc * 8) * 2) = *(const uint4*)(g_ql + go);
    }
    __syncthreads();

    const int a_r = ((lane >> 3) & 1) * 8 + (lane & 7);
    const int a_c = (lane >> 4) * 8;
    const int b_r = (lane >> 4) * 8 + (lane & 7);
    const int b_c = ((lane >> 3) & 1) * 8;
    const int v_r = lane & 15;
    const int v_c = (lane >> 4) * 8;

    const int r = lane >> 2;
    const int c2 = (lane & 3) * 2;
    const int qmax = q0 + wm + 15;
    const float cq0 = 0.125f * g_gates[(base + q0 + wm + r) * 2 + blk];
    const float cq1 = 0.125f * g_gates[(base + q0 + wm + r + 8) * 2 + blk];
    float mrow0 = -1e30f, mrow1 = -1e30f, lrow0 = 0.f, lrow1 = 0.f;
    float O[8][4];
    #pragma unroll
    for (int nt = 0; nt < 8; nt++)
        #pragma unroll
        for (int j = 0; j < 4; j++) O[nt][j] = 0.f;

    for (int kt = 0; kt < nkt; kt++) {
        const int k0 = kt * 64;
        if (kt + 1 < nkt) {
            KV_ISSUE(kt + 1, (unsigned)(SKV0_B + ((kt + 1) & 1) * KV_BUF_B));
            CP_WAIT1();
        } else {
            CP_WAIT0();
        }
        __syncthreads();
        const unsigned kvb = (unsigned)(SKV0_B + (kt & 1) * KV_BUF_B);
        const float* stg = stgk + (kt & 1) * 64;

        float S[8][4];
        #pragma unroll
        for (int nt = 0; nt < 8; nt++)
            #pragma unroll
            for (int j = 0; j < 4; j++) S[nt][j] = 0.f;
        // term-pair reordered S: per (ks, n16-pair), 3 term passes of 4 MMAs
        #pragma unroll
        for (int ks = 0; ks < 4; ks++) {
            unsigned aqh[4], aql[4];
            const unsigned qoff =
                ((unsigned)((wm + a_r) * AT_AST + ks * 16 + a_c)) * 2u;
            ldsm_x4(aqh[0], aqh[1], aqh[2], aqh[3], sbase + SQH_B + qoff);
            ldsm_x4(aql[0], aql[1], aql[2], aql[3], sbase + SQL_B + qoff);
            #pragma unroll
            for (int p16 = 0; p16 < 2; p16++) {
                const int na = 2 * p16, nb = 2 * p16 + 1;
                const bool actA = (k0 + na * 16 <= qmax);
                const bool actB = (k0 + nb * 16 <= qmax);
                unsigned kAh[2][2], kAl[2][2], kBh[2][2], kBl[2][2];
                if (actA) {
                    const unsigned off =
                        ((unsigned)((na * 16 + b_r) * AT_AST + ks * 16 + b_c)) * 2u;
                    ldsm_x4(kAh[0][0], kAh[0][1], kAh[1][0], kAh[1][1],
                            sbase + kvb + off);
                    ldsm_x4(kAl[0][0], kAl[0][1], kAl[1][0], kAl[1][1],
                            sbase + kvb + K_TB + off);
                }
                if (actB) {
                    const unsigned off =
                        ((unsigned)((nb * 16 + b_r) * AT_AST + ks * 16 + b_c)) * 2u;
                    ldsm_x4(kBh[0][0], kBh[0][1], kBh[1][0], kBh[1][1],
                            sbase + kvb + off);
                    ldsm_x4(kBl[0][0], kBl[0][1], kBl[1][0], kBl[1][1],
                            sbase + kvb + K_TB + off);
                }
                // term hh
                if (actA) { mma16816(S[2*na], aqh, kAh[0]); mma16816(S[2*na+1], aqh, kAh[1]); }
                if (actB) { mma16816(S[2*nb], aqh, kBh[0]); mma16816(S[2*nb+1], aqh, kBh[1]); }
                // term lh
                if (actA) { mma16816(S[2*na], aql, kAh[0]); mma16816(S[2*na+1], aql, kAh[1]); }
                if (actB) { mma16816(S[2*nb], aql, kBh[0]); mma16816(S[2*nb+1], aql, kBh[1]); }
                // term hl
                if (actA) { mma16816(S[2*na], aqh, kAl[0]); mma16816(S[2*na+1], aqh, kAl[1]); }
                if (actB) { mma16816(S[2*nb], aqh, kBl[0]); mma16816(S[2*nb+1], aqh, kBl[1]); }
            }
        }

        const bool need_mask = (k0 + 63 > q0 + wm);
        float mt0 = -1e30f, mt1 = -1e30f;
        #pragma unroll
        for (int nt = 0; nt < 8; nt++) {
            const int col = nt * 8 + c2;
            const float tga = stg[col], tgb = stg[col + 1];
            float v0 = S[nt][0] * cq0 * tga;
            float v1 = S[nt][1] * cq0 * tgb;
            float v2 = S[nt][2] * cq1 * tga;
            float v3 = S[nt][3] * cq1 * tgb;
            if (need_mask) {
                const int kg = k0 + col;
                const int qa = q0 + wm + r, qb2 = qa + 8;
                if (kg     > qa)  v0 = -1e30f;
                if (kg + 1 > qa)  v1 = -1e30f;
                if (kg     > qb2) v2 = -1e30f;
                if (kg + 1 > qb2) v3 = -1e30f;
            }
            S[nt][0] = v0; S[nt][1] = v1; S[nt][2] = v2; S[nt][3] = v3;
            mt0 = fmaxf(mt0, fmaxf(v0, v1));
            mt1 = fmaxf(mt1, fmaxf(v2, v3));
        }
        mt0 = fmaxf(mt0, __shfl_xor_sync(0xffffffffu, mt0, 1));
        mt0 = fmaxf(mt0, __shfl_xor_sync(0xffffffffu, mt0, 2));
        mt1 = fmaxf(mt1, __shfl_xor_sync(0xffffffffu, mt1, 1));
        mt1 = fmaxf(mt1, __shfl_xor_sync(0xffffffffu, mt1, 2));
        const float mn0 = fmaxf(mrow0, mt0), mn1 = fmaxf(mrow1, mt1);
        const float al0 = __expf(mrow0 - mn0), al1 = __expf(mrow1 - mn1);
        mrow0 = mn0; mrow1 = mn1;

        float rs0 = 0.f, rs1 = 0.f;
        unsigned pah[4][4];
        #pragma unroll
        for (int j2 = 0; j2 < 4; j2++) {
            __nv_bfloat16 h0 = __float2bfloat16_rn(__expf(S[2 * j2][0] - mn0));
            __nv_bfloat16 h1 = __float2bfloat16_rn(__expf(S[2 * j2][1] - mn0));
            __nv_bfloat16 h2 = __float2bfloat16_rn(__expf(S[2 * j2][2] - mn1));
            __nv_bfloat16 h3 = __float2bfloat16_rn(__expf(S[2 * j2][3] - mn1));
            __nv_bfloat16 h4 = __float2bfloat16_rn(__expf(S[2 * j2 + 1][0] - mn0));
            __nv_bfloat16 h5 = __float2bfloat16_rn(__expf(S[2 * j2 + 1][1] - mn0));
            __nv_bfloat16 h6 = __float2bfloat16_rn(__expf(S[2 * j2 + 1][2] - mn1));
            __nv_bfloat16 h7 = __float2bfloat16_rn(__expf(S[2 * j2 + 1][3] - mn1));
            rs0 += (__bfloat162float(h0) + __bfloat162float(h1))
                 + (__bfloat162float(h4) + __bfloat162float(h5));
            rs1 += (__bfloat162float(h2) + __bfloat162float(h3))
                 + (__bfloat162float(h6) + __bfloat162float(h7));
            pah[j2][0] = pack_bf2(h0, h1);
            pah[j2][1] = pack_bf2(h2, h3);
            pah[j2][2] = pack_bf2(h4, h5);
            pah[j2][3] = pack_bf2(h6, h7);
        }
        rs0 += __shfl_xor_sync(0xffffffffu, rs0, 1);
        rs0 += __shfl_xor_sync(0xffffffffu, rs0, 2);
        rs1 += __shfl_xor_sync(0xffffffffu, rs1, 1);
        rs1 += __shfl_xor_sync(0xffffffffu, rs1, 2);
        lrow0 = lrow0 * al0 + rs0;
        lrow1 = lrow1 * al1 + rs1;

        #pragma unroll
        for (int nt = 0; nt < 8; nt++) {
            O[nt][0] *= al0; O[nt][1] *= al0;
            O[nt][2] *= al1; O[nt][3] *= al1;
        }

        // PV: per (ks, n16-pair), 2 term passes of 4 MMAs (same per-acc order)
        #pragma unroll
        for (int ks = 0; ks < 4; ks++) {
            if (k0 + ks * 16 <= qmax) {
                #pragma unroll
                for (int p16 = 0; p16 < 2; p16++) {
                    const int na = 2 * p16, nb = 2 * p16 + 1;
                    unsigned vAh[2][2], vAl[2][2], vBh[2][2], vBl[2][2];
                    {
                        const unsigned off =
                            ((unsigned)((ks * 16 + v_r) * AT_AST + na * 16 + v_c)) * 2u;
                        ldsm_x4_t(vAh[0][0], vAh[0][1], vAh[1][0], vAh[1][1],
                                  sbase + kvb + 2 * K_TB + off);
                        ldsm_x4_t(vAl[0][0], vAl[0][1], vAl[1][0], vAl[1][1],
                                  sbase + kvb + 3 * K_TB + off);
                    }
                    {
                        const unsigned off =
                            ((unsigned)((ks * 16 + v_r) * AT_AST + nb * 16 + v_c)) * 2u;
                        ldsm_x4_t(vBh[0][0], vBh[0][1], vBh[1][0], vBh[1][1],
                                  sbase + kvb + 2 * K_TB + off);
                        ldsm_x4_t(vBl[0][0], vBl[0][1], vBl[1][0], vBl[1][1],
                                  sbase + kvb + 3 * K_TB + off);
                    }
                    // term h
                    mma16816(O[2*na],     pah[ks], vAh[0]);
                    mma16816(O[2*na + 1], pah[ks], vAh[1]);
                    mma16816(O[2*nb],     pah[ks], vBh[0]);
                    mma16816(O[2*nb + 1], pah[ks], vBh[1]);
                    // term l
                    mma16816(O[2*na],     pah[ks], vAl[0]);
                    mma16816(O[2*na + 1], pah[ks], vAl[1]);
                    mma16816(O[2*nb],     pah[ks], vBl[0]);
                    mma16816(O[2*nb + 1], pah[ks], vBl[1]);
                }
            }
        }
        __syncthreads();
    }

    const float inv0 = 1.f / lrow0, inv1 = 1.f / lrow1;
    const size_t row0 = (base + q0 + wm + r) * HDIM + hh * HEADD;
    const size_t row1 = (base + q0 + wm + r + 8) * HDIM + hh * HEADD;
    #pragma unroll
    for (int nt = 0; nt < 8; nt++) {
        const int col = nt * 8 + c2;
        *(float2*)(g_ao + row0 + col) = make_float2(O[nt][0] * inv0, O[nt][1] * inv0);
        *(float2*)(g_ao + row1 + col) = make_float2(O[nt][2] * inv1, O[nt][3] * inv1);
    }
}

// ---------------- launcher ---------------------------------------------------
extern "C" void kernel_launch(void* const* d_in, const int* in_sizes, int n_in,
                              void* d_out, int out_size)
{
    const int*   seqs_data = (const int*)  d_in[0];
    const float* seqs_in   = (const float*)d_in[1];
    const int*   position  = (const int*)  d_in[2];
    const float* time_in   = (const float*)d_in[3];
    const float* pos_table = (const float*)d_in[4];
    const float* gate_W    = (const float*)d_in[5];
    const float* gate_b    = (const float*)d_in[6];
    const float* ln_attn_g = (const float*)d_in[7];
    const float* ln_attn_b = (const float*)d_in[8];
    const float* qW        = (const float*)d_in[9];
    const float* qb        = (const float*)d_in[10];
    const float* kW        = (const float*)d_in[11];
    const float* kb        = (const float*)d_in[12];
    const float* vW        = (const float*)d_in[13];
    const float* vb        = (const float*)d_in[14];
    const float* ln_ffn_g  = (const float*)d_in[15];
    const float* ln_ffn_b  = (const float*)d_in[16];
    const float* c1W       = (const float*)d_in[17];
    const float* c1b       = (const float*)d_in[18];
    const float* c2W       = (const float*)d_in[19];
    const float* c2b       = (const float*)d_in[20];
    const float* last_g    = (const float*)d_in[21];
    const float* last_b    = (const float*)d_in[22];

    float *p_seqs, *p_time, *p_Q, *p_ao, *p_x;
    __nv_bfloat16 *p_th, *p_tl, *p_ah, *p_al, *p_bh, *p_bl, *p_wh, *p_wl;
    __nv_bfloat16 *p_qh, *p_ql, *p_kh, *p_kl, *p_vh, *p_vl;
    cudaGetSymbolAddress((void**)&p_seqs, g_seqs);
    cudaGetSymbolAddress((void**)&p_time, g_time);
    cudaGetSymbolAddress((void**)&p_Q,    g_Q);
    cudaGetSymbolAddress((void**)&p_ao,   g_ao);
    cudaGetSymbolAddress((void**)&p_x,    g_x);
    cudaGetSymbolAddress((void**)&p_th,   g_t_hi);
    cudaGetSymbolAddress((void**)&p_tl,   g_t_lo);
    cudaGetSymbolAddress((void**)&p_ah,   g_a_hi);
    cudaGetSymbolAddress((void**)&p_al,   g_a_lo);
    cudaGetSymbolAddress((void**)&p_bh,   g_b_hi);
    cudaGetSymbolAddress((void**)&p_bl,   g_b_lo);
    cudaGetSymbolAddress((void**)&p_wh,   g_w_hi);
    cudaGetSymbolAddress((void**)&p_wl,   g_w_lo);
    cudaGetSymbolAddress((void**)&p_qh,   g_qh);
    cudaGetSymbolAddress((void**)&p_ql,   g_ql);
    cudaGetSymbolAddress((void**)&p_kh,   g_kh);
    cudaGetSymbolAddress((void**)&p_kl,   g_kl);
    cudaGetSymbolAddress((void**)&p_vh,   g_vh);
    cudaGetSymbolAddress((void**)&p_vl,   g_vl);

    cudaFuncSetAttribute(attn_kernel, cudaFuncAttributeMaxDynamicSharedMemorySize, ATTN_SMEM);
    cudaFuncSetAttribute(gemm_qkv,    cudaFuncAttributeMaxDynamicSharedMemorySize, GEMM_SMEM);
    cudaFuncSetAttribute(gemm_mma<1>, cudaFuncAttributeMaxDynamicSharedMemorySize, GEMM_SMEM);
    cudaFuncSetAttribute(gemm_mma<2>, cudaFuncAttributeMaxDynamicSharedMemorySize, GEMM_SMEM);

    prep_kernel<<<NROWS, 256>>>(seqs_data, seqs_in, position, time_in,
                                pos_table, gate_W, gate_b);
    wconv_kernel<<<640, 256>>>(qW, kW, vW, c1W, c2W);

    const size_t WSZ = (size_t)HDIM * HDIM;
    const dim3 ggrid(NROWS / 128, HDIM / 64);
    const dim3 qkvgrid(NROWS / 128, HDIM / 64, 3);
    for (int i = 0; i < 2; i++) {
        lnadd_kernel<<<NROWS, 256>>>(ln_attn_g + i * HDIM, ln_attn_b + i * HDIM,
                                     p_Q, p_ah, p_al, p_bh, p_bl);
        gemm_qkv<<<qkvgrid, 256, GEMM_SMEM>>>(
            p_ah, p_al, p_th, p_tl, p_bh, p_bl,
            p_wh + (size_t)i * WSZ, p_wl + (size_t)i * WSZ,
            qb + i * HDIM, kb + i * HDIM, vb + i * HDIM,
            p_qh, p_ql, p_kh, p_kl, p_vh, p_vl);
        attn_kernel<<<dim3(4, 4, NBATCH), 256, ATTN_SMEM>>>(i);
        ln_kernel<true, true><<<NROWS, 256>>>(p_Q, p_ao,
            ln_ffn_g + i * HDIM, ln_ffn_b + i * HDIM, p_x, p_ah, p_al);
        gemm_mma<1><<<ggrid, 256, GEMM_SMEM>>>(p_ah, p_al,
            p_wh + (3 * 2 + i) * WSZ, p_wl + (3 * 2 + i) * WSZ,
            c1b + i * HDIM, nullptr, nullptr, p_bh, p_bl);
        gemm_mma<2><<<ggrid, 256, GEMM_SMEM>>>(p_bh, p_bl,
            p_wh + (4 * 2 + i) * WSZ, p_wl + (4 * 2 + i) * WSZ,
            c2b + i * HDIM, p_x, p_seqs, nullptr, nullptr);
    }
    ln_kernel<false, false><<<NROWS, 256>>>(p_seqs, nullptr, last_g, last_b,
                                            (float*)d_out, nullptr, nullptr);
}

// round 17
// speedup vs baseline: 1.4737x; 1.1770x over previous
#include <cuda_runtime.h>
#include <cuda_bf16.h>
#include <math.h>

#define NROWS 32768          // B*L
#define HDIM  256
#define LSEQ  512
#define NBATCH 64
#define HEADD 64
#define ITEMPAD 49999

typedef unsigned long long u64;

// ---------------- scratch (device globals; no allocs allowed) ----------------
__device__ __align__(16) float g_seqs[NROWS * HDIM];
__device__ __align__(16) float g_time[NROWS * HDIM];
__device__ __align__(16) float g_Q   [NROWS * HDIM];
__device__ __align__(16) float g_ao  [NROWS * HDIM];
__device__ __align__(16) float g_x   [NROWS * HDIM];
__device__ float g_keep[NROWS];
__device__ float g_gates[NROWS * 2];

__device__ __align__(16) __nv_bfloat16 g_t_hi[NROWS * HDIM];
__device__ __align__(16) __nv_bfloat16 g_t_lo[NROWS * HDIM];
__device__ __align__(16) __nv_bfloat16 g_a_hi[NROWS * HDIM];
__device__ __align__(16) __nv_bfloat16 g_a_lo[NROWS * HDIM];
__device__ __align__(16) __nv_bfloat16 g_b_hi[NROWS * HDIM];
__device__ __align__(16) __nv_bfloat16 g_b_lo[NROWS * HDIM];
__device__ __align__(16) __nv_bfloat16 g_qh[NROWS * HDIM];
__device__ __align__(16) __nv_bfloat16 g_ql[NROWS * HDIM];
__device__ __align__(16) __nv_bfloat16 g_kh[NROWS * HDIM];
__device__ __align__(16) __nv_bfloat16 g_kl[NROWS * HDIM];
__device__ __align__(16) __nv_bfloat16 g_vh[NROWS * HDIM];
__device__ __align__(16) __nv_bfloat16 g_vl[NROWS * HDIM];
__device__ __align__(16) __nv_bfloat16 g_w_hi[5 * 2 * HDIM * HDIM];
__device__ __align__(16) __nv_bfloat16 g_w_lo[5 * 2 * HDIM * HDIM];

// ---------------- small helpers ----------------------------------------------
__device__ __forceinline__ void split_bf(float x, __nv_bfloat16& h, __nv_bfloat16& l) {
    h = __float2bfloat16_rn(x);
    l = __float2bfloat16_rn(x - __bfloat162float(h));
}
__device__ __forceinline__ unsigned pack_bf2(__nv_bfloat16 a, __nv_bfloat16 b) {
    return (unsigned)__bfloat16_as_ushort(a) | ((unsigned)__bfloat16_as_ushort(b) << 16);
}
__device__ __forceinline__ unsigned smem_u32(const void* p) {
    unsigned a;
    asm("{ .reg .u64 t; cvta.to.shared.u64 t, %1; cvt.u32.u64 %0, t; }" : "=r"(a) : "l"(p));
    return a;
}

// ---------------- warp-MMA + cp.async helpers (portable: sm_80+) --------------
__device__ __forceinline__ void ldsm_x4(unsigned& r0, unsigned& r1, unsigned& r2,
                                        unsigned& r3, unsigned addr) {
    asm volatile("ldmatrix.sync.aligned.m8n8.x4.shared.b16 {%0,%1,%2,%3}, [%4];"
        : "=r"(r0), "=r"(r1), "=r"(r2), "=r"(r3) : "r"(addr));
}
__device__ __forceinline__ void ldsm_x4_t(unsigned& r0, unsigned& r1, unsigned& r2,
                                          unsigned& r3, unsigned addr) {
    asm volatile("ldmatrix.sync.aligned.m8n8.x4.trans.shared.b16 {%0,%1,%2,%3}, [%4];"
        : "=r"(r0), "=r"(r1), "=r"(r2), "=r"(r3) : "r"(addr));
}
__device__ __forceinline__ void mma16816(float* d, const unsigned* a, const unsigned* b) {
    asm volatile("mma.sync.aligned.m16n8k16.row.col.f32.bf16.bf16.f32 "
        "{%0,%1,%2,%3}, {%4,%5,%6,%7}, {%8,%9}, {%0,%1,%2,%3};"
        : "+f"(d[0]), "+f"(d[1]), "+f"(d[2]), "+f"(d[3])
        : "r"(a[0]), "r"(a[1]), "r"(a[2]), "r"(a[3]), "r"(b[0]), "r"(b[1]));
}
__device__ __forceinline__ void cp16(unsigned dst, const void* src) {
    asm volatile("cp.async.cg.shared.global [%0], [%1], 16;" :: "r"(dst), "l"(src));
}
__device__ __forceinline__ void cp4(unsigned dst, const void* src) {
    asm volatile("cp.async.ca.shared.global [%0], [%1], 4;" :: "r"(dst), "l"(src));
}
#define CP_COMMIT() asm volatile("cp.async.commit_group;" ::: "memory")
#define CP_WAIT1()  asm volatile("cp.async.wait_group 1;" ::: "memory")
#define CP_WAIT0()  asm volatile("cp.async.wait_group 0;" ::: "memory")

// ---------------- prep -------------------------------------------------------
__global__ __launch_bounds__(256) void prep_kernel(
    const int* __restrict__ seqs_data, const float* __restrict__ seqs_in,
    const int* __restrict__ position, const float* __restrict__ time_in,
    const float* __restrict__ pos_table, const float* __restrict__ gate_W,
    const float* __restrict__ gate_b)
{
    const int n = blockIdx.x;
    const int h = threadIdx.x;
    const size_t idx = (size_t)n * HDIM + h;
    const int p = position[n];
    const float pe = pos_table[(size_t)p * HDIM + h];
    const float t = time_in[idx] + pe;
    const float keep = (seqs_data[n] != ITEMPAD) ? 1.f : 0.f;
    g_seqs[idx] = (seqs_in[idx] + pe) * keep;
    g_time[idx] = t;
    __nv_bfloat16 th, tl;
    split_bf(t, th, tl);
    g_t_hi[idx] = th; g_t_lo[idx] = tl;
    if (h == 0) g_keep[n] = keep;

    __shared__ float red[2][8];
    float p0 = t * gate_W[h];
    float p1 = t * gate_W[HDIM + h];
    #pragma unroll
    for (int o = 16; o; o >>= 1) {
        p0 += __shfl_xor_sync(0xffffffffu, p0, o);
        p1 += __shfl_xor_sync(0xffffffffu, p1, o);
    }
    if ((h & 31) == 0) { red[0][h >> 5] = p0; red[1][h >> 5] = p1; }
    __syncthreads();
    if (h < 2) {
        float s = 0.f;
        #pragma unroll
        for (int j = 0; j < 8; j++) s += red[h][j];
        g_gates[(size_t)n * 2 + h] = 1.f / (1.f + __expf(-(s + gate_b[h])));
    }
}

// ---------------- weight conversion ------------------------------------------
__global__ __launch_bounds__(256) void wconv_kernel(
    const float* __restrict__ q, const float* __restrict__ k,
    const float* __restrict__ v, const float* __restrict__ c1,
    const float* __restrict__ c2)
{
    const int i = blockIdx.x * blockDim.x + threadIdx.x;
    if (i >= 5 * 32768) return;
    const int mat = i >> 15, rem = i & 32767;
    const float* src = (mat == 0) ? q : (mat == 1) ? k : (mat == 2) ? v : (mat == 3) ? c1 : c2;
    float4 x = ((const float4*)src)[rem];
    __nv_bfloat16 h0,l0,h1,l1,h2,l2,h3,l3;
    split_bf(x.x,h0,l0); split_bf(x.y,h1,l1); split_bf(x.z,h2,l2); split_bf(x.w,h3,l3);
    const size_t o = ((size_t)mat << 17) + (size_t)rem * 4;
    *(uint2*)(g_w_hi + o) = make_uint2(pack_bf2(h0,h1), pack_bf2(h2,h3));
    *(uint2*)(g_w_lo + o) = make_uint2(pack_bf2(l0,l1), pack_bf2(l2,l3));
}

// ---------------- vectorized LN family (4 rows/block, 64 thr x float4) --------
__device__ __forceinline__ void row_reduce(float& s, float& q, int t,
                                           float* rs, float* rq) {
    #pragma unroll
    for (int o = 16; o; o >>= 1) {
        s += __shfl_xor_sync(0xffffffffu, s, o);
        q += __shfl_xor_sync(0xffffffffu, q, o);
    }
    const int w = t >> 5;
    if ((t & 31) == 0) { rs[w] = s; rq[w] = q; }
    __syncthreads();
    const int rw2 = (t >> 6) << 1;
    s = rs[rw2] + rs[rw2 + 1];
    q = rq[rw2] + rq[rw2 + 1];
}

// fused LN(seqs) + (seqs+time) split; 4 rows per block
__global__ __launch_bounds__(256) void lnadd_kernel(
    const float* __restrict__ g, const float* __restrict__ beta,
    float* __restrict__ Q, __nv_bfloat16* __restrict__ Dh,
    __nv_bfloat16* __restrict__ Dl, __nv_bfloat16* __restrict__ Sh,
    __nv_bfloat16* __restrict__ Sl)
{
    __shared__ float rs[8], rq[8];
    const int t = threadIdx.x;
    const int rw = t >> 6, l64 = t & 63;
    const int n = blockIdx.x * 4 + rw;
    const size_t idx = (size_t)n * HDIM + l64 * 4;
    const float4 x = *(const float4*)(g_seqs + idx);
    float s = x.x + x.y + x.z + x.w;
    float q = x.x * x.x + x.y * x.y + x.z * x.z + x.w * x.w;
    row_reduce(s, q, t, rs, rq);
    const float mean = s * (1.f / HDIM);
    const float var  = q * (1.f / HDIM) - mean * mean;
    const float rstd = rsqrtf(var + 1e-8f);
    const float4 gg = __ldg((const float4*)(g + l64 * 4));
    const float4 bb = __ldg((const float4*)(beta + l64 * 4));
    float y[4];
    y[0] = (x.x - mean) * rstd * gg.x + bb.x;
    y[1] = (x.y - mean) * rstd * gg.y + bb.y;
    y[2] = (x.z - mean) * rstd * gg.z + bb.z;
    y[3] = (x.w - mean) * rstd * gg.w + bb.w;
    *(float4*)(Q + idx) = *(float4*)y;
    __nv_bfloat16 h0,l0,h1,l1,h2,l2,h3,l3;
    split_bf(y[0],h0,l0); split_bf(y[1],h1,l1); split_bf(y[2],h2,l2); split_bf(y[3],h3,l3);
    *(uint2*)(Dh + idx) = make_uint2(pack_bf2(h0,h1), pack_bf2(h2,h3));
    *(uint2*)(Dl + idx) = make_uint2(pack_bf2(l0,l1), pack_bf2(l2,l3));
    const float4 tv = *(const float4*)(g_time + idx);
    split_bf(x.x + tv.x, h0, l0); split_bf(x.y + tv.y, h1, l1);
    split_bf(x.z + tv.z, h2, l2); split_bf(x.w + tv.w, h3, l3);
    *(uint2*)(Sh + idx) = make_uint2(pack_bf2(h0,h1), pack_bf2(h2,h3));
    *(uint2*)(Sl + idx) = make_uint2(pack_bf2(l0,l1), pack_bf2(l2,l3));
}

// layernorm (+residual, +bf16 split outputs); 4 rows per block
template<bool ADD, bool BF>
__global__ __launch_bounds__(256) void ln_kernel(
    const float* __restrict__ A, const float* __restrict__ B2,
    const float* __restrict__ g, const float* __restrict__ beta,
    float* __restrict__ dst, __nv_bfloat16* __restrict__ Dh,
    __nv_bfloat16* __restrict__ Dl)
{
    __shared__ float rs[8], rq[8];
    const int t = threadIdx.x;
    const int rw = t >> 6, l64 = t & 63;
    const int n = blockIdx.x * 4 + rw;
    const size_t idx = (size_t)n * HDIM + l64 * 4;
    float4 x = *(const float4*)(A + idx);
    if (ADD) {
        const float4 b2 = *(const float4*)(B2 + idx);
        x.x += b2.x; x.y += b2.y; x.z += b2.z; x.w += b2.w;
    }
    float s = x.x + x.y + x.z + x.w;
    float q = x.x * x.x + x.y * x.y + x.z * x.z + x.w * x.w;
    row_reduce(s, q, t, rs, rq);
    const float mean = s * (1.f / HDIM);
    const float var  = q * (1.f / HDIM) - mean * mean;
    const float rstd = rsqrtf(var + 1e-8f);
    const float4 gg = __ldg((const float4*)(g + l64 * 4));
    const float4 bb = __ldg((const float4*)(beta + l64 * 4));
    float y[4];
    y[0] = (x.x - mean) * rstd * gg.x + bb.x;
    y[1] = (x.y - mean) * rstd * gg.y + bb.y;
    y[2] = (x.z - mean) * rstd * gg.z + bb.z;
    y[3] = (x.w - mean) * rstd * gg.w + bb.w;
    *(float4*)(dst + idx) = *(float4*)y;
    if (BF) {
        __nv_bfloat16 h0,l0,h1,l1,h2,l2,h3,l3;
        split_bf(y[0],h0,l0); split_bf(y[1],h1,l1);
        split_bf(y[2],h2,l2); split_bf(y[3],h3,l3);
        *(uint2*)(Dh + idx) = make_uint2(pack_bf2(h0,h1), pack_bf2(h2,h3));
        *(uint2*)(Dl + idx) = make_uint2(pack_bf2(l0,l1), pack_bf2(l2,l3));
    }
}

// ---------------- GEMM v6 (at HMMA roof; frozen) ------------------------------
#define ASTRIDE 72
#define A_TSZ (128 * ASTRIDE)
#define B_TSZ (64 * ASTRIDE)
#define BUF_ELE (2 * A_TSZ + 2 * B_TSZ)   // 55296 bytes
#define GEMM_SMEM (2 * BUF_ELE * 2)       // 110592 bytes

#define GEMM_ISSUE(c, bufe)                                                      \
    {                                                                            \
        _Pragma("unroll")                                                        \
        for (int i_ = 0; i_ < 4; i_++) {                                         \
            const int v_ = tid + 256 * i_;                                       \
            const int r_ = v_ >> 3, cc_ = v_ & 7;                                \
            const size_t gA_ = (size_t)(bm + r_) * HDIM + (c) * 64 + cc_ * 8;    \
            const unsigned so_ = sbase + ((bufe) + r_ * ASTRIDE + cc_ * 8) * 2u; \
            cp16(so_,             Ah + gA_);                                     \
            cp16(so_ + A_TSZ * 2, Al + gA_);                                     \
        }                                                                        \
        _Pragma("unroll")                                                        \
        for (int i_ = 0; i_ < 2; i_++) {                                         \
            const int v_ = tid + 256 * i_;                                       \
            const int r_ = v_ >> 3, cc_ = v_ & 7;                                \
            const size_t gB_ = (size_t)(bn + r_) * HDIM + (c) * 64 + cc_ * 8;    \
            const unsigned so_ = sbase +                                         \
                ((bufe) + 2 * A_TSZ + r_ * ASTRIDE + cc_ * 8) * 2u;              \
            cp16(so_,             Wh + gB_);                                     \
            cp16(so_ + B_TSZ * 2, Wl + gB_);                                     \
        }                                                                        \
        CP_COMMIT();                                                             \
    }

#define LOADF(p, ks)                                                             \
    {                                                                            \
        const int k_ = (ks) * 16;                                                \
        _Pragma("unroll")                                                        \
        for (int mt_ = 0; mt_ < 2; mt_++) {                                      \
            const unsigned off_ =                                                \
                ((unsigned)((wm + mt_ * 16 + a_r) * ASTRIDE + k_ + a_c)) * 2u;   \
            ldsm_x4(ah[p][mt_][0], ah[p][mt_][1], ah[p][mt_][2], ah[p][mt_][3],  \
                    sbase + bb + off_);                                          \
            ldsm_x4(al[p][mt_][0], al[p][mt_][1], al[p][mt_][2], al[p][mt_][3],  \
                    sbase + bb + A_TSZ * 2 + off_);                              \
        }                                                                        \
        _Pragma("unroll")                                                        \
        for (int nt2_ = 0; nt2_ < 2; nt2_++) {                                   \
            const unsigned off_ = ((unsigned)(2 * A_TSZ +                        \
                (wn + nt2_ * 16 + b_r) * ASTRIDE + k_ + b_c)) * 2u;              \
            unsigned r0_, r1_, r2_, r3_;                                         \
            ldsm_x4(r0_, r1_, r2_, r3_, sbase + bb + off_);                      \
            bh[p][nt2_ * 2][0] = r0_; bh[p][nt2_ * 2][1] = r1_;                  \
            bh[p][nt2_ * 2 + 1][0] = r2_; bh[p][nt2_ * 2 + 1][1] = r3_;          \
            ldsm_x4(r0_, r1_, r2_, r3_, sbase + bb + B_TSZ * 2 + off_);          \
            bl[p][nt2_ * 2][0] = r0_; bl[p][nt2_ * 2][1] = r1_;                  \
            bl[p][nt2_ * 2 + 1][0] = r2_; bl[p][nt2_ * 2 + 1][1] = r3_;          \
        }                                                                        \
    }

#define GEMM_MMAS(p)                                                             \
    {                                                                            \
        _Pragma("unroll")                                                        \
        for (int mt = 0; mt < 2; mt++)                                           \
            _Pragma("unroll")                                                    \
            for (int nt = 0; nt < 4; nt++)                                       \
                mma16816(acc[mt][nt], ah[p][mt], bh[p][nt]);                     \
        _Pragma("unroll")                                                        \
        for (int mt = 0; mt < 2; mt++)                                           \
            _Pragma("unroll")                                                    \
            for (int nt = 0; nt < 4; nt++)                                       \
                mma16816(acc[mt][nt], al[p][mt], bh[p][nt]);                     \
        _Pragma("unroll")                                                        \
        for (int mt = 0; mt < 2; mt++)                                           \
            _Pragma("unroll")                                                    \
            for (int nt = 0; nt < 4; nt++)                                       \
                mma16816(acc[mt][nt], ah[p][mt], bl[p][nt]);                     \
    }

template<int EPI>
__global__ __launch_bounds__(256, 2) void gemm_mma(
    const __nv_bfloat16* __restrict__ Ah, const __nv_bfloat16* __restrict__ Al,
    const __nv_bfloat16* __restrict__ Wh, const __nv_bfloat16* __restrict__ Wl,
    const float* __restrict__ bias, const float* __restrict__ R,
    float* __restrict__ Cf, __nv_bfloat16* __restrict__ Ch,
    __nv_bfloat16* __restrict__ Cl)
{
    extern __shared__ __align__(16) __nv_bfloat16 smb[];
    const int tid = threadIdx.x;
    const int lane = tid & 31, wid = tid >> 5;
    const int bm = blockIdx.x << 7;
    const int bn = blockIdx.y << 6;
    const int wm = (wid >> 1) << 5;
    const int wn = (wid & 1) << 5;

    float acc[2][4][4];
    #pragma unroll
    for (int mt = 0; mt < 2; mt++)
        #pragma unroll
        for (int nt = 0; nt < 4; nt++)
            #pragma unroll
            for (int j = 0; j < 4; j++) acc[mt][nt][j] = 0.f;

    const unsigned sbase = smem_u32(smb);
    const int a_r = ((lane >> 3) & 1) * 8 + (lane & 7);
    const int a_c = (lane >> 4) * 8;
    const int b_r = (lane >> 4) * 8 + (lane & 7);
    const int b_c = ((lane >> 3) & 1) * 8;

    unsigned ah[2][2][4], al[2][2][4], bh[2][4][2], bl[2][4][2];

    GEMM_ISSUE(0, 0u);

    for (int c = 0; c < 4; c++) {
        if (c + 1 < 4) {
            GEMM_ISSUE(c + 1, (unsigned)(((c + 1) & 1) * BUF_ELE));
            CP_WAIT1();
        } else {
            CP_WAIT0();
        }
        __syncthreads();
        const unsigned bb = (unsigned)((c & 1) * BUF_ELE) * 2u;

        LOADF(0, 0);
        #pragma unroll
        for (int ks = 0; ks < 4; ks++) {
            if (ks < 3) LOADF((ks + 1) & 1, ks + 1);
            const int p = ks & 1;
            GEMM_MMAS(p);
        }
        __syncthreads();
    }

    const int qrow = lane >> 2;
    const int qcol = (lane & 3) * 2;
    #pragma unroll
    for (int mt = 0; mt < 2; mt++) {
        #pragma unroll
        for (int half = 0; half < 2; half++) {
            const int row = bm + wm + mt * 16 + qrow + half * 8;
            float keep = 1.f;
            if (EPI == 2) keep = g_keep[row];
            #pragma unroll
            for (int nt = 0; nt < 4; nt++) {
                const int col = bn + wn + nt * 8 + qcol;
                float v0 = acc[mt][nt][half * 2]     + __ldg(bias + col);
                float v1 = acc[mt][nt][half * 2 + 1] + __ldg(bias + col + 1);
                const size_t o = (size_t)row * HDIM + col;
                if (EPI == 0) {
                    *(float2*)(Cf + o) = make_float2(v0, v1);
                } else if (EPI == 1 || EPI == 3) {
                    if (EPI == 1) { v0 = fmaxf(v0, 0.f); v1 = fmaxf(v1, 0.f); }
                    __nv_bfloat16 h0, l0, h1, l1;
                    split_bf(v0, h0, l0); split_bf(v1, h1, l1);
                    *(unsigned*)(Ch + o) = pack_bf2(h0, h1);
                    *(unsigned*)(Cl + o) = pack_bf2(l0, l1);
                } else {
                    const float2 rr = *(const float2*)(R + o);
                    *(float2*)(Cf + o) = make_float2((v0 + rr.x) * keep,
                                                     (v1 + rr.y) * keep);
                }
            }
        }
    }
}

// ---------------- merged q/k/v GEMM (EPI=3), z selects the job ----------------
__global__ __launch_bounds__(256, 2) void gemm_qkv(
    const __nv_bfloat16* __restrict__ Ah0, const __nv_bfloat16* __restrict__ Al0,
    const __nv_bfloat16* __restrict__ Ah1, const __nv_bfloat16* __restrict__ Al1,
    const __nv_bfloat16* __restrict__ Ah2, const __nv_bfloat16* __restrict__ Al2,
    const __nv_bfloat16* __restrict__ Whb, const __nv_bfloat16* __restrict__ Wlb,
    const float* __restrict__ b0, const float* __restrict__ b1,
    const float* __restrict__ b2,
    __nv_bfloat16* __restrict__ C0h, __nv_bfloat16* __restrict__ C0l,
    __nv_bfloat16* __restrict__ C1h, __nv_bfloat16* __restrict__ C1l,
    __nv_bfloat16* __restrict__ C2h, __nv_bfloat16* __restrict__ C2l)
{
    extern __shared__ __align__(16) __nv_bfloat16 smb[];
    const int z = blockIdx.z;
    const __nv_bfloat16* Ah = (z == 0) ? Ah0 : (z == 1) ? Ah1 : Ah2;
    const __nv_bfloat16* Al = (z == 0) ? Al0 : (z == 1) ? Al1 : Al2;
    const __nv_bfloat16* Wh = Whb + (size_t)z * 2 * HDIM * HDIM;
    const __nv_bfloat16* Wl = Wlb + (size_t)z * 2 * HDIM * HDIM;
    const float* bias = (z == 0) ? b0 : (z == 1) ? b1 : b2;
    __nv_bfloat16* Ch = (z == 0) ? C0h : (z == 1) ? C1h : C2h;
    __nv_bfloat16* Cl = (z == 0) ? C0l : (z == 1) ? C1l : C2l;

    const int tid = threadIdx.x;
    const int lane = tid & 31, wid = tid >> 5;
    const int bm = blockIdx.x << 7;
    const int bn = blockIdx.y << 6;
    const int wm = (wid >> 1) << 5;
    const int wn = (wid & 1) << 5;

    float acc[2][4][4];
    #pragma unroll
    for (int mt = 0; mt < 2; mt++)
        #pragma unroll
        for (int nt = 0; nt < 4; nt++)
            #pragma unroll
            for (int j = 0; j < 4; j++) acc[mt][nt][j] = 0.f;

    const unsigned sbase = smem_u32(smb);
    const int a_r = ((lane >> 3) & 1) * 8 + (lane & 7);
    const int a_c = (lane >> 4) * 8;
    const int b_r = (lane >> 4) * 8 + (lane & 7);
    const int b_c = ((lane >> 3) & 1) * 8;

    unsigned ah[2][2][4], al[2][2][4], bh[2][4][2], bl[2][4][2];

    GEMM_ISSUE(0, 0u);

    for (int c = 0; c < 4; c++) {
        if (c + 1 < 4) {
            GEMM_ISSUE(c + 1, (unsigned)(((c + 1) & 1) * BUF_ELE));
            CP_WAIT1();
        } else {
            CP_WAIT0();
        }
        __syncthreads();
        const unsigned bb = (unsigned)((c & 1) * BUF_ELE) * 2u;

        LOADF(0, 0);
        #pragma unroll
        for (int ks = 0; ks < 4; ks++) {
            if (ks < 3) LOADF((ks + 1) & 1, ks + 1);
            const int p = ks & 1;
            GEMM_MMAS(p);
        }
        __syncthreads();
    }

    const int qrow = lane >> 2;
    const int qcol = (lane & 3) * 2;
    #pragma unroll
    for (int mt = 0; mt < 2; mt++) {
        #pragma unroll
        for (int half = 0; half < 2; half++) {
            const int row = bm + wm + mt * 16 + qrow + half * 8;
            #pragma unroll
            for (int nt = 0; nt < 4; nt++) {
                const int col = bn + wn + nt * 8 + qcol;
                float v0 = acc[mt][nt][half * 2]     + __ldg(bias + col);
                float v1 = acc[mt][nt][half * 2 + 1] + __ldg(bias + col + 1);
                const size_t o = (size_t)row * HDIM + col;
                __nv_bfloat16 h0, l0, h1, l1;
                split_bf(v0, h0, l0); split_bf(v1, h1, l1);
                *(unsigned*)(Ch + o) = pack_bf2(h0, h1);
                *(unsigned*)(Cl + o) = pack_bf2(l0, l1);
            }
        }
    }
}

// ---------------- flash attention (MMA, causal, gated, cp.async 2-buf) --------
// S = (Qh + Ql)·Kh (2-term); Kl tile no longer loaded.
#define AT_AST 72
#define SQH_B 0
#define SQL_B (128 * AT_AST * 2)
#define SKV0_B (2 * 128 * AT_AST * 2)
#define KV_BUF_B (4 * 64 * AT_AST * 2)
#define K_TB (64 * AT_AST * 2)
#define STG_B (SKV0_B + 2 * KV_BUF_B)
#define ATTN_SMEM (STG_B + 2 * 64 * 4)

#define KV_ISSUE(kt, bufb)                                                       \
    {                                                                            \
        const int k0_ = (kt) * 64;                                               \
        _Pragma("unroll")                                                        \
        for (int i_ = 0; i_ < 2; i_++) {                                         \
            const int v_ = tid + 256 * i_;                                       \
            const int rr_ = v_ >> 3, cc_ = v_ & 7;                               \
            const size_t go_ = (base + k0_ + rr_) * HDIM + hh * HEADD + cc_ * 8; \
            const unsigned so_ = sbase + (bufb) + (rr_ * AT_AST + cc_ * 8) * 2u; \
            cp16(so_,            g_kh + go_);                                    \
            cp16(so_ + 2 * K_TB, g_vh + go_);                                    \
            cp16(so_ + 3 * K_TB, g_vl + go_);                                    \
        }                                                                        \
        if (tid < 64)                                                            \
            cp4(sbase + STG_B + (((kt) & 1) * 64 + tid) * 4u,                    \
                g_gates + (base + k0_ + tid) * 2 + blk);                         \
        CP_COMMIT();                                                             \
    }

__global__ __launch_bounds__(256, 2) void attn_kernel(int blk)
{
    extern __shared__ __align__(16) __nv_bfloat16 smb[];
    float* stgk = (float*)((char*)smb + STG_B);

    const int tid = threadIdx.x;
    const int lane = tid & 31, wid = tid >> 5;
    const int qt = blockIdx.x, hh = blockIdx.y, b = blockIdx.z;
    const int q0 = qt * 128;
    const size_t base = (size_t)b * LSEQ;
    const int wm = wid * 16;
    const unsigned sbase = smem_u32(smb);
    const int nkt = 2 * (qt + 1);

    KV_ISSUE(0, (unsigned)SKV0_B);

    #pragma unroll
    for (int i = 0; i < 4; i++) {
        const int v = tid + 256 * i;
        const int r = v >> 3, cc = v & 7;
        const size_t go = (base + q0 + r) * HDIM + hh * HEADD + cc * 8;
        *(uint4*)((char*)smb + SQH_B + (r * AT_AST + cc * 8) * 2) = *(const uint4*)(g_qh + go);
        *(uint4*)((char*)smb + SQL_B + (r * AT_AST + cc * 8) * 2) = *(const uint4*)(g_ql + go);
    }
    __syncthreads();

    const int a_r = ((lane >> 3) & 1) * 8 + (lane & 7);
    const int a_c = (lane >> 4) * 8;
    const int b_r = (lane >> 4) * 8 + (lane & 7);
    const int b_c = ((lane >> 3) & 1) * 8;
    const int v_r = lane & 15;
    const int v_c = (lane >> 4) * 8;

    const int r = lane >> 2;
    const int c2 = (lane & 3) * 2;
    const int qmax = q0 + wm + 15;
    const float cq0 = 0.125f * g_gates[(base + q0 + wm + r) * 2 + blk];
    const float cq1 = 0.125f * g_gates[(base + q0 + wm + r + 8) * 2 + blk];
    float mrow0 = -1e30f, mrow1 = -1e30f, lrow0 = 0.f, lrow1 = 0.f;
    float O[8][4];
    #pragma unroll
    for (int nt = 0; nt < 8; nt++)
        #pragma unroll
        for (int j = 0; j < 4; j++) O[nt][j] = 0.f;

    for (int kt = 0; kt < nkt; kt++) {
        const int k0 = kt * 64;
        if (kt + 1 < nkt) {
            KV_ISSUE(kt + 1, (unsigned)(SKV0_B + ((kt + 1) & 1) * KV_BUF_B));
            CP_WAIT1();
        } else {
            CP_WAIT0();
        }
        __syncthreads();
        const unsigned kvb = (unsigned)(SKV0_B + (kt & 1) * KV_BUF_B);
        const float* stg = stgk + (kt & 1) * 64;

        float S[8][4];
        #pragma unroll
        for (int nt = 0; nt < 8; nt++)
            #pragma unroll
            for (int j = 0; j < 4; j++) S[nt][j] = 0.f;
        #pragma unroll
        for (int ks = 0; ks < 4; ks++) {
            unsigned aqh[4], aql[4];
            const unsigned qoff =
                ((unsigned)((wm + a_r) * AT_AST + ks * 16 + a_c)) * 2u;
            ldsm_x4(aqh[0], aqh[1], aqh[2], aqh[3], sbase + SQH_B + qoff);
            ldsm_x4(aql[0], aql[1], aql[2], aql[3], sbase + SQL_B + qoff);
            #pragma unroll
            for (int p16 = 0; p16 < 2; p16++) {
                const int na = 2 * p16, nb = 2 * p16 + 1;
                const bool actA = (k0 + na * 16 <= qmax);
                const bool actB = (k0 + nb * 16 <= qmax);
                unsigned kAh[2][2], kBh[2][2];
                if (actA) {
                    const unsigned off =
                        ((unsigned)((na * 16 + b_r) * AT_AST + ks * 16 + b_c)) * 2u;
                    ldsm_x4(kAh[0][0], kAh[0][1], kAh[1][0], kAh[1][1],
                            sbase + kvb + off);
                }
                if (actB) {
                    const unsigned off =
                        ((unsigned)((nb * 16 + b_r) * AT_AST + ks * 16 + b_c)) * 2u;
                    ldsm_x4(kBh[0][0], kBh[0][1], kBh[1][0], kBh[1][1],
                            sbase + kvb + off);
                }
                // term hh
                if (actA) { mma16816(S[2*na], aqh, kAh[0]); mma16816(S[2*na+1], aqh, kAh[1]); }
                if (actB) { mma16816(S[2*nb], aqh, kBh[0]); mma16816(S[2*nb+1], aqh, kBh[1]); }
                // term lh
                if (actA) { mma16816(S[2*na], aql, kAh[0]); mma16816(S[2*na+1], aql, kAh[1]); }
                if (actB) { mma16816(S[2*nb], aql, kBh[0]); mma16816(S[2*nb+1], aql, kBh[1]); }
            }
        }

        const bool need_mask = (k0 + 63 > q0 + wm);
        float mt0 = -1e30f, mt1 = -1e30f;
        #pragma unroll
        for (int nt = 0; nt < 8; nt++) {
            const int col = nt * 8 + c2;
            const float tga = stg[col], tgb = stg[col + 1];
            float v0 = S[nt][0] * cq0 * tga;
            float v1 = S[nt][1] * cq0 * tgb;
            float v2 = S[nt][2] * cq1 * tga;
            float v3 = S[nt][3] * cq1 * tgb;
            if (need_mask) {
                const int kg = k0 + col;
                const int qa = q0 + wm + r, qb2 = qa + 8;
                if (kg     > qa)  v0 = -1e30f;
                if (kg + 1 > qa)  v1 = -1e30f;
                if (kg     > qb2) v2 = -1e30f;
                if (kg + 1 > qb2) v3 = -1e30f;
            }
            S[nt][0] = v0; S[nt][1] = v1; S[nt][2] = v2; S[nt][3] = v3;
            mt0 = fmaxf(mt0, fmaxf(v0, v1));
            mt1 = fmaxf(mt1, fmaxf(v2, v3));
        }
        mt0 = fmaxf(mt0, __shfl_xor_sync(0xffffffffu, mt0, 1));
        mt0 = fmaxf(mt0, __shfl_xor_sync(0xffffffffu, mt0, 2));
        mt1 = fmaxf(mt1, __shfl_xor_sync(0xffffffffu, mt1, 1));
        mt1 = fmaxf(mt1, __shfl_xor_sync(0xffffffffu, mt1, 2));
        const float mn0 = fmaxf(mrow0, mt0), mn1 = fmaxf(mrow1, mt1);
        const float al0 = __expf(mrow0 - mn0), al1 = __expf(mrow1 - mn1);
        mrow0 = mn0; mrow1 = mn1;

        float rs0 = 0.f, rs1 = 0.f;
        unsigned pah[4][4];
        #pragma unroll
        for (int j2 = 0; j2 < 4; j2++) {
            __nv_bfloat16 h0 = __float2bfloat16_rn(__expf(S[2 * j2][0] - mn0));
            __nv_bfloat16 h1 = __float2bfloat16_rn(__expf(S[2 * j2][1] - mn0));
            __nv_bfloat16 h2 = __float2bfloat16_rn(__expf(S[2 * j2][2] - mn1));
            __nv_bfloat16 h3 = __float2bfloat16_rn(__expf(S[2 * j2][3] - mn1));
            __nv_bfloat16 h4 = __float2bfloat16_rn(__expf(S[2 * j2 + 1][0] - mn0));
            __nv_bfloat16 h5 = __float2bfloat16_rn(__expf(S[2 * j2 + 1][1] - mn0));
            __nv_bfloat16 h6 = __float2bfloat16_rn(__expf(S[2 * j2 + 1][2] - mn1));
            __nv_bfloat16 h7 = __float2bfloat16_rn(__expf(S[2 * j2 + 1][3] - mn1));
            rs0 += (__bfloat162float(h0) + __bfloat162float(h1))
                 + (__bfloat162float(h4) + __bfloat162float(h5));
            rs1 += (__bfloat162float(h2) + __bfloat162float(h3))
                 + (__bfloat162float(h6) + __bfloat162float(h7));
            pah[j2][0] = pack_bf2(h0, h1);
            pah[j2][1] = pack_bf2(h2, h3);
            pah[j2][2] = pack_bf2(h4, h5);
            pah[j2][3] = pack_bf2(h6, h7);
        }
        rs0 += __shfl_xor_sync(0xffffffffu, rs0, 1);
        rs0 += __shfl_xor_sync(0xffffffffu, rs0, 2);
        rs1 += __shfl_xor_sync(0xffffffffu, rs1, 1);
        rs1 += __shfl_xor_sync(0xffffffffu, rs1, 2);
        lrow0 = lrow0 * al0 + rs0;
        lrow1 = lrow1 * al1 + rs1;

        #pragma unroll
        for (int nt = 0; nt < 8; nt++) {
            O[nt][0] *= al0; O[nt][1] *= al0;
            O[nt][2] *= al1; O[nt][3] *= al1;
        }

        #pragma unroll
        for (int ks = 0; ks < 4; ks++) {
            if (k0 + ks * 16 <= qmax) {
                #pragma unroll
                for (int p16 = 0; p16 < 2; p16++) {
                    const int na = 2 * p16, nb = 2 * p16 + 1;
                    unsigned vAh[2][2], vAl[2][2], vBh[2][2], vBl[2][2];
                    {
                        const unsigned off =
                            ((unsigned)((ks * 16 + v_r) * AT_AST + na * 16 + v_c)) * 2u;
                        ldsm_x4_t(vAh[0][0], vAh[0][1], vAh[1][0], vAh[1][1],
                                  sbase + kvb + 2 * K_TB + off);
                        ldsm_x4_t(vAl[0][0], vAl[0][1], vAl[1][0], vAl[1][1],
                                  sbase + kvb + 3 * K_TB + off);
                    }
                    {
                        const unsigned off =
                            ((unsigned)((ks * 16 + v_r) * AT_AST + nb * 16 + v_c)) * 2u;
                        ldsm_x4_t(vBh[0][0], vBh[0][1], vBh[1][0], vBh[1][1],
                                  sbase + kvb + 2 * K_TB + off);
                        ldsm_x4_t(vBl[0][0], vBl[0][1], vBl[1][0], vBl[1][1],
                                  sbase + kvb + 3 * K_TB + off);
                    }
                    mma16816(O[2*na],     pah[ks], vAh[0]);
                    mma16816(O[2*na + 1], pah[ks], vAh[1]);
                    mma16816(O[2*nb],     pah[ks], vBh[0]);
                    mma16816(O[2*nb + 1], pah[ks], vBh[1]);
                    mma16816(O[2*na],     pah[ks], vAl[0]);
                    mma16816(O[2*na + 1], pah[ks], vAl[1]);
                    mma16816(O[2*nb],     pah[ks], vBl[0]);
                    mma16816(O[2*nb + 1], pah[ks], vBl[1]);
                }
            }
        }
        __syncthreads();
    }

    const float inv0 = 1.f / lrow0, inv1 = 1.f / lrow1;
    const size_t row0 = (base + q0 + wm + r) * HDIM + hh * HEADD;
    const size_t row1 = (base + q0 + wm + r + 8) * HDIM + hh * HEADD;
    #pragma unroll
    for (int nt = 0; nt < 8; nt++) {
        const int col = nt * 8 + c2;
        *(float2*)(g_ao + row0 + col) = make_float2(O[nt][0] * inv0, O[nt][1] * inv0);
        *(float2*)(g_ao + row1 + col) = make_float2(O[nt][2] * inv1, O[nt][3] * inv1);
    }
}

// ---------------- launcher ---------------------------------------------------
extern "C" void kernel_launch(void* const* d_in, const int* in_sizes, int n_in,
                              void* d_out, int out_size)
{
    const int*   seqs_data = (const int*)  d_in[0];
    const float* seqs_in   = (const float*)d_in[1];
    const int*   position  = (const int*)  d_in[2];
    const float* time_in   = (const float*)d_in[3];
    const float* pos_table = (const float*)d_in[4];
    const float* gate_W    = (const float*)d_in[5];
    const float* gate_b    = (const float*)d_in[6];
    const float* ln_attn_g = (const float*)d_in[7];
    const float* ln_attn_b = (const float*)d_in[8];
    const float* qW        = (const float*)d_in[9];
    const float* qb        = (const float*)d_in[10];
    const float* kW        = (const float*)d_in[11];
    const float* kb        = (const float*)d_in[12];
    const float* vW        = (const float*)d_in[13];
    const float* vb        = (const float*)d_in[14];
    const float* ln_ffn_g  = (const float*)d_in[15];
    const float* ln_ffn_b  = (const float*)d_in[16];
    const float* c1W       = (const float*)d_in[17];
    const float* c1b       = (const float*)d_in[18];
    const float* c2W       = (const float*)d_in[19];
    const float* c2b       = (const float*)d_in[20];
    const float* last_g    = (const float*)d_in[21];
    const float* last_b    = (const float*)d_in[22];

    float *p_seqs, *p_time, *p_Q, *p_ao, *p_x;
    __nv_bfloat16 *p_th, *p_tl, *p_ah, *p_al, *p_bh, *p_bl, *p_wh, *p_wl;
    __nv_bfloat16 *p_qh, *p_ql, *p_kh, *p_kl, *p_vh, *p_vl;
    cudaGetSymbolAddress((void**)&p_seqs, g_seqs);
    cudaGetSymbolAddress((void**)&p_time, g_time);
    cudaGetSymbolAddress((void**)&p_Q,    g_Q);
    cudaGetSymbolAddress((void**)&p_ao,   g_ao);
    cudaGetSymbolAddress((void**)&p_x,    g_x);
    cudaGetSymbolAddress((void**)&p_th,   g_t_hi);
    cudaGetSymbolAddress((void**)&p_tl,   g_t_lo);
    cudaGetSymbolAddress((void**)&p_ah,   g_a_hi);
    cudaGetSymbolAddress((void**)&p_al,   g_a_lo);
    cudaGetSymbolAddress((void**)&p_bh,   g_b_hi);
    cudaGetSymbolAddress((void**)&p_bl,   g_b_lo);
    cudaGetSymbolAddress((void**)&p_wh,   g_w_hi);
    cudaGetSymbolAddress((void**)&p_wl,   g_w_lo);
    cudaGetSymbolAddress((void**)&p_qh,   g_qh);
    cudaGetSymbolAddress((void**)&p_ql,   g_ql);
    cudaGetSymbolAddress((void**)&p_kh,   g_kh);
    cudaGetSymbolAddress((void**)&p_kl,   g_kl);
    cudaGetSymbolAddress((void**)&p_vh,   g_vh);
    cudaGetSymbolAddress((void**)&p_vl,   g_vl);

    cudaFuncSetAttribute(attn_kernel, cudaFuncAttributeMaxDynamicSharedMemorySize, ATTN_SMEM);
    cudaFuncSetAttribute(gemm_qkv,    cudaFuncAttributeMaxDynamicSharedMemorySize, GEMM_SMEM);
    cudaFuncSetAttribute(gemm_mma<1>, cudaFuncAttributeMaxDynamicSharedMemorySize, GEMM_SMEM);
    cudaFuncSetAttribute(gemm_mma<2>, cudaFuncAttributeMaxDynamicSharedMemorySize, GEMM_SMEM);

    prep_kernel<<<NROWS, 256>>>(seqs_data, seqs_in, position, time_in,
                                pos_table, gate_W, gate_b);
    wconv_kernel<<<640, 256>>>(qW, kW, vW, c1W, c2W);

    const size_t WSZ = (size_t)HDIM * HDIM;
    const dim3 ggrid(NROWS / 128, HDIM / 64);
    const dim3 qkvgrid(NROWS / 128, HDIM / 64, 3);
    for (int i = 0; i < 2; i++) {
        lnadd_kernel<<<NROWS / 4, 256>>>(ln_attn_g + i * HDIM, ln_attn_b + i * HDIM,
                                         p_Q, p_ah, p_al, p_bh, p_bl);
        gemm_qkv<<<qkvgrid, 256, GEMM_SMEM>>>(
            p_ah, p_al, p_th, p_tl, p_bh, p_bl,
            p_wh + (size_t)i * WSZ, p_wl + (size_t)i * WSZ,
            qb + i * HDIM, kb + i * HDIM, vb + i * HDIM,
            p_qh, p_ql, p_kh, p_kl, p_vh, p_vl);
        attn_kernel<<<dim3(4, 4, NBATCH), 256, ATTN_SMEM>>>(i);
        ln_kernel<true, true><<<NROWS / 4, 256>>>(p_Q, p_ao,
            ln_ffn_g + i * HDIM, ln_ffn_b + i * HDIM, p_x, p_ah, p_al);
        gemm_mma<1><<<ggrid, 256, GEMM_SMEM>>>(p_ah, p_al,
            p_wh + (3 * 2 + i) * WSZ, p_wl + (3 * 2 + i) * WSZ,
            c1b + i * HDIM, nullptr, nullptr, p_bh, p_bl);
        gemm_mma<2><<<ggrid, 256, GEMM_SMEM>>>(p_bh, p_bl,
            p_wh + (4 * 2 + i) * WSZ, p_wl + (4 * 2 + i) * WSZ,
            c2b + i * HDIM, p_x, p_seqs, nullptr, nullptr);
    }
    ln_kernel<false, false><<<NROWS / 4, 256>>>(p_seqs, nullptr, last_g, last_b,
                                                (float*)d_out, nullptr, nullptr);
}